// round 1
// baseline (speedup 1.0000x reference)
#include <cuda_runtime.h>
#include <math.h>

// Problem constants (match the reference's _build_indices(N=1024, M=32))
#define NN   1024
#define MMW  32
#define NEg  32240          // total edges
#define BBc  2
#define RE   (BBc*NEg)      // 64480 edge rows
#define RN   (BBc*NN)       // 2048 node rows

// ---------------- scratch (static device globals; no runtime allocs) -------
__device__ int2  g_eij[NEg];          // (i=target, j=source) per edge
__device__ float g_h1n[(size_t)RE*256];
__device__ float g_hn [(size_t)RE*128];
__device__ float g_pn [(size_t)RN*128];
__device__ float g_h3n[(size_t)RN*192];
__device__ float g_h1e[(size_t)RE*128];
__device__ float g_he [(size_t)RE*64];
__device__ float g_pe [(size_t)RE*64];
__device__ float g_h3e[(size_t)RE*96];

// ---------------- edge index builder ---------------------------------------
// edges enumerated: for i in 1..N-1, j in [max(0,i-M), i).  k0(i) = group start.
__global__ void build_eij_kernel() {
    int e = blockIdx.x * blockDim.x + threadIdx.x;
    if (e >= NEg) return;
    int i, j;
    if (e < 496) {                       // i in 1..31, k0 = i(i-1)/2, j0 = 0
        i = (int)((1.0f + sqrtf(8.0f * (float)e + 1.0f)) * 0.5f);
        while (i * (i - 1) / 2 > e) i--;
        while ((i + 1) * i / 2 <= e) i++;
        j = e - i * (i - 1) / 2;
    } else {                             // i >= 32, k0 = 496 + (i-32)*32, j0 = i-32
        int q = (e - 496) >> 5;
        i = 32 + q;
        j = (i - 32) + ((e - 496) & 31);
    }
    g_eij[e] = make_int2(i, j);
}

__device__ __forceinline__ int group_start(int i) {
    return (i <= 32) ? (i * (i - 1) / 2) : (496 + (i - 32) * 32);
}

// ---------------- fused gather + GEMM + bias + relu -------------------------
// C[R x NOUT] = relu(A_gathered[R x K] @ W[K x NOUT] + bias)
// MODE 0: A plain [R x K]
// MODE 1: triples  = nodes[j](64) ++ edges[e](32) ++ nodes[i](64)   (K=160)
// MODE 2: pairs    = nodes[j](64) ++ edges[e](32)                   (K=96)
// MODE 3: nodes_in = g_pn[r](128) ++ nodes[r](64)                   (K=192)
// MODE 4: edges_in = g_pe[r](64)  ++ edges[r](32)                   (K=96)
template<int K, int NOUT, int MODE>
__global__ __launch_bounds__(256)
void gemm_bias_relu(const float* __restrict__ A,
                    const float* __restrict__ W,
                    const float* __restrict__ bias,
                    float* __restrict__ C, int R,
                    const float* __restrict__ nodes,
                    const float* __restrict__ edges)
{
    __shared__ float As[16][129];
    __shared__ float Bs[16][64];

    const int tid   = threadIdx.x;
    const int tx    = tid & 15;          // 16 col-groups
    const int ty    = tid >> 4;          // 16 row-groups
    const int rbase = blockIdx.y * 128;
    const int cbase = blockIdx.x * 64;

    // ---- A-load mapping: 2 threads per row, 8 k's each ----
    const int lm = tid >> 1;             // 0..127 (row within tile)
    const int lk = (tid & 1) * 8;        // 0 or 8
    const int r  = rbase + lm;
    const bool rv = (r < R);

    const float* p0 = nullptr;
    const float* p1 = nullptr;
    const float* p2 = nullptr;
    if (rv) {
        if (MODE == 0) {
            p0 = A + (size_t)r * K;
        } else if (MODE == 1 || MODE == 2) {
            int b = (r >= NEg) ? 1 : 0;
            int e = r - b * NEg;
            int2 ij = g_eij[e];
            p0 = nodes + ((size_t)(b * NN + ij.y)) * 64;
            p1 = edges + ((size_t)(b * NEg + e)) * 32;
            if (MODE == 1) p2 = nodes + ((size_t)(b * NN + ij.x)) * 64;
        } else if (MODE == 3) {
            p0 = g_pn + (size_t)r * 128;
            p1 = nodes + (size_t)r * 64;
        } else {
            p0 = g_pe + (size_t)r * 64;
            p1 = edges + (size_t)r * 32;
        }
    }

    // ---- B-load mapping: one float4 per thread per chunk ----
    const int bk = tid >> 4;             // 0..15
    const int bn = (tid & 15) * 4;       // 0..60
    const bool cv = (cbase + bn < NOUT);

    float acc[8][4];
#pragma unroll
    for (int u = 0; u < 8; u++)
#pragma unroll
        for (int v = 0; v < 4; v++) acc[u][v] = 0.f;

    for (int k0 = 0; k0 < K; k0 += 16) {
        // load A chunk (gathered)
#pragma unroll
        for (int u = 0; u < 8; u++) {
            int k = k0 + lk + u;
            float v = 0.f;
            if (rv) {
                if (MODE == 0)      v = p0[k];
                else if (MODE == 1) v = (k < 64) ? p0[k] : ((k < 96) ? p1[k - 64] : p2[k - 96]);
                else if (MODE == 2) v = (k < 64) ? p0[k] : p1[k - 64];
                else if (MODE == 3) v = (k < 128) ? p0[k] : p1[k - 128];
                else                v = (k < 64) ? p0[k] : p1[k - 64];
            }
            As[lk + u][lm] = v;
        }
        // load B chunk
        {
            float4 bv = make_float4(0.f, 0.f, 0.f, 0.f);
            if (cv) bv = *(const float4*)(W + (size_t)(k0 + bk) * NOUT + (cbase + bn));
            *(float4*)&Bs[bk][bn] = bv;
        }
        __syncthreads();

#pragma unroll
        for (int kk = 0; kk < 16; kk++) {
            float4 b4 = *(const float4*)&Bs[kk][tx * 4];
            float a[8];
#pragma unroll
            for (int u = 0; u < 8; u++) a[u] = As[kk][ty * 8 + u];
#pragma unroll
            for (int u = 0; u < 8; u++) {
                acc[u][0] = fmaf(a[u], b4.x, acc[u][0]);
                acc[u][1] = fmaf(a[u], b4.y, acc[u][1]);
                acc[u][2] = fmaf(a[u], b4.z, acc[u][2]);
                acc[u][3] = fmaf(a[u], b4.w, acc[u][3]);
            }
        }
        __syncthreads();
    }

    // epilogue: bias + relu, vectorized store
    const int c = cbase + tx * 4;
    if (c < NOUT) {
        float4 bb = *(const float4*)(bias + c);
#pragma unroll
        for (int u = 0; u < 8; u++) {
            int rr = rbase + ty * 8 + u;
            if (rr < R) {
                float4 o;
                o.x = fmaxf(acc[u][0] + bb.x, 0.f);
                o.y = fmaxf(acc[u][1] + bb.y, 0.f);
                o.z = fmaxf(acc[u][2] + bb.z, 0.f);
                o.w = fmaxf(acc[u][3] + bb.w, 0.f);
                *(float4*)(C + (size_t)rr * NOUT + c) = o;
            }
        }
    }
}

// ---------------- node aggregation: mean of hn over incoming edges ----------
__global__ void pn_agg_kernel() {
    const int i = blockIdx.x;            // node
    const int b = blockIdx.y;            // batch
    const int ch = threadIdx.x;          // 128 channels
    const int t  = min(i, 32);
    const int k0 = group_start(i);
    float s = 0.f;
    const float* src = g_hn + ((size_t)(b * NEg + k0)) * 128 + ch;
    for (int l = 0; l < t; l++) s += src[(size_t)l * 128];
    const float nrm = 1.f / (float)max(t, 1);
    g_pn[((size_t)(b * NN + i)) * 128 + ch] = s * nrm;
}

// ---------------- edge aggregation: exclusive in-group prefix mean ----------
__global__ void pe_agg_kernel() {
    const int i = blockIdx.x + 1;        // node (groups exist for i>=1)
    const int b = blockIdx.y;
    const int ch = threadIdx.x;          // 64 channels
    const int t  = min(i, 32);
    const int k0 = group_start(i);
    float run = 0.f;
    size_t base = ((size_t)(b * NEg + k0)) * 64 + ch;
    for (int l = 0; l < t; l++) {
        float nrm = (l > 0) ? (1.f / (float)l) : 1.f;
        g_pe[base] = run * nrm;
        run += g_he[base];
        base += 64;
    }
}

// ---------------- launch -----------------------------------------------------
extern "C" void kernel_launch(void* const* d_in, const int* in_sizes, int n_in,
                              void* d_out, int out_size) {
    const float* nodes = (const float*)d_in[0];
    const float* edges = (const float*)d_in[1];
    const float* Wan1  = (const float*)d_in[2];
    const float* ban1  = (const float*)d_in[3];
    const float* Wan2  = (const float*)d_in[4];
    const float* ban2  = (const float*)d_in[5];
    const float* Wln1  = (const float*)d_in[6];
    const float* bln1  = (const float*)d_in[7];
    const float* Wln2  = (const float*)d_in[8];
    const float* bln2  = (const float*)d_in[9];
    const float* Wae1  = (const float*)d_in[10];
    const float* bae1  = (const float*)d_in[11];
    const float* Wae2  = (const float*)d_in[12];
    const float* bae2  = (const float*)d_in[13];
    const float* Wle1  = (const float*)d_in[14];
    const float* ble1  = (const float*)d_in[15];
    const float* Wle2  = (const float*)d_in[16];
    const float* ble2  = (const float*)d_in[17];

    float* out_nodes = (float*)d_out;                       // [2,1024,64]
    float* out_edges = (float*)d_out + (size_t)BBc * NN * 64; // [2,NE,32]

    float *h1n, *hn, *h3n, *h1e, *he, *h3e;
    cudaGetSymbolAddress((void**)&h1n, g_h1n);
    cudaGetSymbolAddress((void**)&hn,  g_hn);
    cudaGetSymbolAddress((void**)&h3n, g_h3n);
    cudaGetSymbolAddress((void**)&h1e, g_h1e);
    cudaGetSymbolAddress((void**)&he,  g_he);
    cudaGetSymbolAddress((void**)&h3e, g_h3e);

    const int gbE = (RE + 127) / 128;    // 504 row tiles for edge rows
    const int gbN = (RN + 127) / 128;    // 16 row tiles for node rows

    build_eij_kernel<<<(NEg + 255) / 256, 256>>>();

    // node branch
    gemm_bias_relu<160, 256, 1><<<dim3(4, gbE), 256>>>(nullptr, Wan1, ban1, h1n, RE, nodes, edges);
    gemm_bias_relu<256, 128, 0><<<dim3(2, gbE), 256>>>(h1n,     Wan2, ban2, hn,  RE, nodes, edges);
    pn_agg_kernel<<<dim3(NN, BBc), 128>>>();
    gemm_bias_relu<192, 192, 3><<<dim3(3, gbN), 256>>>(nullptr, Wln1, bln1, h3n, RN, nodes, edges);
    gemm_bias_relu<192,  64, 0><<<dim3(1, gbN), 256>>>(h3n,     Wln2, bln2, out_nodes, RN, nodes, edges);

    // edge branch
    gemm_bias_relu< 96, 128, 2><<<dim3(2, gbE), 256>>>(nullptr, Wae1, bae1, h1e, RE, nodes, edges);
    gemm_bias_relu<128,  64, 0><<<dim3(1, gbE), 256>>>(h1e,     Wae2, bae2, he,  RE, nodes, edges);
    pe_agg_kernel<<<dim3(NN - 1, BBc), 64>>>();
    gemm_bias_relu< 96,  96, 4><<<dim3(2, gbE), 256>>>(nullptr, Wle1, ble1, h3e, RE, nodes, edges);
    gemm_bias_relu< 96,  32, 0><<<dim3(1, gbE), 256>>>(h3e,     Wle2, ble2, out_edges, RE, nodes, edges);
}

// round 2
// speedup vs baseline: 1.7211x; 1.7211x over previous
#include <cuda_runtime.h>
#include <math.h>

// Problem constants (match the reference's _build_indices(N=1024, M=32))
#define NN   1024
#define MMW  32
#define NEg  32240          // total edges
#define BBc  2
#define RE   (BBc*NEg)      // 64480 edge rows
#define RN   (BBc*NN)       // 2048 node rows

// ---------------- scratch (static device globals; no runtime allocs) -------
__device__ int2  g_eij[NEg];          // (i=target, j=source) per edge
__device__ float g_h1n[(size_t)RE*256];
__device__ float g_hn [(size_t)RE*128];
__device__ float g_pn [(size_t)RN*128];
__device__ float g_h3n[(size_t)RN*192];
__device__ float g_h1e[(size_t)RE*128];
__device__ float g_he [(size_t)RE*64];
__device__ float g_pe [(size_t)RE*64];
__device__ float g_h3e[(size_t)RE*96];

// ---------------- f32x2 packed-FMA helpers ----------------------------------
__device__ __forceinline__ void ffma2(unsigned long long& d,
                                      unsigned long long a,
                                      unsigned long long b) {
    asm("fma.rn.f32x2 %0, %1, %2, %0;" : "+l"(d) : "l"(a), "l"(b));
}
__device__ __forceinline__ unsigned long long bcast2(float x) {
    unsigned long long r;
    asm("mov.b64 %0, {%1, %1};" : "=l"(r) : "f"(x));
    return r;
}
__device__ __forceinline__ float2 unpack2(unsigned long long v) {
    float2 f;
    asm("mov.b64 {%0, %1}, %2;" : "=f"(f.x), "=f"(f.y) : "l"(v));
    return f;
}

// ---------------- edge index builder ---------------------------------------
__global__ void build_eij_kernel() {
    int e = blockIdx.x * blockDim.x + threadIdx.x;
    if (e >= NEg) return;
    int i, j;
    if (e < 496) {                       // i in 1..31, k0 = i(i-1)/2, j0 = 0
        i = (int)((1.0f + sqrtf(8.0f * (float)e + 1.0f)) * 0.5f);
        while (i * (i - 1) / 2 > e) i--;
        while ((i + 1) * i / 2 <= e) i++;
        j = e - i * (i - 1) / 2;
    } else {                             // i >= 32, k0 = 496 + (i-32)*32, j0 = i-32
        int q = (e - 496) >> 5;
        i = 32 + q;
        j = (i - 32) + ((e - 496) & 31);
    }
    g_eij[e] = make_int2(i, j);
}

__device__ __forceinline__ int group_start(int i) {
    return (i <= 32) ? (i * (i - 1) / 2) : (496 + (i - 32) * 32);
}

// ---------------- fused gather + GEMM + bias + relu -------------------------
// C[R x NOUT] = relu(A_gathered[R x K] @ W[K x NOUT] + bias)
// MODE 0: A plain [R x K]
// MODE 1: triples  = nodes[j](64) ++ edges[e](32) ++ nodes[i](64)   (K=160)
// MODE 2: pairs    = nodes[j](64) ++ edges[e](32)                   (K=96)
// MODE 3: nodes_in = g_pn[r](128) ++ nodes[r](64)                   (K=192)
// MODE 4: edges_in = g_pe[r](64)  ++ edges[r](32)                   (K=96)
template<int K, int NOUT, int MODE>
__global__ __launch_bounds__(256)
void gemm_bias_relu(const float* __restrict__ A,
                    const float* __restrict__ W,
                    const float* __restrict__ bias,
                    float* __restrict__ C, int R,
                    const float* __restrict__ nodes,
                    const float* __restrict__ edges)
{
    __shared__ float As[16][130];        // 130 pad: even -> 8B-aligned rows
    __shared__ float Bs[16][64];

    const int tid   = threadIdx.x;
    const int tx    = tid & 15;          // 16 col-groups (4 cols each)
    const int ty    = tid >> 4;          // 16 row-groups (8 rows each)
    const int rbase = blockIdx.y * 128;
    const int cbase = blockIdx.x * 64;

    // ---- A-load mapping: 2 threads per row, 8 k's each ----
    const int lm = tid >> 1;             // 0..127 (row within tile)
    const int lk = (tid & 1) * 8;        // 0 or 8
    const int r  = rbase + lm;
    const bool rv = (r < R);

    const float* p0 = nullptr;
    const float* p1 = nullptr;
    const float* p2 = nullptr;
    if (rv) {
        if (MODE == 0) {
            p0 = A + (size_t)r * K;
        } else if (MODE == 1 || MODE == 2) {
            int b = (r >= NEg) ? 1 : 0;
            int e = r - b * NEg;
            int2 ij = g_eij[e];
            p0 = nodes + ((size_t)(b * NN + ij.y)) * 64;
            p1 = edges + ((size_t)(b * NEg + e)) * 32;
            if (MODE == 1) p2 = nodes + ((size_t)(b * NN + ij.x)) * 64;
        } else if (MODE == 3) {
            p0 = g_pn + (size_t)r * 128;
            p1 = nodes + (size_t)r * 64;
        } else {
            p0 = g_pe + (size_t)r * 64;
            p1 = edges + (size_t)r * 32;
        }
    }

    // ---- B-load mapping: one float4 per thread per chunk ----
    const int bk = tid >> 4;             // 0..15
    const int bn = (tid & 15) * 4;       // 0..60
    const bool cv = (cbase + bn < NOUT);

    // accumulators: 4 row-pairs x 4 cols, packed f32x2 (lo=even row, hi=odd)
    unsigned long long acc[4][4];
#pragma unroll
    for (int p = 0; p < 4; p++)
#pragma unroll
        for (int v = 0; v < 4; v++) acc[p][v] = 0ull;

    for (int k0 = 0; k0 < K; k0 += 16) {
        // load A chunk (gathered)
#pragma unroll
        for (int u = 0; u < 8; u++) {
            int k = k0 + lk + u;
            float v = 0.f;
            if (rv) {
                if (MODE == 0)      v = p0[k];
                else if (MODE == 1) v = (k < 64) ? p0[k] : ((k < 96) ? p1[k - 64] : p2[k - 96]);
                else if (MODE == 2) v = (k < 64) ? p0[k] : p1[k - 64];
                else if (MODE == 3) v = (k < 128) ? p0[k] : p1[k - 128];
                else                v = (k < 64) ? p0[k] : p1[k - 64];
            }
            As[lk + u][lm] = v;
        }
        // load B chunk
        {
            float4 bv = make_float4(0.f, 0.f, 0.f, 0.f);
            if (cv) bv = *(const float4*)(W + (size_t)(k0 + bk) * NOUT + (cbase + bn));
            *(float4*)&Bs[bk][bn] = bv;
        }
        __syncthreads();

#pragma unroll
        for (int kk = 0; kk < 16; kk++) {
            float4 b4 = *(const float4*)&Bs[kk][tx * 4];
            unsigned long long bx = bcast2(b4.x);
            unsigned long long by = bcast2(b4.y);
            unsigned long long bz = bcast2(b4.z);
            unsigned long long bw = bcast2(b4.w);
            const unsigned long long* ap =
                (const unsigned long long*)&As[kk][ty * 8];
#pragma unroll
            for (int p = 0; p < 4; p++) {
                unsigned long long a2 = ap[p];
                ffma2(acc[p][0], a2, bx);
                ffma2(acc[p][1], a2, by);
                ffma2(acc[p][2], a2, bz);
                ffma2(acc[p][3], a2, bw);
            }
        }
        __syncthreads();
    }

    // epilogue: bias + relu, vectorized store
    const int c = cbase + tx * 4;
    if (c < NOUT) {
        float4 bb = *(const float4*)(bias + c);
#pragma unroll
        for (int p = 0; p < 4; p++) {
            float2 q0 = unpack2(acc[p][0]);
            float2 q1 = unpack2(acc[p][1]);
            float2 q2 = unpack2(acc[p][2]);
            float2 q3 = unpack2(acc[p][3]);
            int r0 = rbase + ty * 8 + 2 * p;
            if (r0 < R) {
                float4 o;
                o.x = fmaxf(q0.x + bb.x, 0.f);
                o.y = fmaxf(q1.x + bb.y, 0.f);
                o.z = fmaxf(q2.x + bb.z, 0.f);
                o.w = fmaxf(q3.x + bb.w, 0.f);
                *(float4*)(C + (size_t)r0 * NOUT + c) = o;
            }
            if (r0 + 1 < R) {
                float4 o;
                o.x = fmaxf(q0.y + bb.x, 0.f);
                o.y = fmaxf(q1.y + bb.y, 0.f);
                o.z = fmaxf(q2.y + bb.z, 0.f);
                o.w = fmaxf(q3.y + bb.w, 0.f);
                *(float4*)(C + (size_t)(r0 + 1) * NOUT + c) = o;
            }
        }
    }
}

// ---------------- node aggregation: mean of hn over incoming edges ----------
__global__ void pn_agg_kernel() {
    const int i = blockIdx.x;            // node
    const int b = blockIdx.y;            // batch
    const int ch = threadIdx.x;          // 128 channels
    const int t  = min(i, 32);
    const int k0 = group_start(i);
    float s = 0.f;
    const float* src = g_hn + ((size_t)(b * NEg + k0)) * 128 + ch;
    for (int l = 0; l < t; l++) s += src[(size_t)l * 128];
    const float nrm = 1.f / (float)max(t, 1);
    g_pn[((size_t)(b * NN + i)) * 128 + ch] = s * nrm;
}

// ---------------- edge aggregation: exclusive in-group prefix mean ----------
__global__ void pe_agg_kernel() {
    const int i = blockIdx.x + 1;        // node (groups exist for i>=1)
    const int b = blockIdx.y;
    const int ch = threadIdx.x;          // 64 channels
    const int t  = min(i, 32);
    const int k0 = group_start(i);
    float run = 0.f;
    size_t base = ((size_t)(b * NEg + k0)) * 64 + ch;
    for (int l = 0; l < t; l++) {
        float nrm = (l > 0) ? (1.f / (float)l) : 1.f;
        g_pe[base] = run * nrm;
        run += g_he[base];
        base += 64;
    }
}

// ---------------- launch -----------------------------------------------------
extern "C" void kernel_launch(void* const* d_in, const int* in_sizes, int n_in,
                              void* d_out, int out_size) {
    const float* nodes = (const float*)d_in[0];
    const float* edges = (const float*)d_in[1];
    const float* Wan1  = (const float*)d_in[2];
    const float* ban1  = (const float*)d_in[3];
    const float* Wan2  = (const float*)d_in[4];
    const float* ban2  = (const float*)d_in[5];
    const float* Wln1  = (const float*)d_in[6];
    const float* bln1  = (const float*)d_in[7];
    const float* Wln2  = (const float*)d_in[8];
    const float* bln2  = (const float*)d_in[9];
    const float* Wae1  = (const float*)d_in[10];
    const float* bae1  = (const float*)d_in[11];
    const float* Wae2  = (const float*)d_in[12];
    const float* bae2  = (const float*)d_in[13];
    const float* Wle1  = (const float*)d_in[14];
    const float* ble1  = (const float*)d_in[15];
    const float* Wle2  = (const float*)d_in[16];
    const float* ble2  = (const float*)d_in[17];

    float* out_nodes = (float*)d_out;                         // [2,1024,64]
    float* out_edges = (float*)d_out + (size_t)BBc * NN * 64; // [2,NE,32]

    float *h1n, *hn, *h3n, *h1e, *he, *h3e;
    cudaGetSymbolAddress((void**)&h1n, g_h1n);
    cudaGetSymbolAddress((void**)&hn,  g_hn);
    cudaGetSymbolAddress((void**)&h3n, g_h3n);
    cudaGetSymbolAddress((void**)&h1e, g_h1e);
    cudaGetSymbolAddress((void**)&he,  g_he);
    cudaGetSymbolAddress((void**)&h3e, g_h3e);

    const int gbE = (RE + 127) / 128;    // 504 row tiles for edge rows
    const int gbN = (RN + 127) / 128;    // 16 row tiles for node rows

    build_eij_kernel<<<(NEg + 255) / 256, 256>>>();

    // node branch
    gemm_bias_relu<160, 256, 1><<<dim3(4, gbE), 256>>>(nullptr, Wan1, ban1, h1n, RE, nodes, edges);
    gemm_bias_relu<256, 128, 0><<<dim3(2, gbE), 256>>>(h1n,     Wan2, ban2, hn,  RE, nodes, edges);
    pn_agg_kernel<<<dim3(NN, BBc), 128>>>();
    gemm_bias_relu<192, 192, 3><<<dim3(3, gbN), 256>>>(nullptr, Wln1, bln1, h3n, RN, nodes, edges);
    gemm_bias_relu<192,  64, 0><<<dim3(1, gbN), 256>>>(h3n,     Wln2, bln2, out_nodes, RN, nodes, edges);

    // edge branch
    gemm_bias_relu< 96, 128, 2><<<dim3(2, gbE), 256>>>(nullptr, Wae1, bae1, h1e, RE, nodes, edges);
    gemm_bias_relu<128,  64, 0><<<dim3(1, gbE), 256>>>(h1e,     Wae2, bae2, he,  RE, nodes, edges);
    pe_agg_kernel<<<dim3(NN - 1, BBc), 64>>>();
    gemm_bias_relu< 96,  96, 4><<<dim3(2, gbE), 256>>>(nullptr, Wle1, ble1, h3e, RE, nodes, edges);
    gemm_bias_relu< 96,  32, 0><<<dim3(1, gbE), 256>>>(h3e,     Wle2, ble2, out_edges, RE, nodes, edges);
}

// round 4
// speedup vs baseline: 2.8664x; 1.6655x over previous
#include <cuda_runtime.h>
#include <math.h>

// Problem constants (match the reference's _build_indices(N=1024, M=32))
#define NN   1024
#define MMW  32
#define NEg  32240          // total edges
#define BBc  2
#define RE   (BBc*NEg)      // 64480 edge rows
#define RN   (BBc*NN)       // 2048 node rows

// ---------------- scratch (static device globals; no runtime allocs) -------
__device__ int2  g_eij[NEg];              // (i=target, j=source) per edge
__device__ float g_U  [(size_t)RN*256];   // nodes @ Wan1[0:64]       (no relu)
__device__ float g_V  [(size_t)RN*256];   // nodes @ Wan1[96:160]     (no relu)
__device__ float g_P  [(size_t)RN*128];   // nodes @ Wae1[0:64]       (no relu)
__device__ float g_E1 [(size_t)RE*256];   // edges @ Wan1[64:96]+ban1 (no relu)
__device__ float g_E2 [(size_t)RE*128];   // edges @ Wae1[64:96]+bae1 (no relu)
__device__ float g_hn [(size_t)RE*128];
__device__ float g_pn [(size_t)RN*128];
__device__ float g_h3n[(size_t)RN*192];
__device__ float g_he [(size_t)RE*64];
__device__ float g_pe [(size_t)RE*64];
__device__ float g_h3e[(size_t)RE*96];

// ---------------- f32x2 packed-FMA helpers ----------------------------------
__device__ __forceinline__ void ffma2(unsigned long long& d,
                                      unsigned long long a,
                                      unsigned long long b) {
    asm("fma.rn.f32x2 %0, %1, %2, %0;" : "+l"(d) : "l"(a), "l"(b));
}
__device__ __forceinline__ unsigned long long bcast2(float x) {
    unsigned long long r;
    asm("mov.b64 %0, {%1, %1};" : "=l"(r) : "f"(x));
    return r;
}
__device__ __forceinline__ float2 unpack2(unsigned long long v) {
    float2 f;
    asm("mov.b64 {%0, %1}, %2;" : "=f"(f.x), "=f"(f.y) : "l"(v));
    return f;
}

// ---------------- edge index builder ---------------------------------------
__global__ void build_eij_kernel() {
    int e = blockIdx.x * blockDim.x + threadIdx.x;
    if (e >= NEg) return;
    int i, j;
    if (e < 496) {                       // i in 1..31, k0 = i(i-1)/2, j0 = 0
        i = (int)((1.0f + sqrtf(8.0f * (float)e + 1.0f)) * 0.5f);
        while (i * (i - 1) / 2 > e) i--;
        while ((i + 1) * i / 2 <= e) i++;
        j = e - i * (i - 1) / 2;
    } else {                             // i >= 32, k0 = 496 + (i-32)*32, j0 = i-32
        int q = (e - 496) >> 5;
        i = 32 + q;
        j = (i - 32) + ((e - 496) & 31);
    }
    g_eij[e] = make_int2(i, j);
}

__device__ __forceinline__ int group_start(int i) {
    return (i <= 32) ? (i * (i - 1) / 2) : (496 + (i - 32) * 32);
}

__device__ __forceinline__ float4 relu4(float4 v) {
    v.x = fmaxf(v.x, 0.f); v.y = fmaxf(v.y, 0.f);
    v.z = fmaxf(v.z, 0.f); v.w = fmaxf(v.w, 0.f);
    return v;
}
__device__ __forceinline__ float4 add4(float4 a, float4 b) {
    return make_float4(a.x + b.x, a.y + b.y, a.z + b.z, a.w + b.w);
}

// ---------------- fused gather + GEMM + bias + (relu) -----------------------
// C[R x NOUT] = act(A_src[R x K] @ W[K x NOUT] (+ bias)),  act = relu iff RELU
// MODE 0: A plain [R x K]
// MODE 3: A = X0[r](128) ++ X1[r](64)                      (K=192)
// MODE 4: A = X0[r](64)  ++ X1[r](32)                      (K=96)
// MODE 5: A[k] = relu(E1[r][k] + U[j][k] + V[i][k])        (K=256)
// MODE 6: A[k] = relu(E2[r][k] + P[j][k])                  (K=128)
template<int K, int NOUT, int MODE, bool RELU>
__global__ __launch_bounds__(256, 2)
void gemm_bias_relu(const float* __restrict__ A,
                    const float* __restrict__ W, int ldW,
                    const float* __restrict__ bias,
                    float* __restrict__ C, int R,
                    const float* __restrict__ X0,
                    const float* __restrict__ X1,
                    const float* __restrict__ X2)
{
    __shared__ __align__(16) float As[2][32][128];  // [buf][k][m]
    __shared__ __align__(16) float Bs[2][32][64];

    const int tid   = threadIdx.x;
    const int tx    = tid & 15;          // 16 col-groups (4 cols each)
    const int ty    = tid >> 4;          // 16 row-groups (8 rows each)
    const int rbase = blockIdx.y * 128;
    const int cbase = blockIdx.x * 64;

    // ---- A-load mapping: 2 threads per row, 16 consecutive k's each ----
    const int lm = tid >> 1;             // 0..127 (row within tile)
    const int lk = (tid & 1) * 16;       // 0 or 16
    const int r  = rbase + lm;
    const bool rv = (r < R);

    const float* p0 = nullptr;
    const float* p1 = nullptr;
    const float* p2 = nullptr;
    if (rv) {
        if (MODE == 0) {
            p0 = A + (size_t)r * K;
        } else if (MODE == 3) {
            p0 = X0 + (size_t)r * 128;   // pn
            p1 = X1 + (size_t)r * 64;    // nodes
        } else if (MODE == 4) {
            p0 = X0 + (size_t)r * 64;    // pe
            p1 = X1 + (size_t)r * 32;    // edges
        } else if (MODE == 5) {
            int b = (r >= NEg) ? 1 : 0;
            int e = r - b * NEg;
            int2 ij = g_eij[e];
            p0 = X0 + (size_t)r * 256;                  // E1
            p1 = X1 + ((size_t)(b * NN + ij.y)) * 256;  // U[j]
            p2 = X2 + ((size_t)(b * NN + ij.x)) * 256;  // V[i]
        } else { // MODE 6
            int b = (r >= NEg) ? 1 : 0;
            int e = r - b * NEg;
            int2 ij = g_eij[e];
            p0 = X0 + (size_t)r * 128;                  // E2
            p1 = X1 + ((size_t)(b * NN + ij.y)) * 128;  // P[j]
        }
    }

    // ---- B-load mapping: two float4 rows per thread per chunk ----
    const int bk = tid >> 4;             // 0..15 (k within chunk; +16 for 2nd)
    const int bn = (tid & 15) * 4;       // 0..60
    const bool cv = (cbase + bn < NOUT);

    // accumulators: 4 row-pairs x 4 cols, packed f32x2 (lo=even row, hi=odd)
    unsigned long long acc[4][4];
#pragma unroll
    for (int p = 0; p < 4; p++)
#pragma unroll
        for (int v = 0; v < 4; v++) acc[p][v] = 0ull;

    float4 apf[4];
    float4 bpf[2];

    // per-chunk A prefetch into registers
    auto loadA = [&](int k0) {
        const int kb = k0 + lk;
#pragma unroll
        for (int u = 0; u < 4; u++) apf[u] = make_float4(0.f, 0.f, 0.f, 0.f);
        if (!rv) return;
        if (MODE == 0) {
#pragma unroll
            for (int u = 0; u < 4; u++) apf[u] = *(const float4*)(p0 + kb + 4 * u);
        } else if (MODE == 3) {
            const float* s = (kb < 128) ? (p0 + kb) : (p1 + kb - 128);
#pragma unroll
            for (int u = 0; u < 4; u++) apf[u] = *(const float4*)(s + 4 * u);
        } else if (MODE == 4) {
            const float* s = (kb < 64) ? (p0 + kb) : (p1 + kb - 64);
#pragma unroll
            for (int u = 0; u < 4; u++) apf[u] = *(const float4*)(s + 4 * u);
        } else if (MODE == 5) {
#pragma unroll
            for (int u = 0; u < 4; u++) {
                float4 e = *(const float4*)(p0 + kb + 4 * u);
                float4 uu = *(const float4*)(p1 + kb + 4 * u);
                float4 vv = *(const float4*)(p2 + kb + 4 * u);
                apf[u] = relu4(add4(add4(e, uu), vv));
            }
        } else { // MODE 6
#pragma unroll
            for (int u = 0; u < 4; u++) {
                float4 e = *(const float4*)(p0 + kb + 4 * u);
                float4 pp = *(const float4*)(p1 + kb + 4 * u);
                apf[u] = relu4(add4(e, pp));
            }
        }
    };
    auto loadB = [&](int k0) {
        bpf[0] = make_float4(0.f, 0.f, 0.f, 0.f);
        bpf[1] = make_float4(0.f, 0.f, 0.f, 0.f);
        if (cv) {
            bpf[0] = *(const float4*)(W + (size_t)(k0 + bk) * ldW + (cbase + bn));
            bpf[1] = *(const float4*)(W + (size_t)(k0 + bk + 16) * ldW + (cbase + bn));
        }
    };
    auto stsA = [&](int buf) {
#pragma unroll
        for (int u = 0; u < 4; u++) {
            As[buf][lk + 4 * u + 0][lm] = apf[u].x;
            As[buf][lk + 4 * u + 1][lm] = apf[u].y;
            As[buf][lk + 4 * u + 2][lm] = apf[u].z;
            As[buf][lk + 4 * u + 3][lm] = apf[u].w;
        }
    };
    auto stsB = [&](int buf) {
        *(float4*)&Bs[buf][bk][bn]      = bpf[0];
        *(float4*)&Bs[buf][bk + 16][bn] = bpf[1];
    };

    constexpr int NC = K / 32;
    loadA(0); loadB(0);
    stsA(0);  stsB(0);
    __syncthreads();

#pragma unroll
    for (int c = 0; c < NC; c++) {
        const int cur = c & 1;
        if (c + 1 < NC) { loadA((c + 1) * 32); loadB((c + 1) * 32); }

#pragma unroll
        for (int kk = 0; kk < 32; kk++) {
            float4 b4 = *(const float4*)&Bs[cur][kk][tx * 4];
            unsigned long long bx = bcast2(b4.x);
            unsigned long long by = bcast2(b4.y);
            unsigned long long bz = bcast2(b4.z);
            unsigned long long bw = bcast2(b4.w);
            ulonglong2 a01 = *(const ulonglong2*)&As[cur][kk][ty * 8];
            ulonglong2 a23 = *(const ulonglong2*)&As[cur][kk][ty * 8 + 4];
            ffma2(acc[0][0], a01.x, bx); ffma2(acc[0][1], a01.x, by);
            ffma2(acc[0][2], a01.x, bz); ffma2(acc[0][3], a01.x, bw);
            ffma2(acc[1][0], a01.y, bx); ffma2(acc[1][1], a01.y, by);
            ffma2(acc[1][2], a01.y, bz); ffma2(acc[1][3], a01.y, bw);
            ffma2(acc[2][0], a23.x, bx); ffma2(acc[2][1], a23.x, by);
            ffma2(acc[2][2], a23.x, bz); ffma2(acc[2][3], a23.x, bw);
            ffma2(acc[3][0], a23.y, bx); ffma2(acc[3][1], a23.y, by);
            ffma2(acc[3][2], a23.y, bz); ffma2(acc[3][3], a23.y, bw);
        }

        if (c + 1 < NC) { stsA(1 - cur); stsB(1 - cur); }
        __syncthreads();
    }

    // epilogue: bias (+ relu), vectorized store
    const int c = cbase + tx * 4;
    if (c < NOUT) {
        float4 bb = make_float4(0.f, 0.f, 0.f, 0.f);
        if (bias) bb = *(const float4*)(bias + c);
        auto act = [](float v) { return RELU ? fmaxf(v, 0.f) : v; };
#pragma unroll
        for (int p = 0; p < 4; p++) {
            float2 q0 = unpack2(acc[p][0]);
            float2 q1 = unpack2(acc[p][1]);
            float2 q2 = unpack2(acc[p][2]);
            float2 q3 = unpack2(acc[p][3]);
            int r0 = rbase + ty * 8 + 2 * p;
            if (r0 < R) {
                float4 o;
                o.x = act(q0.x + bb.x);
                o.y = act(q1.x + bb.y);
                o.z = act(q2.x + bb.z);
                o.w = act(q3.x + bb.w);
                *(float4*)(C + (size_t)r0 * NOUT + c) = o;
            }
            if (r0 + 1 < R) {
                float4 o;
                o.x = act(q0.y + bb.x);
                o.y = act(q1.y + bb.y);
                o.z = act(q2.y + bb.z);
                o.w = act(q3.y + bb.w);
                *(float4*)(C + (size_t)(r0 + 1) * NOUT + c) = o;
            }
        }
    }
}

// ---------------- node aggregation: mean of hn over incoming edges ----------
// grid (NN/4, BBc), block 128: one warp per node, 32 lanes x float4 channels
__global__ void pn_agg_kernel() {
    const int w    = threadIdx.x >> 5;
    const int lane = threadIdx.x & 31;
    const int i    = blockIdx.x * 4 + w;
    const int b    = blockIdx.y;
    const int t    = min(i, 32);
    const int k0   = group_start(i);
    float4 s = make_float4(0.f, 0.f, 0.f, 0.f);
    const float* src = g_hn + ((size_t)(b * NEg + k0)) * 128 + lane * 4;
    for (int l = 0; l < t; l++) {
        float4 v = *(const float4*)src;
        s = add4(s, v);
        src += 128;
    }
    const float nrm = 1.f / (float)max(t, 1);
    s.x *= nrm; s.y *= nrm; s.z *= nrm; s.w *= nrm;
    *(float4*)(g_pn + ((size_t)(b * NN + i)) * 128 + lane * 4) = s;
}

// ---------------- edge aggregation: exclusive in-group prefix mean ----------
// grid (NN/4, BBc), block 128: one warp per node group, 32 lanes x float2
__global__ void pe_agg_kernel() {
    const int w    = threadIdx.x >> 5;
    const int lane = threadIdx.x & 31;
    const int i    = blockIdx.x * 4 + w;
    const int b    = blockIdx.y;
    if (i == 0) return;
    const int t  = min(i, 32);
    const int k0 = group_start(i);
    float2 run = make_float2(0.f, 0.f);
    size_t base = ((size_t)(b * NEg + k0)) * 64 + lane * 2;
    for (int l = 0; l < t; l++) {
        float nrm = (l > 0) ? (1.f / (float)l) : 1.f;
        *(float2*)(g_pe + base) = make_float2(run.x * nrm, run.y * nrm);
        float2 h = *(const float2*)(g_he + base);
        run.x += h.x; run.y += h.y;
        base += 64;
    }
}

// ---------------- launch -----------------------------------------------------
extern "C" void kernel_launch(void* const* d_in, const int* in_sizes, int n_in,
                              void* d_out, int out_size) {
    const float* nodes = (const float*)d_in[0];
    const float* edges = (const float*)d_in[1];
    const float* Wan1  = (const float*)d_in[2];
    const float* ban1  = (const float*)d_in[3];
    const float* Wan2  = (const float*)d_in[4];
    const float* ban2  = (const float*)d_in[5];
    const float* Wln1  = (const float*)d_in[6];
    const float* bln1  = (const float*)d_in[7];
    const float* Wln2  = (const float*)d_in[8];
    const float* bln2  = (const float*)d_in[9];
    const float* Wae1  = (const float*)d_in[10];
    const float* bae1  = (const float*)d_in[11];
    const float* Wae2  = (const float*)d_in[12];
    const float* bae2  = (const float*)d_in[13];
    const float* Wle1  = (const float*)d_in[14];
    const float* ble1  = (const float*)d_in[15];
    const float* Wle2  = (const float*)d_in[16];
    const float* ble2  = (const float*)d_in[17];

    float* out_nodes = (float*)d_out;                         // [2,1024,64]
    float* out_edges = (float*)d_out + (size_t)BBc * NN * 64; // [2,NE,32]

    float *U, *V, *P, *E1, *E2, *hn, *pn, *h3n, *he, *pe, *h3e;
    cudaGetSymbolAddress((void**)&U,   g_U);
    cudaGetSymbolAddress((void**)&V,   g_V);
    cudaGetSymbolAddress((void**)&P,   g_P);
    cudaGetSymbolAddress((void**)&E1,  g_E1);
    cudaGetSymbolAddress((void**)&E2,  g_E2);
    cudaGetSymbolAddress((void**)&hn,  g_hn);
    cudaGetSymbolAddress((void**)&pn,  g_pn);
    cudaGetSymbolAddress((void**)&h3n, g_h3n);
    cudaGetSymbolAddress((void**)&he,  g_he);
    cudaGetSymbolAddress((void**)&pe,  g_pe);
    cudaGetSymbolAddress((void**)&h3e, g_h3e);

    const int gbE = (RE + 127) / 128;    // 504 row tiles for edge rows
    const int gbN = (RN + 127) / 128;    // 16 row tiles for node rows

    build_eij_kernel<<<(NEg + 255) / 256, 256>>>();

    // per-node precomputes (A = nodes, K = 64)  -- NO relu (raw linear parts)
    gemm_bias_relu<64, 256, 0, false><<<dim3(4, gbN), 256>>>(nodes, Wan1,            256, nullptr, U, RN, nullptr, nullptr, nullptr);
    gemm_bias_relu<64, 256, 0, false><<<dim3(4, gbN), 256>>>(nodes, Wan1 + 96 * 256, 256, nullptr, V, RN, nullptr, nullptr, nullptr);
    gemm_bias_relu<64, 128, 0, false><<<dim3(2, gbN), 256>>>(nodes, Wae1,            128, nullptr, P, RN, nullptr, nullptr, nullptr);

    // per-edge first-layer parts -- NO relu (bias folded here)
    gemm_bias_relu<32, 256, 0, false><<<dim3(4, gbE), 256>>>(edges, Wan1 + 64 * 256, 256, ban1, E1, RE, nullptr, nullptr, nullptr);
    gemm_bias_relu<32, 128, 0, false><<<dim3(2, gbE), 256>>>(edges, Wae1 + 64 * 128, 128, bae1, E2, RE, nullptr, nullptr, nullptr);

    // node branch: L2 (A fused = relu(E1+U[j]+V[i])), agg, L3, L4
    gemm_bias_relu<256, 128, 5, true><<<dim3(2, gbE), 256>>>(nullptr, Wan2, 128, ban2, hn, RE, E1, U, V);
    pn_agg_kernel<<<dim3(NN / 4, BBc), 128>>>();
    gemm_bias_relu<192, 192, 3, true><<<dim3(3, gbN), 256>>>(nullptr, Wln1, 192, bln1, h3n, RN, pn, nodes, nullptr);
    gemm_bias_relu<192,  64, 0, true><<<dim3(1, gbN), 256>>>(h3n,     Wln2,  64, bln2, out_nodes, RN, nullptr, nullptr, nullptr);

    // edge branch: L2 (A fused = relu(E2+P[j])), agg, L3, L4
    gemm_bias_relu<128,  64, 6, true><<<dim3(1, gbE), 256>>>(nullptr, Wae2,  64, bae2, he, RE, E2, P, nullptr);
    pe_agg_kernel<<<dim3(NN / 4, BBc), 128>>>();
    gemm_bias_relu< 96,  96, 4, true><<<dim3(2, gbE), 256>>>(nullptr, Wle1,  96, ble1, h3e, RE, pe, edges, nullptr);
    gemm_bias_relu< 96,  32, 0, true><<<dim3(1, gbE), 256>>>(h3e,     Wle2,  32, ble2, out_edges, RE, nullptr, nullptr, nullptr);
}

// round 6
// speedup vs baseline: 3.2301x; 1.1269x over previous
#include <cuda_runtime.h>
#include <cuda_bf16.h>
#include <math.h>
#include <stdint.h>

// Problem constants (match the reference's _build_indices(N=1024, M=32))
#define NN   1024
#define MMW  32
#define NEg  32240          // total edges
#define BBc  2
#define RE   (BBc*NEg)      // 64480 edge rows
#define RN   (BBc*NN)       // 2048 node rows

// ---------------- scratch (static device globals; no runtime allocs) -------
__device__ int2  g_eij[NEg];              // (i=target, j=source) per edge
__device__ float g_U  [(size_t)RN*256];   // nodes @ Wan1[0:64]       (no relu)
__device__ float g_V  [(size_t)RN*256];   // nodes @ Wan1[96:160]     (no relu)
__device__ float g_P  [(size_t)RN*128];   // nodes @ Wae1[0:64]       (no relu)
__device__ float g_E1 [(size_t)RE*256];   // edges @ Wan1[64:96]+ban1 (no relu)
__device__ float g_E2 [(size_t)RE*128];   // edges @ Wae1[64:96]+bae1 (no relu)
__device__ float g_hn [(size_t)RE*128];
__device__ float g_pn [(size_t)RN*128];
__device__ float g_h3n[(size_t)RN*192];
__device__ float g_he [(size_t)RE*64];
__device__ float g_pe [(size_t)RE*64];
__device__ float g_h3e[(size_t)RE*96];
// bf16 hi/lo split of Wan2, stored as B[n][k] (transposed), n=128, k=256
__device__ unsigned short g_Bhi[128*256];
__device__ unsigned short g_Blo[128*256];

// ---------------- f32x2 packed-FMA helpers ----------------------------------
__device__ __forceinline__ void ffma2(unsigned long long& d,
                                      unsigned long long a,
                                      unsigned long long b) {
    asm("fma.rn.f32x2 %0, %1, %2, %0;" : "+l"(d) : "l"(a), "l"(b));
}
__device__ __forceinline__ unsigned long long bcast2(float x) {
    unsigned long long r;
    asm("mov.b64 %0, {%1, %1};" : "=l"(r) : "f"(x));
    return r;
}
__device__ __forceinline__ float2 unpack2(unsigned long long v) {
    float2 f;
    asm("mov.b64 {%0, %1}, %2;" : "=f"(f.x), "=f"(f.y) : "l"(v));
    return f;
}

// ---------------- mma.sync helpers (family-portable, no 'a' features) -------
__device__ __forceinline__ uint32_t smem_u32(const void* p) {
    uint32_t a;
    asm("{ .reg .u64 t; cvta.to.shared.u64 t, %1; cvt.u32.u64 %0, t; }"
        : "=r"(a) : "l"(p));
    return a;
}
__device__ __forceinline__ void ldsm_x4(uint32_t& r0, uint32_t& r1,
                                        uint32_t& r2, uint32_t& r3,
                                        uint32_t addr) {
    asm volatile("ldmatrix.sync.aligned.m8n8.x4.shared.b16 {%0,%1,%2,%3}, [%4];"
                 : "=r"(r0), "=r"(r1), "=r"(r2), "=r"(r3) : "r"(addr));
}
__device__ __forceinline__ void mma_bf16(float& c0, float& c1, float& c2, float& c3,
                                         uint32_t a0, uint32_t a1, uint32_t a2, uint32_t a3,
                                         uint32_t b0, uint32_t b1) {
    asm volatile("mma.sync.aligned.m16n8k16.row.col.f32.bf16.bf16.f32 "
                 "{%0,%1,%2,%3}, {%4,%5,%6,%7}, {%8,%9}, {%0,%1,%2,%3};"
                 : "+f"(c0), "+f"(c1), "+f"(c2), "+f"(c3)
                 : "r"(a0), "r"(a1), "r"(a2), "r"(a3), "r"(b0), "r"(b1));
}

static __device__ __forceinline__ unsigned short bf16_bits(__nv_bfloat16 h) {
    return *reinterpret_cast<unsigned short*>(&h);
}

// ---------------- edge index builder ---------------------------------------
__global__ void build_eij_kernel() {
    int e = blockIdx.x * blockDim.x + threadIdx.x;
    if (e >= NEg) return;
    int i, j;
    if (e < 496) {                       // i in 1..31, k0 = i(i-1)/2, j0 = 0
        i = (int)((1.0f + sqrtf(8.0f * (float)e + 1.0f)) * 0.5f);
        while (i * (i - 1) / 2 > e) i--;
        while ((i + 1) * i / 2 <= e) i++;
        j = e - i * (i - 1) / 2;
    } else {                             // i >= 32
        int q = (e - 496) >> 5;
        i = 32 + q;
        j = (i - 32) + ((e - 496) & 31);
    }
    g_eij[e] = make_int2(i, j);
}

__device__ __forceinline__ int group_start(int i) {
    return (i <= 32) ? (i * (i - 1) / 2) : (496 + (i - 32) * 32);
}

__device__ __forceinline__ float4 relu4(float4 v) {
    v.x = fmaxf(v.x, 0.f); v.y = fmaxf(v.y, 0.f);
    v.z = fmaxf(v.z, 0.f); v.w = fmaxf(v.w, 0.f);
    return v;
}
__device__ __forceinline__ float4 add4(float4 a, float4 b) {
    return make_float4(a.x + b.x, a.y + b.y, a.z + b.z, a.w + b.w);
}

// ---------------- Wan2 bf16 hi/lo split (B[n][k] = W[k][n]) -----------------
__global__ void split_Wan2_kernel(const float* __restrict__ Wan2) {
    int idx = blockIdx.x * blockDim.x + threadIdx.x;  // 0..32767
    if (idx >= 128 * 256) return;
    int n = idx >> 8;
    int k = idx & 255;
    float w = Wan2[(size_t)k * 128 + n];
    __nv_bfloat16 hi = __float2bfloat16(w);
    float rem = w - __bfloat162float(hi);
    __nv_bfloat16 lo = __float2bfloat16(rem);
    g_Bhi[(size_t)n * 256 + k] = bf16_bits(hi);
    g_Blo[(size_t)n * 256 + k] = bf16_bits(lo);
}

// ---------------- mma.sync bf16x3 kernel: hn = relu((E1+U+V)@Wan2 + ban2) ---
// grid 504 (M-tiles of 128 rows), block 512 (16 warps: warp_m = wid&3,
// warp_n = wid>>2). N = 128 full, K = 256 in 8 chunks of 32.
// smem rows padded to 80B -> ldmatrix 8-address phases hit distinct banks.
#define A_STRIDE 40          // bf16 elems per row (80 B)
#define SM_AHI 0
#define SM_ALO 10240
#define SM_BHI 20480
#define SM_BLO 30720

__global__ __launch_bounds__(512, 1)
void hn_mma_kernel(const float* __restrict__ E1,
                   const float* __restrict__ U,
                   const float* __restrict__ V,
                   const float* __restrict__ bias,
                   float* __restrict__ C)
{
    __shared__ __align__(16) char smem[40960];
    const uint32_t sb = smem_u32(smem);

    const int tid   = threadIdx.x;
    const int wid   = tid >> 5;
    const int lane  = tid & 31;
    const int warp_m = wid & 3;          // 4 row groups of 32
    const int warp_n = wid >> 2;         // 4 col groups of 32
    const int rbase = blockIdx.x * 128;

    // ---- loader mapping: 4 threads per row, 8 elems each ----
    const int lrow = tid >> 2;           // 0..127
    const int lk   = (tid & 3) * 8;      // 0,8,16,24
    const int r    = rbase + lrow;
    const bool rv  = (r < RE);

    const float* pe1 = nullptr;
    const float* pu  = nullptr;
    const float* pv  = nullptr;
    if (rv) {
        int b = (r >= NEg) ? 1 : 0;
        int e = r - b * NEg;
        int2 ij = g_eij[e];
        pe1 = E1 + (size_t)r * 256;
        pu  = U + ((size_t)(b * NN + ij.y)) * 256;
        pv  = V + ((size_t)(b * NN + ij.x)) * 256;
    }

    // staged regs for next chunk
    float  a_st[8];
    uint4  b_st_hi, b_st_lo;

    auto loadregs = [&](int k0) {
        // A: fused relu(E1 + U[j] + V[i]) for 8 consecutive k
        if (rv) {
            float4 e0 = *(const float4*)(pe1 + k0 + lk);
            float4 e1 = *(const float4*)(pe1 + k0 + lk + 4);
            float4 u0 = *(const float4*)(pu + k0 + lk);
            float4 u1 = *(const float4*)(pu + k0 + lk + 4);
            float4 v0 = *(const float4*)(pv + k0 + lk);
            float4 v1 = *(const float4*)(pv + k0 + lk + 4);
            float4 s0 = relu4(add4(add4(e0, u0), v0));
            float4 s1 = relu4(add4(add4(e1, u1), v1));
            a_st[0] = s0.x; a_st[1] = s0.y; a_st[2] = s0.z; a_st[3] = s0.w;
            a_st[4] = s1.x; a_st[5] = s1.y; a_st[6] = s1.z; a_st[7] = s1.w;
        } else {
#pragma unroll
            for (int q = 0; q < 8; q++) a_st[q] = 0.f;
        }
        // B: 8 bf16 hi + 8 bf16 lo (row n = lrow)
        b_st_hi = *(const uint4*)(g_Bhi + (size_t)lrow * 256 + k0 + lk);
        b_st_lo = *(const uint4*)(g_Blo + (size_t)lrow * 256 + k0 + lk);
    };
    auto stsregs = [&]() {
        uint32_t hp[4], lp[4];
#pragma unroll
        for (int q = 0; q < 4; q++) {
            __nv_bfloat16 h0 = __float2bfloat16(a_st[2 * q]);
            __nv_bfloat16 h1 = __float2bfloat16(a_st[2 * q + 1]);
            float r0 = a_st[2 * q]     - __bfloat162float(h0);
            float r1 = a_st[2 * q + 1] - __bfloat162float(h1);
            __nv_bfloat16 l0 = __float2bfloat16(r0);
            __nv_bfloat16 l1 = __float2bfloat16(r1);
            hp[q] = (uint32_t)bf16_bits(h0) | ((uint32_t)bf16_bits(h1) << 16);
            lp[q] = (uint32_t)bf16_bits(l0) | ((uint32_t)bf16_bits(l1) << 16);
        }
        uint32_t off = (uint32_t)(lrow * (A_STRIDE * 2) + lk * 2);
        *(uint4*)(smem + SM_AHI + off) = make_uint4(hp[0], hp[1], hp[2], hp[3]);
        *(uint4*)(smem + SM_ALO + off) = make_uint4(lp[0], lp[1], lp[2], lp[3]);
        *(uint4*)(smem + SM_BHI + off) = b_st_hi;
        *(uint4*)(smem + SM_BLO + off) = b_st_lo;
    };

    // accumulators: 2 m16 tiles x 4 n8 tiles x 4 regs
    float acc[2][4][4];
#pragma unroll
    for (int mt = 0; mt < 2; mt++)
#pragma unroll
        for (int nt = 0; nt < 4; nt++)
#pragma unroll
            for (int q = 0; q < 4; q++) acc[mt][nt][q] = 0.f;

    // ldmatrix per-lane address components
    const int a_m   = warp_m * 32 + (lane & 7) + ((lane >> 3) & 1) * 8;
    const int a_koff = (lane >> 4) * 8;               // + ks*16
    const int b_n   = warp_n * 32 + (lane & 7) + (lane >> 4) * 8;
    const int b_koff = ((lane >> 3) & 1) * 8;         // + ks*16

    loadregs(0);
#pragma unroll 1
    for (int c = 0; c < 8; c++) {
        stsregs();
        __syncthreads();
        if (c < 7) loadregs((c + 1) * 32);            // LDG overlapped with mma

#pragma unroll
        for (int ks = 0; ks < 2; ks++) {
            uint32_t ahi[2][4], alo[2][4];
#pragma unroll
            for (int mt = 0; mt < 2; mt++) {
                uint32_t ad = sb + SM_AHI +
                    (uint32_t)((a_m + mt * 16) * (A_STRIDE * 2) +
                               (ks * 16 + a_koff) * 2);
                ldsm_x4(ahi[mt][0], ahi[mt][1], ahi[mt][2], ahi[mt][3], ad);
                ldsm_x4(alo[mt][0], alo[mt][1], alo[mt][2], alo[mt][3],
                        ad + (SM_ALO - SM_AHI));
            }
            uint32_t bhi[4][2], blo[4][2];
#pragma unroll
            for (int p = 0; p < 2; p++) {             // ntile pairs
                uint32_t bd = sb + SM_BHI +
                    (uint32_t)((b_n + p * 16) * (A_STRIDE * 2) +
                               (ks * 16 + b_koff) * 2);
                ldsm_x4(bhi[2 * p][0], bhi[2 * p][1],
                        bhi[2 * p + 1][0], bhi[2 * p + 1][1], bd);
                ldsm_x4(blo[2 * p][0], blo[2 * p][1],
                        blo[2 * p + 1][0], blo[2 * p + 1][1],
                        bd + (SM_BLO - SM_BHI));
            }
#pragma unroll
            for (int mt = 0; mt < 2; mt++)
#pragma unroll
                for (int nt = 0; nt < 4; nt++) {
                    float* d = acc[mt][nt];
                    mma_bf16(d[0], d[1], d[2], d[3],
                             ahi[mt][0], ahi[mt][1], ahi[mt][2], ahi[mt][3],
                             bhi[nt][0], bhi[nt][1]);
                    mma_bf16(d[0], d[1], d[2], d[3],
                             ahi[mt][0], ahi[mt][1], ahi[mt][2], ahi[mt][3],
                             blo[nt][0], blo[nt][1]);
                    mma_bf16(d[0], d[1], d[2], d[3],
                             alo[mt][0], alo[mt][1], alo[mt][2], alo[mt][3],
                             bhi[nt][0], bhi[nt][1]);
                }
        }
        __syncthreads();
    }

    // ---- epilogue: bias + relu, float2 stores ----
    const int lq = lane & 3;
    const int lr = lane >> 2;
#pragma unroll
    for (int mt = 0; mt < 2; mt++) {
        int m0 = rbase + warp_m * 32 + mt * 16 + lr;
#pragma unroll
        for (int nt = 0; nt < 4; nt++) {
            int cc = warp_n * 32 + nt * 8 + lq * 2;
            float2 bb = *(const float2*)(bias + cc);
            if (m0 < RE) {
                float2 o;
                o.x = fmaxf(acc[mt][nt][0] + bb.x, 0.f);
                o.y = fmaxf(acc[mt][nt][1] + bb.y, 0.f);
                *(float2*)(C + (size_t)m0 * 128 + cc) = o;
            }
            if (m0 + 8 < RE) {
                float2 o;
                o.x = fmaxf(acc[mt][nt][2] + bb.x, 0.f);
                o.y = fmaxf(acc[mt][nt][3] + bb.y, 0.f);
                *(float2*)(C + (size_t)(m0 + 8) * 128 + cc) = o;
            }
        }
    }
}

// ---------------- fused gather + GEMM + bias + (relu) -----------------------
// C[R x NOUT] = act(A_src[R x K] @ W[K x NOUT] (+ bias)),  act = relu iff RELU
// MODE 0: A plain [R x K]
// MODE 3: A = X0[r](128) ++ X1[r](64)                      (K=192)
// MODE 4: A = X0[r](64)  ++ X1[r](32)                      (K=96)
// MODE 6: A[k] = relu(E2[r][k] + P[j][k])                  (K=128)
template<int K, int NOUT, int MODE, bool RELU>
__global__ __launch_bounds__(256, 2)
void gemm_bias_relu(const float* __restrict__ A,
                    const float* __restrict__ W, int ldW,
                    const float* __restrict__ bias,
                    float* __restrict__ C, int R,
                    const float* __restrict__ X0,
                    const float* __restrict__ X1,
                    const float* __restrict__ X2)
{
    __shared__ __align__(16) float As[2][32][128];  // [buf][k][m]
    __shared__ __align__(16) float Bs[2][32][64];

    const int tid   = threadIdx.x;
    const int tx    = tid & 15;          // 16 col-groups (4 cols each)
    const int ty    = tid >> 4;          // 16 row-groups (8 rows each)
    const int rbase = blockIdx.y * 128;
    const int cbase = blockIdx.x * 64;

    const int lm = tid >> 1;             // 0..127 (row within tile)
    const int lk = (tid & 1) * 16;       // 0 or 16
    const int r  = rbase + lm;
    const bool rv = (r < R);

    const float* p0 = nullptr;
    const float* p1 = nullptr;
    if (rv) {
        if (MODE == 0) {
            p0 = A + (size_t)r * K;
        } else if (MODE == 3) {
            p0 = X0 + (size_t)r * 128;   // pn
            p1 = X1 + (size_t)r * 64;    // nodes
        } else if (MODE == 4) {
            p0 = X0 + (size_t)r * 64;    // pe
            p1 = X1 + (size_t)r * 32;    // edges
        } else { // MODE 6
            int b = (r >= NEg) ? 1 : 0;
            int e = r - b * NEg;
            int2 ij = g_eij[e];
            p0 = X0 + (size_t)r * 128;                  // E2
            p1 = X1 + ((size_t)(b * NN + ij.y)) * 128;  // P[j]
        }
    }

    const int bk = tid >> 4;             // 0..15
    const int bn = (tid & 15) * 4;       // 0..60
    const bool cv = (cbase + bn < NOUT);

    unsigned long long acc[4][4];
#pragma unroll
    for (int p = 0; p < 4; p++)
#pragma unroll
        for (int v = 0; v < 4; v++) acc[p][v] = 0ull;

    float4 apf[4];
    float4 bpf[2];

    auto loadA = [&](int k0) {
        const int kb = k0 + lk;
#pragma unroll
        for (int u = 0; u < 4; u++) apf[u] = make_float4(0.f, 0.f, 0.f, 0.f);
        if (!rv) return;
        if (MODE == 0) {
#pragma unroll
            for (int u = 0; u < 4; u++) apf[u] = *(const float4*)(p0 + kb + 4 * u);
        } else if (MODE == 3) {
            const float* s = (kb < 128) ? (p0 + kb) : (p1 + kb - 128);
#pragma unroll
            for (int u = 0; u < 4; u++) apf[u] = *(const float4*)(s + 4 * u);
        } else if (MODE == 4) {
            const float* s = (kb < 64) ? (p0 + kb) : (p1 + kb - 64);
#pragma unroll
            for (int u = 0; u < 4; u++) apf[u] = *(const float4*)(s + 4 * u);
        } else { // MODE 6
#pragma unroll
            for (int u = 0; u < 4; u++) {
                float4 e = *(const float4*)(p0 + kb + 4 * u);
                float4 pp = *(const float4*)(p1 + kb + 4 * u);
                apf[u] = relu4(add4(e, pp));
            }
        }
    };
    auto loadB = [&](int k0) {
        bpf[0] = make_float4(0.f, 0.f, 0.f, 0.f);
        bpf[1] = make_float4(0.f, 0.f, 0.f, 0.f);
        if (cv) {
            bpf[0] = *(const float4*)(W + (size_t)(k0 + bk) * ldW + (cbase + bn));
            bpf[1] = *(const float4*)(W + (size_t)(k0 + bk + 16) * ldW + (cbase + bn));
        }
    };
    auto stsA = [&](int buf) {
#pragma unroll
        for (int u = 0; u < 4; u++) {
            As[buf][lk + 4 * u + 0][lm] = apf[u].x;
            As[buf][lk + 4 * u + 1][lm] = apf[u].y;
            As[buf][lk + 4 * u + 2][lm] = apf[u].z;
            As[buf][lk + 4 * u + 3][lm] = apf[u].w;
        }
    };
    auto stsB = [&](int buf) {
        *(float4*)&Bs[buf][bk][bn]      = bpf[0];
        *(float4*)&Bs[buf][bk + 16][bn] = bpf[1];
    };

    constexpr int NC = K / 32;
    loadA(0); loadB(0);
    stsA(0);  stsB(0);
    __syncthreads();

#pragma unroll
    for (int c = 0; c < NC; c++) {
        const int cur = c & 1;
        if (c + 1 < NC) { loadA((c + 1) * 32); loadB((c + 1) * 32); }

#pragma unroll
        for (int kk = 0; kk < 32; kk++) {
            float4 b4 = *(const float4*)&Bs[cur][kk][tx * 4];
            unsigned long long bx = bcast2(b4.x);
            unsigned long long by = bcast2(b4.y);
            unsigned long long bz = bcast2(b4.z);
            unsigned long long bw = bcast2(b4.w);
            ulonglong2 a01 = *(const ulonglong2*)&As[cur][kk][ty * 8];
            ulonglong2 a23 = *(const ulonglong2*)&As[cur][kk][ty * 8 + 4];
            ffma2(acc[0][0], a01.x, bx); ffma2(acc[0][1], a01.x, by);
            ffma2(acc[0][2], a01.x, bz); ffma2(acc[0][3], a01.x, bw);
            ffma2(acc[1][0], a01.y, bx); ffma2(acc[1][1], a01.y, by);
            ffma2(acc[1][2], a01.y, bz); ffma2(acc[1][3], a01.y, bw);
            ffma2(acc[2][0], a23.x, bx); ffma2(acc[2][1], a23.x, by);
            ffma2(acc[2][2], a23.x, bz); ffma2(acc[2][3], a23.x, bw);
            ffma2(acc[3][0], a23.y, bx); ffma2(acc[3][1], a23.y, by);
            ffma2(acc[3][2], a23.y, bz); ffma2(acc[3][3], a23.y, bw);
        }

        if (c + 1 < NC) { stsA(1 - cur); stsB(1 - cur); }
        __syncthreads();
    }

    const int c = cbase + tx * 4;
    if (c < NOUT) {
        float4 bb = make_float4(0.f, 0.f, 0.f, 0.f);
        if (bias) bb = *(const float4*)(bias + c);
        auto act = [](float v) { return RELU ? fmaxf(v, 0.f) : v; };
#pragma unroll
        for (int p = 0; p < 4; p++) {
            float2 q0 = unpack2(acc[p][0]);
            float2 q1 = unpack2(acc[p][1]);
            float2 q2 = unpack2(acc[p][2]);
            float2 q3 = unpack2(acc[p][3]);
            int r0 = rbase + ty * 8 + 2 * p;
            if (r0 < R) {
                float4 o;
                o.x = act(q0.x + bb.x);
                o.y = act(q1.x + bb.y);
                o.z = act(q2.x + bb.z);
                o.w = act(q3.x + bb.w);
                *(float4*)(C + (size_t)r0 * NOUT + c) = o;
            }
            if (r0 + 1 < R) {
                float4 o;
                o.x = act(q0.y + bb.x);
                o.y = act(q1.y + bb.y);
                o.z = act(q2.y + bb.z);
                o.w = act(q3.y + bb.w);
                *(float4*)(C + (size_t)(r0 + 1) * NOUT + c) = o;
            }
        }
    }
}

// ---------------- node aggregation: mean of hn over incoming edges ----------
__global__ void pn_agg_kernel() {
    const int w    = threadIdx.x >> 5;
    const int lane = threadIdx.x & 31;
    const int i    = blockIdx.x * 4 + w;
    const int b    = blockIdx.y;
    const int t    = min(i, 32);
    const int k0   = group_start(i);
    float4 s = make_float4(0.f, 0.f, 0.f, 0.f);
    const float* src = g_hn + ((size_t)(b * NEg + k0)) * 128 + lane * 4;
    for (int l = 0; l < t; l++) {
        float4 v = *(const float4*)src;
        s = add4(s, v);
        src += 128;
    }
    const float nrm = 1.f / (float)max(t, 1);
    s.x *= nrm; s.y *= nrm; s.z *= nrm; s.w *= nrm;
    *(float4*)(g_pn + ((size_t)(b * NN + i)) * 128 + lane * 4) = s;
}

// ---------------- edge aggregation: exclusive in-group prefix mean ----------
__global__ void pe_agg_kernel() {
    const int w    = threadIdx.x >> 5;
    const int lane = threadIdx.x & 31;
    const int i    = blockIdx.x * 4 + w;
    const int b    = blockIdx.y;
    if (i == 0) return;
    const int t  = min(i, 32);
    const int k0 = group_start(i);
    float2 run = make_float2(0.f, 0.f);
    size_t base = ((size_t)(b * NEg + k0)) * 64 + lane * 2;
    for (int l = 0; l < t; l++) {
        float nrm = (l > 0) ? (1.f / (float)l) : 1.f;
        *(float2*)(g_pe + base) = make_float2(run.x * nrm, run.y * nrm);
        float2 h = *(const float2*)(g_he + base);
        run.x += h.x; run.y += h.y;
        base += 64;
    }
}

// ---------------- launch -----------------------------------------------------
extern "C" void kernel_launch(void* const* d_in, const int* in_sizes, int n_in,
                              void* d_out, int out_size) {
    const float* nodes = (const float*)d_in[0];
    const float* edges = (const float*)d_in[1];
    const float* Wan1  = (const float*)d_in[2];
    const float* ban1  = (const float*)d_in[3];
    const float* Wan2  = (const float*)d_in[4];
    const float* ban2  = (const float*)d_in[5];
    const float* Wln1  = (const float*)d_in[6];
    const float* bln1  = (const float*)d_in[7];
    const float* Wln2  = (const float*)d_in[8];
    const float* bln2  = (const float*)d_in[9];
    const float* Wae1  = (const float*)d_in[10];
    const float* bae1  = (const float*)d_in[11];
    const float* Wae2  = (const float*)d_in[12];
    const float* bae2  = (const float*)d_in[13];
    const float* Wle1  = (const float*)d_in[14];
    const float* ble1  = (const float*)d_in[15];
    const float* Wle2  = (const float*)d_in[16];
    const float* ble2  = (const float*)d_in[17];

    float* out_nodes = (float*)d_out;                         // [2,1024,64]
    float* out_edges = (float*)d_out + (size_t)BBc * NN * 64; // [2,NE,32]

    float *U, *V, *P, *E1, *E2, *hn, *pn, *h3n, *he, *pe, *h3e;
    cudaGetSymbolAddress((void**)&U,   g_U);
    cudaGetSymbolAddress((void**)&V,   g_V);
    cudaGetSymbolAddress((void**)&P,   g_P);
    cudaGetSymbolAddress((void**)&E1,  g_E1);
    cudaGetSymbolAddress((void**)&E2,  g_E2);
    cudaGetSymbolAddress((void**)&hn,  g_hn);
    cudaGetSymbolAddress((void**)&pn,  g_pn);
    cudaGetSymbolAddress((void**)&h3n, g_h3n);
    cudaGetSymbolAddress((void**)&he,  g_he);
    cudaGetSymbolAddress((void**)&pe,  g_pe);
    cudaGetSymbolAddress((void**)&h3e, g_h3e);

    const int gbE = (RE + 127) / 128;    // 504 row tiles for edge rows
    const int gbN = (RN + 127) / 128;    // 16 row tiles for node rows

    build_eij_kernel<<<(NEg + 255) / 256, 256>>>();
    split_Wan2_kernel<<<128, 256>>>(Wan2);

    // per-node precomputes (A = nodes, K = 64)  -- NO relu (raw linear parts)
    gemm_bias_relu<64, 256, 0, false><<<dim3(4, gbN), 256>>>(nodes, Wan1,            256, nullptr, U, RN, nullptr, nullptr, nullptr);
    gemm_bias_relu<64, 256, 0, false><<<dim3(4, gbN), 256>>>(nodes, Wan1 + 96 * 256, 256, nullptr, V, RN, nullptr, nullptr, nullptr);
    gemm_bias_relu<64, 128, 0, false><<<dim3(2, gbN), 256>>>(nodes, Wae1,            128, nullptr, P, RN, nullptr, nullptr, nullptr);

    // per-edge first-layer parts -- NO relu (bias folded here)
    gemm_bias_relu<32, 256, 0, false><<<dim3(4, gbE), 256>>>(edges, Wan1 + 64 * 256, 256, ban1, E1, RE, nullptr, nullptr, nullptr);
    gemm_bias_relu<32, 128, 0, false><<<dim3(2, gbE), 256>>>(edges, Wae1 + 64 * 128, 128, bae1, E2, RE, nullptr, nullptr, nullptr);

    // node branch: L2 on tensor cores (mma.sync bf16x3), agg, L3, L4
    hn_mma_kernel<<<gbE, 512>>>(E1, U, V, ban2, hn);
    pn_agg_kernel<<<dim3(NN / 4, BBc), 128>>>();
    gemm_bias_relu<192, 192, 3, true><<<dim3(3, gbN), 256>>>(nullptr, Wln1, 192, bln1, h3n, RN, pn, nodes, nullptr);
    gemm_bias_relu<192,  64, 0, true><<<dim3(1, gbN), 256>>>(h3n,     Wln2,  64, bln2, out_nodes, RN, nullptr, nullptr, nullptr);

    // edge branch: L2 (A fused = relu(E2+P[j])), agg, L3, L4
    gemm_bias_relu<128,  64, 6, true><<<dim3(1, gbE), 256>>>(nullptr, Wae2,  64, bae2, he, RE, E2, P, nullptr);
    pe_agg_kernel<<<dim3(NN / 4, BBc), 128>>>();
    gemm_bias_relu< 96,  96, 4, true><<<dim3(2, gbE), 256>>>(nullptr, Wle1,  96, ble1, h3e, RE, pe, edges, nullptr);
    gemm_bias_relu< 96,  32, 0, true><<<dim3(1, gbE), 256>>>(h3e,     Wle2,  32, ble2, out_edges, RE, nullptr, nullptr, nullptr);
}

// round 7
// speedup vs baseline: 3.6910x; 1.1427x over previous
#include <cuda_runtime.h>
#include <cuda_bf16.h>
#include <math.h>
#include <stdint.h>

// Problem constants (match the reference's _build_indices(N=1024, M=32))
#define NN   1024
#define MMW  32
#define NEg  32240          // total edges
#define BBc  2
#define RE   (BBc*NEg)      // 64480 edge rows
#define RN   (BBc*NN)       // 2048 node rows

// ---------------- scratch (static device globals; no runtime allocs) -------
__device__ int2  g_eij[NEg];              // (i=target, j=source) per edge
__device__ float g_U  [(size_t)RN*256];   // nodes @ Wan1[0:64]       (no relu)
__device__ float g_V  [(size_t)RN*256];   // nodes @ Wan1[96:160]     (no relu)
__device__ float g_P  [(size_t)RN*128];   // nodes @ Wae1[0:64]       (no relu)
__device__ float g_E1 [(size_t)RE*256];   // edges @ Wan1[64:96]+ban1 (no relu)
__device__ float g_E2 [(size_t)RE*128];   // edges @ Wae1[64:96]+bae1 (no relu)
__device__ float g_hn [(size_t)RE*128];
__device__ float g_pn [(size_t)RN*128];
__device__ float g_h3n[(size_t)RN*192];
__device__ float g_he [(size_t)RE*64];
__device__ float g_pe [(size_t)RE*64];
__device__ float g_h3e[(size_t)RE*96];
// bf16 hi/lo splits of weights, stored as B[n][k] (transposed)
__device__ unsigned short g_Bhi  [128*256];   // Wan2
__device__ unsigned short g_Blo  [128*256];
__device__ unsigned short g_BheH [64*128];    // Wae2
__device__ unsigned short g_BheL [64*128];
__device__ unsigned short g_B3eH [96*96];     // Wle1
__device__ unsigned short g_B3eL [96*96];
__device__ unsigned short g_BoeH [32*96];     // Wle2
__device__ unsigned short g_BoeL [32*96];

// ---------------- f32x2 packed-FMA helpers ----------------------------------
__device__ __forceinline__ void ffma2(unsigned long long& d,
                                      unsigned long long a,
                                      unsigned long long b) {
    asm("fma.rn.f32x2 %0, %1, %2, %0;" : "+l"(d) : "l"(a), "l"(b));
}
__device__ __forceinline__ unsigned long long bcast2(float x) {
    unsigned long long r;
    asm("mov.b64 %0, {%1, %1};" : "=l"(r) : "f"(x));
    return r;
}
__device__ __forceinline__ float2 unpack2(unsigned long long v) {
    float2 f;
    asm("mov.b64 {%0, %1}, %2;" : "=f"(f.x), "=f"(f.y) : "l"(v));
    return f;
}

// ---------------- mma.sync helpers (family-portable, no 'a' features) -------
__device__ __forceinline__ uint32_t smem_u32(const void* p) {
    uint32_t a;
    asm("{ .reg .u64 t; cvta.to.shared.u64 t, %1; cvt.u32.u64 %0, t; }"
        : "=r"(a) : "l"(p));
    return a;
}
__device__ __forceinline__ void ldsm_x4(uint32_t& r0, uint32_t& r1,
                                        uint32_t& r2, uint32_t& r3,
                                        uint32_t addr) {
    asm volatile("ldmatrix.sync.aligned.m8n8.x4.shared.b16 {%0,%1,%2,%3}, [%4];"
                 : "=r"(r0), "=r"(r1), "=r"(r2), "=r"(r3) : "r"(addr));
}
__device__ __forceinline__ void mma_bf16(float& c0, float& c1, float& c2, float& c3,
                                         uint32_t a0, uint32_t a1, uint32_t a2, uint32_t a3,
                                         uint32_t b0, uint32_t b1) {
    asm volatile("mma.sync.aligned.m16n8k16.row.col.f32.bf16.bf16.f32 "
                 "{%0,%1,%2,%3}, {%4,%5,%6,%7}, {%8,%9}, {%0,%1,%2,%3};"
                 : "+f"(c0), "+f"(c1), "+f"(c2), "+f"(c3)
                 : "r"(a0), "r"(a1), "r"(a2), "r"(a3), "r"(b0), "r"(b1));
}

static __device__ __forceinline__ unsigned short bf16_bits(__nv_bfloat16 h) {
    return *reinterpret_cast<unsigned short*>(&h);
}
__device__ __forceinline__ void split_pack8(const float* vals,
                                            uint32_t* hp, uint32_t* lp) {
#pragma unroll
    for (int q = 0; q < 4; q++) {
        __nv_bfloat16 h0 = __float2bfloat16(vals[2 * q]);
        __nv_bfloat16 h1 = __float2bfloat16(vals[2 * q + 1]);
        float r0 = vals[2 * q]     - __bfloat162float(h0);
        float r1 = vals[2 * q + 1] - __bfloat162float(h1);
        __nv_bfloat16 l0 = __float2bfloat16(r0);
        __nv_bfloat16 l1 = __float2bfloat16(r1);
        hp[q] = (uint32_t)bf16_bits(h0) | ((uint32_t)bf16_bits(h1) << 16);
        lp[q] = (uint32_t)bf16_bits(l0) | ((uint32_t)bf16_bits(l1) << 16);
    }
}

// ---------------- edge index builder ---------------------------------------
__global__ void build_eij_kernel() {
    int e = blockIdx.x * blockDim.x + threadIdx.x;
    if (e >= NEg) return;
    int i, j;
    if (e < 496) {                       // i in 1..31, k0 = i(i-1)/2, j0 = 0
        i = (int)((1.0f + sqrtf(8.0f * (float)e + 1.0f)) * 0.5f);
        while (i * (i - 1) / 2 > e) i--;
        while ((i + 1) * i / 2 <= e) i++;
        j = e - i * (i - 1) / 2;
    } else {                             // i >= 32
        int q = (e - 496) >> 5;
        i = 32 + q;
        j = (i - 32) + ((e - 496) & 31);
    }
    g_eij[e] = make_int2(i, j);
}

__device__ __forceinline__ int group_start(int i) {
    return (i <= 32) ? (i * (i - 1) / 2) : (496 + (i - 32) * 32);
}

__device__ __forceinline__ float4 relu4(float4 v) {
    v.x = fmaxf(v.x, 0.f); v.y = fmaxf(v.y, 0.f);
    v.z = fmaxf(v.z, 0.f); v.w = fmaxf(v.w, 0.f);
    return v;
}
__device__ __forceinline__ float4 add4(float4 a, float4 b) {
    return make_float4(a.x + b.x, a.y + b.y, a.z + b.z, a.w + b.w);
}

// ---------------- all weight splits in one launch ---------------------------
__device__ __forceinline__ void split_store(float w, unsigned short* hi,
                                            unsigned short* lo, size_t o) {
    __nv_bfloat16 h = __float2bfloat16(w);
    float rem = w - __bfloat162float(h);
    hi[o] = bf16_bits(h);
    lo[o] = bf16_bits(__float2bfloat16(rem));
}
__global__ void split_all_kernel(const float* __restrict__ Wan2,
                                 const float* __restrict__ Wae2,
                                 const float* __restrict__ Wle1,
                                 const float* __restrict__ Wle2) {
    int idx = blockIdx.x * blockDim.x + threadIdx.x;
    if (idx < 32768) {                                   // Wan2 [256][128]
        int k = idx >> 7, n = idx & 127;
        split_store(Wan2[idx], g_Bhi, g_Blo, (size_t)n * 256 + k);
    } else if (idx < 32768 + 8192) {                     // Wae2 [128][64]
        int t = idx - 32768;
        int k = t >> 6, n = t & 63;
        split_store(Wae2[t], g_BheH, g_BheL, (size_t)n * 128 + k);
    } else if (idx < 32768 + 8192 + 9216) {              // Wle1 [96][96]
        int t = idx - 32768 - 8192;
        int k = t / 96, n = t % 96;
        split_store(Wle1[t], g_B3eH, g_B3eL, (size_t)n * 96 + k);
    } else if (idx < 32768 + 8192 + 9216 + 3072) {       // Wle2 [96][32]
        int t = idx - 32768 - 8192 - 9216;
        int k = t >> 5, n = t & 31;
        split_store(Wle2[t], g_BoeH, g_BoeL, (size_t)n * 96 + k);
    }
}

// ---------------- mma.sync bf16x3 kernel: hn = relu((E1+U+V)@Wan2 + ban2) ---
// (unchanged from the 289us round — proven)
#define A_STRIDE 40          // bf16 elems per row (80 B)
#define SM_AHI 0
#define SM_ALO 10240
#define SM_BHI 20480
#define SM_BLO 30720

__global__ __launch_bounds__(512, 1)
void hn_mma_kernel(const float* __restrict__ E1,
                   const float* __restrict__ U,
                   const float* __restrict__ V,
                   const float* __restrict__ bias,
                   float* __restrict__ C)
{
    __shared__ __align__(16) char smem[40960];
    const uint32_t sb = smem_u32(smem);

    const int tid   = threadIdx.x;
    const int wid   = tid >> 5;
    const int lane  = tid & 31;
    const int warp_m = wid & 3;
    const int warp_n = wid >> 2;
    const int rbase = blockIdx.x * 128;

    const int lrow = tid >> 2;
    const int lk   = (tid & 3) * 8;
    const int r    = rbase + lrow;
    const bool rv  = (r < RE);

    const float* pe1 = nullptr;
    const float* pu  = nullptr;
    const float* pv  = nullptr;
    if (rv) {
        int b = (r >= NEg) ? 1 : 0;
        int e = r - b * NEg;
        int2 ij = g_eij[e];
        pe1 = E1 + (size_t)r * 256;
        pu  = U + ((size_t)(b * NN + ij.y)) * 256;
        pv  = V + ((size_t)(b * NN + ij.x)) * 256;
    }

    float  a_st[8];
    uint4  b_st_hi, b_st_lo;

    auto loadregs = [&](int k0) {
        if (rv) {
            float4 e0 = *(const float4*)(pe1 + k0 + lk);
            float4 e1 = *(const float4*)(pe1 + k0 + lk + 4);
            float4 u0 = *(const float4*)(pu + k0 + lk);
            float4 u1 = *(const float4*)(pu + k0 + lk + 4);
            float4 v0 = *(const float4*)(pv + k0 + lk);
            float4 v1 = *(const float4*)(pv + k0 + lk + 4);
            float4 s0 = relu4(add4(add4(e0, u0), v0));
            float4 s1 = relu4(add4(add4(e1, u1), v1));
            a_st[0] = s0.x; a_st[1] = s0.y; a_st[2] = s0.z; a_st[3] = s0.w;
            a_st[4] = s1.x; a_st[5] = s1.y; a_st[6] = s1.z; a_st[7] = s1.w;
        } else {
#pragma unroll
            for (int q = 0; q < 8; q++) a_st[q] = 0.f;
        }
        b_st_hi = *(const uint4*)(g_Bhi + (size_t)lrow * 256 + k0 + lk);
        b_st_lo = *(const uint4*)(g_Blo + (size_t)lrow * 256 + k0 + lk);
    };
    auto stsregs = [&]() {
        uint32_t hp[4], lp[4];
        split_pack8(a_st, hp, lp);
        uint32_t off = (uint32_t)(lrow * (A_STRIDE * 2) + lk * 2);
        *(uint4*)(smem + SM_AHI + off) = make_uint4(hp[0], hp[1], hp[2], hp[3]);
        *(uint4*)(smem + SM_ALO + off) = make_uint4(lp[0], lp[1], lp[2], lp[3]);
        *(uint4*)(smem + SM_BHI + off) = b_st_hi;
        *(uint4*)(smem + SM_BLO + off) = b_st_lo;
    };

    float acc[2][4][4];
#pragma unroll
    for (int mt = 0; mt < 2; mt++)
#pragma unroll
        for (int nt = 0; nt < 4; nt++)
#pragma unroll
            for (int q = 0; q < 4; q++) acc[mt][nt][q] = 0.f;

    const int a_m   = warp_m * 32 + (lane & 7) + ((lane >> 3) & 1) * 8;
    const int a_koff = (lane >> 4) * 8;
    const int b_n   = warp_n * 32 + (lane & 7) + (lane >> 4) * 8;
    const int b_koff = ((lane >> 3) & 1) * 8;

    loadregs(0);
#pragma unroll 1
    for (int c = 0; c < 8; c++) {
        stsregs();
        __syncthreads();
        if (c < 7) loadregs((c + 1) * 32);

#pragma unroll
        for (int ks = 0; ks < 2; ks++) {
            uint32_t ahi[2][4], alo[2][4];
#pragma unroll
            for (int mt = 0; mt < 2; mt++) {
                uint32_t ad = sb + SM_AHI +
                    (uint32_t)((a_m + mt * 16) * (A_STRIDE * 2) +
                               (ks * 16 + a_koff) * 2);
                ldsm_x4(ahi[mt][0], ahi[mt][1], ahi[mt][2], ahi[mt][3], ad);
                ldsm_x4(alo[mt][0], alo[mt][1], alo[mt][2], alo[mt][3],
                        ad + (SM_ALO - SM_AHI));
            }
            uint32_t bhi[4][2], blo[4][2];
#pragma unroll
            for (int p = 0; p < 2; p++) {
                uint32_t bd = sb + SM_BHI +
                    (uint32_t)((b_n + p * 16) * (A_STRIDE * 2) +
                               (ks * 16 + b_koff) * 2);
                ldsm_x4(bhi[2 * p][0], bhi[2 * p][1],
                        bhi[2 * p + 1][0], bhi[2 * p + 1][1], bd);
                ldsm_x4(blo[2 * p][0], blo[2 * p][1],
                        blo[2 * p + 1][0], blo[2 * p + 1][1],
                        bd + (SM_BLO - SM_BHI));
            }
#pragma unroll
            for (int mt = 0; mt < 2; mt++)
#pragma unroll
                for (int nt = 0; nt < 4; nt++) {
                    float* d = acc[mt][nt];
                    mma_bf16(d[0], d[1], d[2], d[3],
                             ahi[mt][0], ahi[mt][1], ahi[mt][2], ahi[mt][3],
                             bhi[nt][0], bhi[nt][1]);
                    mma_bf16(d[0], d[1], d[2], d[3],
                             ahi[mt][0], ahi[mt][1], ahi[mt][2], ahi[mt][3],
                             blo[nt][0], blo[nt][1]);
                    mma_bf16(d[0], d[1], d[2], d[3],
                             alo[mt][0], alo[mt][1], alo[mt][2], alo[mt][3],
                             bhi[nt][0], bhi[nt][1]);
                }
        }
        __syncthreads();
    }

    const int lq = lane & 3;
    const int lr = lane >> 2;
#pragma unroll
    for (int mt = 0; mt < 2; mt++) {
        int m0 = rbase + warp_m * 32 + mt * 16 + lr;
#pragma unroll
        for (int nt = 0; nt < 4; nt++) {
            int cc = warp_n * 32 + nt * 8 + lq * 2;
            float2 bb = *(const float2*)(bias + cc);
            if (m0 < RE) {
                float2 o;
                o.x = fmaxf(acc[mt][nt][0] + bb.x, 0.f);
                o.y = fmaxf(acc[mt][nt][1] + bb.y, 0.f);
                *(float2*)(C + (size_t)m0 * 128 + cc) = o;
            }
            if (m0 + 8 < RE) {
                float2 o;
                o.x = fmaxf(acc[mt][nt][2] + bb.x, 0.f);
                o.y = fmaxf(acc[mt][nt][3] + bb.y, 0.f);
                *(float2*)(C + (size_t)(m0 + 8) * 128 + cc) = o;
            }
        }
    }
}

// ---------------- generalized mma.sync bf16x3 GEMM --------------------------
// C[R x NOUT] = relu(A[R x K] @ Wsplit + bias)
// MMODE 0: A = X0[r] (plain, row stride K)
// MMODE 1: A[k] = relu(X0[r][k] + X1[b*NN+j][k])  (he: E2 + P[j], K=128)
// MMODE 2: A = X0[r](64) ++ X1[r](32)             (h3e: pe ++ edges, K=96)
template<int K, int NOUT, int WM, int WN, int MMODE>
__global__ __launch_bounds__(WM * WN * 32)
void mma_gemm(const float* __restrict__ X0,
              const float* __restrict__ X1,
              const unsigned short* __restrict__ Bhi,
              const unsigned short* __restrict__ Blo,
              const float* __restrict__ bias,
              float* __restrict__ C, int R)
{
    constexpr int MT  = WM * 32;
    constexpr int NTH = WM * WN * 32;
    __shared__ __align__(16) unsigned short sAhi[MT * A_STRIDE];
    __shared__ __align__(16) unsigned short sAlo[MT * A_STRIDE];
    __shared__ __align__(16) unsigned short sBhi[NOUT * A_STRIDE];
    __shared__ __align__(16) unsigned short sBlo[NOUT * A_STRIDE];

    const int tid  = threadIdx.x;
    const int wid  = tid >> 5;
    const int lane = tid & 31;
    const int warp_m = wid % WM;
    const int warp_n = wid / WM;
    const int rbase = blockIdx.x * MT;

    float acc[2][4][4];
#pragma unroll
    for (int mt = 0; mt < 2; mt++)
#pragma unroll
        for (int nt = 0; nt < 4; nt++)
#pragma unroll
            for (int q = 0; q < 4; q++) acc[mt][nt][q] = 0.f;

    const int a_m    = warp_m * 32 + (lane & 7) + ((lane >> 3) & 1) * 8;
    const int a_koff = (lane >> 4) * 8;
    const int b_n    = warp_n * 32 + (lane & 7) + (lane >> 4) * 8;
    const int b_koff = ((lane >> 3) & 1) * 8;

    const uint32_t sb_ahi = smem_u32(sAhi);
    const uint32_t sb_alo = smem_u32(sAlo);
    const uint32_t sb_bhi = smem_u32(sBhi);
    const uint32_t sb_blo = smem_u32(sBlo);

#pragma unroll 1
    for (int c = 0; c < K / 32; c++) {
        const int k0 = c * 32;
        // ---- A loader ----
        for (int idx = tid; idx < MT * 4; idx += NTH) {
            const int row = idx >> 2;
            const int lk  = (idx & 3) * 8;
            const int r   = rbase + row;
            const int kb  = k0 + lk;
            float vals[8];
            if (r < R) {
                if (MMODE == 0) {
                    float4 v0 = *(const float4*)(X0 + (size_t)r * K + kb);
                    float4 v1 = *(const float4*)(X0 + (size_t)r * K + kb + 4);
                    vals[0] = v0.x; vals[1] = v0.y; vals[2] = v0.z; vals[3] = v0.w;
                    vals[4] = v1.x; vals[5] = v1.y; vals[6] = v1.z; vals[7] = v1.w;
                } else if (MMODE == 1) {
                    int b = (r >= NEg) ? 1 : 0;
                    int e = r - b * NEg;
                    int2 ij = g_eij[e];
                    const float* pa = X0 + (size_t)r * 128 + kb;
                    const float* pb = X1 + ((size_t)(b * NN + ij.y)) * 128 + kb;
                    float4 s0 = relu4(add4(*(const float4*)pa,
                                           *(const float4*)pb));
                    float4 s1 = relu4(add4(*(const float4*)(pa + 4),
                                           *(const float4*)(pb + 4)));
                    vals[0] = s0.x; vals[1] = s0.y; vals[2] = s0.z; vals[3] = s0.w;
                    vals[4] = s1.x; vals[5] = s1.y; vals[6] = s1.z; vals[7] = s1.w;
                } else { // MMODE 2: pe(64) ++ edges(32)
                    const float* s = (kb < 64) ? (X0 + (size_t)r * 64 + kb)
                                               : (X1 + (size_t)r * 32 + kb - 64);
                    float4 v0 = *(const float4*)s;
                    float4 v1 = *(const float4*)(s + 4);
                    vals[0] = v0.x; vals[1] = v0.y; vals[2] = v0.z; vals[3] = v0.w;
                    vals[4] = v1.x; vals[5] = v1.y; vals[6] = v1.z; vals[7] = v1.w;
                }
            } else {
#pragma unroll
                for (int q = 0; q < 8; q++) vals[q] = 0.f;
            }
            uint32_t hp[4], lp[4];
            split_pack8(vals, hp, lp);
            uint32_t off = (uint32_t)(row * A_STRIDE + lk) * 2;
            *(uint4*)((char*)sAhi + off) = make_uint4(hp[0], hp[1], hp[2], hp[3]);
            *(uint4*)((char*)sAlo + off) = make_uint4(lp[0], lp[1], lp[2], lp[3]);
        }
        // ---- B loader ----
        for (int idx = tid; idx < NOUT * 4; idx += NTH) {
            const int n  = idx >> 2;
            const int lk = (idx & 3) * 8;
            uint4 hv = *(const uint4*)(Bhi + (size_t)n * K + k0 + lk);
            uint4 lv = *(const uint4*)(Blo + (size_t)n * K + k0 + lk);
            uint32_t off = (uint32_t)(n * A_STRIDE + lk) * 2;
            *(uint4*)((char*)sBhi + off) = hv;
            *(uint4*)((char*)sBlo + off) = lv;
        }
        __syncthreads();

#pragma unroll
        for (int ks = 0; ks < 2; ks++) {
            uint32_t ahi[2][4], alo[2][4];
#pragma unroll
            for (int mt = 0; mt < 2; mt++) {
                uint32_t ad = sb_ahi +
                    (uint32_t)((a_m + mt * 16) * (A_STRIDE * 2) +
                               (ks * 16 + a_koff) * 2);
                ldsm_x4(ahi[mt][0], ahi[mt][1], ahi[mt][2], ahi[mt][3], ad);
                ldsm_x4(alo[mt][0], alo[mt][1], alo[mt][2], alo[mt][3],
                        ad + (sb_alo - sb_ahi));
            }
            uint32_t bhi[4][2], blo[4][2];
#pragma unroll
            for (int p = 0; p < 2; p++) {
                uint32_t bd = sb_bhi +
                    (uint32_t)((b_n + p * 16) * (A_STRIDE * 2) +
                               (ks * 16 + b_koff) * 2);
                ldsm_x4(bhi[2 * p][0], bhi[2 * p][1],
                        bhi[2 * p + 1][0], bhi[2 * p + 1][1], bd);
                ldsm_x4(blo[2 * p][0], blo[2 * p][1],
                        blo[2 * p + 1][0], blo[2 * p + 1][1],
                        bd + (sb_blo - sb_bhi));
            }
#pragma unroll
            for (int mt = 0; mt < 2; mt++)
#pragma unroll
                for (int nt = 0; nt < 4; nt++) {
                    float* d = acc[mt][nt];
                    mma_bf16(d[0], d[1], d[2], d[3],
                             ahi[mt][0], ahi[mt][1], ahi[mt][2], ahi[mt][3],
                             bhi[nt][0], bhi[nt][1]);
                    mma_bf16(d[0], d[1], d[2], d[3],
                             ahi[mt][0], ahi[mt][1], ahi[mt][2], ahi[mt][3],
                             blo[nt][0], blo[nt][1]);
                    mma_bf16(d[0], d[1], d[2], d[3],
                             alo[mt][0], alo[mt][1], alo[mt][2], alo[mt][3],
                             bhi[nt][0], bhi[nt][1]);
                }
        }
        __syncthreads();
    }

    // ---- epilogue: bias + relu ----
    const int lq = lane & 3;
    const int lr = lane >> 2;
#pragma unroll
    for (int mt = 0; mt < 2; mt++) {
        int m0 = rbase + warp_m * 32 + mt * 16 + lr;
#pragma unroll
        for (int nt = 0; nt < 4; nt++) {
            int cc = warp_n * 32 + nt * 8 + lq * 2;
            float2 bb = *(const float2*)(bias + cc);
            if (m0 < R) {
                float2 o;
                o.x = fmaxf(acc[mt][nt][0] + bb.x, 0.f);
                o.y = fmaxf(acc[mt][nt][1] + bb.y, 0.f);
                *(float2*)(C + (size_t)m0 * NOUT + cc) = o;
            }
            if (m0 + 8 < R) {
                float2 o;
                o.x = fmaxf(acc[mt][nt][2] + bb.x, 0.f);
                o.y = fmaxf(acc[mt][nt][3] + bb.y, 0.f);
                *(float2*)(C + (size_t)(m0 + 8) * NOUT + cc) = o;
            }
        }
    }
}

// ---------------- fused gather + GEMM + bias + (relu), FFMA2 ----------------
// MODE 0: A plain [R x K];  MODE 3: A = X0[r](128) ++ X1[r](64)  (K=192)
template<int K, int NOUT, int MODE, bool RELU>
__global__ __launch_bounds__(256, 2)
void gemm_bias_relu(const float* __restrict__ A,
                    const float* __restrict__ W, int ldW,
                    const float* __restrict__ bias,
                    float* __restrict__ C, int R,
                    const float* __restrict__ X0,
                    const float* __restrict__ X1,
                    const float* __restrict__ W2,
                    float* __restrict__ C2)
{
    __shared__ __align__(16) float As[2][32][128];
    __shared__ __align__(16) float Bs[2][32][64];

    const float* Wp = W;
    float* Cp = C;
    if (blockIdx.z == 1) { Wp = W2; Cp = C2; }

    const int tid   = threadIdx.x;
    const int tx    = tid & 15;
    const int ty    = tid >> 4;
    const int rbase = blockIdx.y * 128;
    const int cbase = blockIdx.x * 64;

    const int lm = tid >> 1;
    const int lk = (tid & 1) * 16;
    const int r  = rbase + lm;
    const bool rv = (r < R);

    const float* p0 = nullptr;
    const float* p1 = nullptr;
    if (rv) {
        if (MODE == 0) {
            p0 = A + (size_t)r * K;
        } else { // MODE 3
            p0 = X0 + (size_t)r * 128;
            p1 = X1 + (size_t)r * 64;
        }
    }

    const int bk = tid >> 4;
    const int bn = (tid & 15) * 4;
    const bool cv = (cbase + bn < NOUT);

    unsigned long long acc[4][4];
#pragma unroll
    for (int p = 0; p < 4; p++)
#pragma unroll
        for (int v = 0; v < 4; v++) acc[p][v] = 0ull;

    float4 apf[4];
    float4 bpf[2];

    auto loadA = [&](int k0) {
        const int kb = k0 + lk;
#pragma unroll
        for (int u = 0; u < 4; u++) apf[u] = make_float4(0.f, 0.f, 0.f, 0.f);
        if (!rv) return;
        if (MODE == 0) {
#pragma unroll
            for (int u = 0; u < 4; u++) apf[u] = *(const float4*)(p0 + kb + 4 * u);
        } else {
            const float* s = (kb < 128) ? (p0 + kb) : (p1 + kb - 128);
#pragma unroll
            for (int u = 0; u < 4; u++) apf[u] = *(const float4*)(s + 4 * u);
        }
    };
    auto loadB = [&](int k0) {
        bpf[0] = make_float4(0.f, 0.f, 0.f, 0.f);
        bpf[1] = make_float4(0.f, 0.f, 0.f, 0.f);
        if (cv) {
            bpf[0] = *(const float4*)(Wp + (size_t)(k0 + bk) * ldW + (cbase + bn));
            bpf[1] = *(const float4*)(Wp + (size_t)(k0 + bk + 16) * ldW + (cbase + bn));
        }
    };
    auto stsA = [&](int buf) {
#pragma unroll
        for (int u = 0; u < 4; u++) {
            As[buf][lk + 4 * u + 0][lm] = apf[u].x;
            As[buf][lk + 4 * u + 1][lm] = apf[u].y;
            As[buf][lk + 4 * u + 2][lm] = apf[u].z;
            As[buf][lk + 4 * u + 3][lm] = apf[u].w;
        }
    };
    auto stsB = [&](int buf) {
        *(float4*)&Bs[buf][bk][bn]      = bpf[0];
        *(float4*)&Bs[buf][bk + 16][bn] = bpf[1];
    };

    constexpr int NC = K / 32;
    loadA(0); loadB(0);
    stsA(0);  stsB(0);
    __syncthreads();

#pragma unroll
    for (int c = 0; c < NC; c++) {
        const int cur = c & 1;
        if (c + 1 < NC) { loadA((c + 1) * 32); loadB((c + 1) * 32); }

#pragma unroll
        for (int kk = 0; kk < 32; kk++) {
            float4 b4 = *(const float4*)&Bs[cur][kk][tx * 4];
            unsigned long long bx = bcast2(b4.x);
            unsigned long long by = bcast2(b4.y);
            unsigned long long bz = bcast2(b4.z);
            unsigned long long bw = bcast2(b4.w);
            ulonglong2 a01 = *(const ulonglong2*)&As[cur][kk][ty * 8];
            ulonglong2 a23 = *(const ulonglong2*)&As[cur][kk][ty * 8 + 4];
            ffma2(acc[0][0], a01.x, bx); ffma2(acc[0][1], a01.x, by);
            ffma2(acc[0][2], a01.x, bz); ffma2(acc[0][3], a01.x, bw);
            ffma2(acc[1][0], a01.y, bx); ffma2(acc[1][1], a01.y, by);
            ffma2(acc[1][2], a01.y, bz); ffma2(acc[1][3], a01.y, bw);
            ffma2(acc[2][0], a23.x, bx); ffma2(acc[2][1], a23.x, by);
            ffma2(acc[2][2], a23.x, bz); ffma2(acc[2][3], a23.x, bw);
            ffma2(acc[3][0], a23.y, bx); ffma2(acc[3][1], a23.y, by);
            ffma2(acc[3][2], a23.y, bz); ffma2(acc[3][3], a23.y, bw);
        }

        if (c + 1 < NC) { stsA(1 - cur); stsB(1 - cur); }
        __syncthreads();
    }

    const int c = cbase + tx * 4;
    if (c < NOUT) {
        float4 bb = make_float4(0.f, 0.f, 0.f, 0.f);
        if (bias) bb = *(const float4*)(bias + c);
        auto act = [](float v) { return RELU ? fmaxf(v, 0.f) : v; };
#pragma unroll
        for (int p = 0; p < 4; p++) {
            float2 q0 = unpack2(acc[p][0]);
            float2 q1 = unpack2(acc[p][1]);
            float2 q2 = unpack2(acc[p][2]);
            float2 q3 = unpack2(acc[p][3]);
            int r0 = rbase + ty * 8 + 2 * p;
            if (r0 < R) {
                float4 o;
                o.x = act(q0.x + bb.x);
                o.y = act(q1.x + bb.y);
                o.z = act(q2.x + bb.z);
                o.w = act(q3.x + bb.w);
                *(float4*)(Cp + (size_t)r0 * NOUT + c) = o;
            }
            if (r0 + 1 < R) {
                float4 o;
                o.x = act(q0.y + bb.x);
                o.y = act(q1.y + bb.y);
                o.z = act(q2.y + bb.z);
                o.w = act(q3.y + bb.w);
                *(float4*)(Cp + (size_t)(r0 + 1) * NOUT + c) = o;
            }
        }
    }
}

// ---------------- node aggregation: mean of hn over incoming edges ----------
__global__ void pn_agg_kernel() {
    const int w    = threadIdx.x >> 5;
    const int lane = threadIdx.x & 31;
    const int i    = blockIdx.x * 4 + w;
    const int b    = blockIdx.y;
    const int t    = min(i, 32);
    const int k0   = group_start(i);
    float4 s = make_float4(0.f, 0.f, 0.f, 0.f);
    const float* src = g_hn + ((size_t)(b * NEg + k0)) * 128 + lane * 4;
    for (int l = 0; l < t; l++) {
        float4 v = *(const float4*)src;
        s = add4(s, v);
        src += 128;
    }
    const float nrm = 1.f / (float)max(t, 1);
    s.x *= nrm; s.y *= nrm; s.z *= nrm; s.w *= nrm;
    *(float4*)(g_pn + ((size_t)(b * NN + i)) * 128 + lane * 4) = s;
}

// ---------------- edge aggregation: exclusive in-group prefix mean ----------
__global__ void pe_agg_kernel() {
    const int w    = threadIdx.x >> 5;
    const int lane = threadIdx.x & 31;
    const int i    = blockIdx.x * 4 + w;
    const int b    = blockIdx.y;
    if (i == 0) return;
    const int t  = min(i, 32);
    const int k0 = group_start(i);
    float2 run = make_float2(0.f, 0.f);
    size_t base = ((size_t)(b * NEg + k0)) * 64 + lane * 2;
    for (int l = 0; l < t; l++) {
        float nrm = (l > 0) ? (1.f / (float)l) : 1.f;
        *(float2*)(g_pe + base) = make_float2(run.x * nrm, run.y * nrm);
        float2 h = *(const float2*)(g_he + base);
        run.x += h.x; run.y += h.y;
        base += 64;
    }
}

// ---------------- launch -----------------------------------------------------
extern "C" void kernel_launch(void* const* d_in, const int* in_sizes, int n_in,
                              void* d_out, int out_size) {
    const float* nodes = (const float*)d_in[0];
    const float* edges = (const float*)d_in[1];
    const float* Wan1  = (const float*)d_in[2];
    const float* ban1  = (const float*)d_in[3];
    const float* Wan2  = (const float*)d_in[4];
    const float* ban2  = (const float*)d_in[5];
    const float* Wln1  = (const float*)d_in[6];
    const float* bln1  = (const float*)d_in[7];
    const float* Wln2  = (const float*)d_in[8];
    const float* bln2  = (const float*)d_in[9];
    const float* Wae1  = (const float*)d_in[10];
    const float* bae1  = (const float*)d_in[11];
    const float* Wae2  = (const float*)d_in[12];
    const float* bae2  = (const float*)d_in[13];
    const float* Wle1  = (const float*)d_in[14];
    const float* ble1  = (const float*)d_in[15];
    const float* Wle2  = (const float*)d_in[16];
    const float* ble2  = (const float*)d_in[17];

    float* out_nodes = (float*)d_out;                         // [2,1024,64]
    float* out_edges = (float*)d_out + (size_t)BBc * NN * 64; // [2,NE,32]

    float *U, *V, *P, *E1, *E2, *hn, *pn, *h3n, *he, *pe, *h3e;
    unsigned short *BheH, *BheL, *B3eH, *B3eL, *BoeH, *BoeL;
    cudaGetSymbolAddress((void**)&U,   g_U);
    cudaGetSymbolAddress((void**)&V,   g_V);
    cudaGetSymbolAddress((void**)&P,   g_P);
    cudaGetSymbolAddress((void**)&E1,  g_E1);
    cudaGetSymbolAddress((void**)&E2,  g_E2);
    cudaGetSymbolAddress((void**)&hn,  g_hn);
    cudaGetSymbolAddress((void**)&pn,  g_pn);
    cudaGetSymbolAddress((void**)&h3n, g_h3n);
    cudaGetSymbolAddress((void**)&he,  g_he);
    cudaGetSymbolAddress((void**)&pe,  g_pe);
    cudaGetSymbolAddress((void**)&h3e, g_h3e);
    cudaGetSymbolAddress((void**)&BheH, g_BheH);
    cudaGetSymbolAddress((void**)&BheL, g_BheL);
    cudaGetSymbolAddress((void**)&B3eH, g_B3eH);
    cudaGetSymbolAddress((void**)&B3eL, g_B3eL);
    cudaGetSymbolAddress((void**)&BoeH, g_BoeH);
    cudaGetSymbolAddress((void**)&BoeL, g_BoeL);

    const int gbE = (RE + 127) / 128;    // 504 row tiles of 128 edge rows
    const int gbN = (RN + 127) / 128;    // 16 row tiles for node rows

    build_eij_kernel<<<(NEg + 255) / 256, 256>>>();
    split_all_kernel<<<(53248 + 255) / 256, 256>>>(Wan2, Wae2, Wle1, Wle2);

    // per-node precomputes: U & V in one z-merged launch, then P
    gemm_bias_relu<64, 256, 0, false><<<dim3(4, gbN, 2), 256>>>(
        nodes, Wan1, 256, nullptr, U, RN, nullptr, nullptr, Wan1 + 96 * 256, V);
    gemm_bias_relu<64, 128, 0, false><<<dim3(2, gbN), 256>>>(
        nodes, Wae1, 128, nullptr, P, RN, nullptr, nullptr, nullptr, nullptr);

    // per-edge first-layer parts -- NO relu (bias folded here)
    gemm_bias_relu<32, 256, 0, false><<<dim3(4, gbE), 256>>>(
        edges, Wan1 + 64 * 256, 256, ban1, E1, RE, nullptr, nullptr, nullptr, nullptr);
    gemm_bias_relu<32, 128, 0, false><<<dim3(2, gbE), 256>>>(
        edges, Wae1 + 64 * 128, 128, bae1, E2, RE, nullptr, nullptr, nullptr, nullptr);

    // node branch: L2 tensor (bf16x3), agg, L3, L4
    hn_mma_kernel<<<gbE, 512>>>(E1, U, V, ban2, hn);
    pn_agg_kernel<<<dim3(NN / 4, BBc), 128>>>();
    gemm_bias_relu<192, 192, 3, true><<<dim3(3, gbN), 256>>>(
        nullptr, Wln1, 192, bln1, h3n, RN, pn, nodes, nullptr, nullptr);
    gemm_bias_relu<192, 64, 0, true><<<dim3(1, gbN), 256>>>(
        h3n, Wln2, 64, bln2, out_nodes, RN, nullptr, nullptr, nullptr, nullptr);

    // edge branch: all tensor (bf16x3)
    mma_gemm<128, 64, 4, 2, 1><<<gbE, 256>>>(E2, P, BheH, BheL, bae2, he, RE);
    pe_agg_kernel<<<dim3(NN / 4, BBc), 128>>>();
    mma_gemm<96, 96, 4, 3, 2><<<gbE, 384>>>(pe, edges, B3eH, B3eL, ble1, h3e, RE);
    mma_gemm<96, 32, 8, 1, 0><<<(RE + 255) / 256, 256>>>(h3e, nullptr, BoeH, BoeL, ble2, out_edges, RE);
}

// round 8
// speedup vs baseline: 3.8296x; 1.0375x over previous
#include <cuda_runtime.h>
#include <cuda_bf16.h>
#include <math.h>
#include <stdint.h>

// Problem constants (match the reference's _build_indices(N=1024, M=32))
#define NN   1024
#define MMW  32
#define NEg  32240          // total edges
#define BBc  2
#define RE   (BBc*NEg)      // 64480 edge rows
#define RN   (BBc*NN)       // 2048 node rows

// ---------------- scratch (static device globals; no runtime allocs) -------
__device__ int2  g_eij[NEg];              // (i=target, j=source) per edge
__device__ float g_UVP[(size_t)RN*640];   // [U(256) | V(256) | P(128)] per node row
__device__ float g_E  [(size_t)RE*384];   // [E1(256) | E2(128)] per edge row (raw)
__device__ float g_hn [(size_t)RE*128];
__device__ float g_pn [(size_t)RN*128];
__device__ float g_h3n[(size_t)RN*192];
__device__ float g_he [(size_t)RE*64];
__device__ float g_pe [(size_t)RE*64];
__device__ float g_h3e[(size_t)RE*96];
// combined fp32 weight for UVP precompute: [64][640]
__device__ float g_WUVP[64*640];
// bf16 hi/lo splits of weights, stored as B[n][k] (transposed)
__device__ unsigned short g_Bhi  [128*256];   // Wan2
__device__ unsigned short g_Blo  [128*256];
__device__ unsigned short g_BheH [64*128];    // Wae2
__device__ unsigned short g_BheL [64*128];
__device__ unsigned short g_B3eH [96*96];     // Wle1
__device__ unsigned short g_B3eL [96*96];
__device__ unsigned short g_BoeH [32*96];     // Wle2
__device__ unsigned short g_BoeL [32*96];
__device__ unsigned short g_BeH  [384*32];    // [Wan1[64:96] | Wae1[64:96]]
__device__ unsigned short g_BeL  [384*32];
__device__ float g_bE[384];                   // [ban1 | bae1]

// ---------------- f32x2 packed-FMA helpers ----------------------------------
__device__ __forceinline__ void ffma2(unsigned long long& d,
                                      unsigned long long a,
                                      unsigned long long b) {
    asm("fma.rn.f32x2 %0, %1, %2, %0;" : "+l"(d) : "l"(a), "l"(b));
}
__device__ __forceinline__ unsigned long long bcast2(float x) {
    unsigned long long r;
    asm("mov.b64 %0, {%1, %1};" : "=l"(r) : "f"(x));
    return r;
}
__device__ __forceinline__ float2 unpack2(unsigned long long v) {
    float2 f;
    asm("mov.b64 {%0, %1}, %2;" : "=f"(f.x), "=f"(f.y) : "l"(v));
    return f;
}

// ---------------- mma.sync helpers ------------------------------------------
__device__ __forceinline__ uint32_t smem_u32(const void* p) {
    uint32_t a;
    asm("{ .reg .u64 t; cvta.to.shared.u64 t, %1; cvt.u32.u64 %0, t; }"
        : "=r"(a) : "l"(p));
    return a;
}
__device__ __forceinline__ void ldsm_x4(uint32_t& r0, uint32_t& r1,
                                        uint32_t& r2, uint32_t& r3,
                                        uint32_t addr) {
    asm volatile("ldmatrix.sync.aligned.m8n8.x4.shared.b16 {%0,%1,%2,%3}, [%4];"
                 : "=r"(r0), "=r"(r1), "=r"(r2), "=r"(r3) : "r"(addr));
}
__device__ __forceinline__ void mma_bf16(float& c0, float& c1, float& c2, float& c3,
                                         uint32_t a0, uint32_t a1, uint32_t a2, uint32_t a3,
                                         uint32_t b0, uint32_t b1) {
    asm volatile("mma.sync.aligned.m16n8k16.row.col.f32.bf16.bf16.f32 "
                 "{%0,%1,%2,%3}, {%4,%5,%6,%7}, {%8,%9}, {%0,%1,%2,%3};"
                 : "+f"(c0), "+f"(c1), "+f"(c2), "+f"(c3)
                 : "r"(a0), "r"(a1), "r"(a2), "r"(a3), "r"(b0), "r"(b1));
}

static __device__ __forceinline__ unsigned short bf16_bits(__nv_bfloat16 h) {
    return *reinterpret_cast<unsigned short*>(&h);
}
__device__ __forceinline__ void split_pack8(const float* vals,
                                            uint32_t* hp, uint32_t* lp) {
#pragma unroll
    for (int q = 0; q < 4; q++) {
        __nv_bfloat16 h0 = __float2bfloat16(vals[2 * q]);
        __nv_bfloat16 h1 = __float2bfloat16(vals[2 * q + 1]);
        float r0 = vals[2 * q]     - __bfloat162float(h0);
        float r1 = vals[2 * q + 1] - __bfloat162float(h1);
        __nv_bfloat16 l0 = __float2bfloat16(r0);
        __nv_bfloat16 l1 = __float2bfloat16(r1);
        hp[q] = (uint32_t)bf16_bits(h0) | ((uint32_t)bf16_bits(h1) << 16);
        lp[q] = (uint32_t)bf16_bits(l0) | ((uint32_t)bf16_bits(l1) << 16);
    }
}

// ---------------- edge index builder ---------------------------------------
__global__ void build_eij_kernel() {
    int e = blockIdx.x * blockDim.x + threadIdx.x;
    if (e >= NEg) return;
    int i, j;
    if (e < 496) {
        i = (int)((1.0f + sqrtf(8.0f * (float)e + 1.0f)) * 0.5f);
        while (i * (i - 1) / 2 > e) i--;
        while ((i + 1) * i / 2 <= e) i++;
        j = e - i * (i - 1) / 2;
    } else {
        int q = (e - 496) >> 5;
        i = 32 + q;
        j = (i - 32) + ((e - 496) & 31);
    }
    g_eij[e] = make_int2(i, j);
}

__device__ __forceinline__ int group_start(int i) {
    return (i <= 32) ? (i * (i - 1) / 2) : (496 + (i - 32) * 32);
}

__device__ __forceinline__ float4 relu4(float4 v) {
    v.x = fmaxf(v.x, 0.f); v.y = fmaxf(v.y, 0.f);
    v.z = fmaxf(v.z, 0.f); v.w = fmaxf(v.w, 0.f);
    return v;
}
__device__ __forceinline__ float4 add4(float4 a, float4 b) {
    return make_float4(a.x + b.x, a.y + b.y, a.z + b.z, a.w + b.w);
}

// ---------------- all weight prep in one launch ------------------------------
__device__ __forceinline__ void split_store(float w, unsigned short* hi,
                                            unsigned short* lo, size_t o) {
    __nv_bfloat16 h = __float2bfloat16(w);
    float rem = w - __bfloat162float(h);
    hi[o] = bf16_bits(h);
    lo[o] = bf16_bits(__float2bfloat16(rem));
}
#define SEG0 32768                 // Wan2 -> g_Bhi/Blo
#define SEG1 (SEG0 + 8192)         // Wae2
#define SEG2 (SEG1 + 9216)         // Wle1
#define SEG3 (SEG2 + 3072)         // Wle2
#define SEG4 (SEG3 + 8192)         // Wan1[64:96] -> g_Be[0:256]
#define SEG5 (SEG4 + 4096)         // Wae1[64:96] -> g_Be[256:384]
#define SEG6 (SEG5 + 40960)        // g_WUVP
#define SEG7 (SEG6 + 384)          // g_bE
__global__ void split_all_kernel(const float* __restrict__ Wan1,
                                 const float* __restrict__ Wan2,
                                 const float* __restrict__ Wae1,
                                 const float* __restrict__ Wae2,
                                 const float* __restrict__ Wle1,
                                 const float* __restrict__ Wle2,
                                 const float* __restrict__ ban1,
                                 const float* __restrict__ bae1) {
    int idx = blockIdx.x * blockDim.x + threadIdx.x;
    if (idx < SEG0) {                          // Wan2 [256][128]
        int k = idx >> 7, n = idx & 127;
        split_store(Wan2[idx], g_Bhi, g_Blo, (size_t)n * 256 + k);
    } else if (idx < SEG1) {                   // Wae2 [128][64]
        int t = idx - SEG0;
        int k = t >> 6, n = t & 63;
        split_store(Wae2[t], g_BheH, g_BheL, (size_t)n * 128 + k);
    } else if (idx < SEG2) {                   // Wle1 [96][96]
        int t = idx - SEG1;
        int k = t / 96, n = t % 96;
        split_store(Wle1[t], g_B3eH, g_B3eL, (size_t)n * 96 + k);
    } else if (idx < SEG3) {                   // Wle2 [96][32]
        int t = idx - SEG2;
        int k = t >> 5, n = t & 31;
        split_store(Wle2[t], g_BoeH, g_BoeL, (size_t)n * 96 + k);
    } else if (idx < SEG4) {                   // Wan1 rows 64..95 -> g_Be n<256
        int t = idx - SEG3;
        int k = t >> 8, n = t & 255;
        split_store(Wan1[(size_t)(64 + k) * 256 + n], g_BeH, g_BeL,
                    (size_t)n * 32 + k);
    } else if (idx < SEG5) {                   // Wae1 rows 64..95 -> g_Be n 256..383
        int t = idx - SEG4;
        int k = t >> 7, n = t & 127;
        split_store(Wae1[(size_t)(64 + k) * 128 + n], g_BeH, g_BeL,
                    (size_t)(256 + n) * 32 + k);
    } else if (idx < SEG6) {                   // g_WUVP [64][640]
        int t = idx - SEG5;
        int k = t / 640, n = t % 640;
        float w;
        if (n < 256)      w = Wan1[(size_t)k * 256 + n];
        else if (n < 512) w = Wan1[(size_t)(96 + k) * 256 + (n - 256)];
        else              w = Wae1[(size_t)k * 128 + (n - 512)];
        g_WUVP[t] = w;
    } else if (idx < SEG7) {                   // g_bE
        int n = idx - SEG6;
        g_bE[n] = (n < 256) ? ban1[n] : bae1[n - 256];
    }
}

// ---------------- mma.sync bf16x3 kernel: hn = relu((E1+U+V)@Wan2 + ban2) ---
#define A_STRIDE 40          // bf16 elems per row (80 B)
#define SM_AHI 0
#define SM_ALO 10240
#define SM_BHI 20480
#define SM_BLO 30720

__global__ __launch_bounds__(512, 1)
void hn_mma_kernel(const float* __restrict__ E,
                   const float* __restrict__ UVP,
                   const float* __restrict__ bias,
                   float* __restrict__ C)
{
    __shared__ __align__(16) char smem[40960];
    const uint32_t sb = smem_u32(smem);

    const int tid   = threadIdx.x;
    const int wid   = tid >> 5;
    const int lane  = tid & 31;
    const int warp_m = wid & 3;
    const int warp_n = wid >> 2;
    const int rbase = blockIdx.x * 128;

    const int lrow = tid >> 2;
    const int lk   = (tid & 3) * 8;
    const int r    = rbase + lrow;
    const bool rv  = (r < RE);

    const float* pe1 = nullptr;
    const float* pu  = nullptr;
    const float* pv  = nullptr;
    if (rv) {
        int b = (r >= NEg) ? 1 : 0;
        int e = r - b * NEg;
        int2 ij = g_eij[e];
        pe1 = E + (size_t)r * 384;
        pu  = UVP + ((size_t)(b * NN + ij.y)) * 640;
        pv  = UVP + ((size_t)(b * NN + ij.x)) * 640 + 256;
    }

    float  a_st[8];
    uint4  b_st_hi, b_st_lo;

    auto loadregs = [&](int k0) {
        if (rv) {
            float4 e0 = *(const float4*)(pe1 + k0 + lk);
            float4 e1 = *(const float4*)(pe1 + k0 + lk + 4);
            float4 u0 = *(const float4*)(pu + k0 + lk);
            float4 u1 = *(const float4*)(pu + k0 + lk + 4);
            float4 v0 = *(const float4*)(pv + k0 + lk);
            float4 v1 = *(const float4*)(pv + k0 + lk + 4);
            float4 s0 = relu4(add4(add4(e0, u0), v0));
            float4 s1 = relu4(add4(add4(e1, u1), v1));
            a_st[0] = s0.x; a_st[1] = s0.y; a_st[2] = s0.z; a_st[3] = s0.w;
            a_st[4] = s1.x; a_st[5] = s1.y; a_st[6] = s1.z; a_st[7] = s1.w;
        } else {
#pragma unroll
            for (int q = 0; q < 8; q++) a_st[q] = 0.f;
        }
        b_st_hi = *(const uint4*)(g_Bhi + (size_t)lrow * 256 + k0 + lk);
        b_st_lo = *(const uint4*)(g_Blo + (size_t)lrow * 256 + k0 + lk);
    };
    auto stsregs = [&]() {
        uint32_t hp[4], lp[4];
        split_pack8(a_st, hp, lp);
        uint32_t off = (uint32_t)(lrow * (A_STRIDE * 2) + lk * 2);
        *(uint4*)(smem + SM_AHI + off) = make_uint4(hp[0], hp[1], hp[2], hp[3]);
        *(uint4*)(smem + SM_ALO + off) = make_uint4(lp[0], lp[1], lp[2], lp[3]);
        *(uint4*)(smem + SM_BHI + off) = b_st_hi;
        *(uint4*)(smem + SM_BLO + off) = b_st_lo;
    };

    float acc[2][4][4];
#pragma unroll
    for (int mt = 0; mt < 2; mt++)
#pragma unroll
        for (int nt = 0; nt < 4; nt++)
#pragma unroll
            for (int q = 0; q < 4; q++) acc[mt][nt][q] = 0.f;

    const int a_m   = warp_m * 32 + (lane & 7) + ((lane >> 3) & 1) * 8;
    const int a_koff = (lane >> 4) * 8;
    const int b_n   = warp_n * 32 + (lane & 7) + (lane >> 4) * 8;
    const int b_koff = ((lane >> 3) & 1) * 8;

    loadregs(0);
#pragma unroll 1
    for (int c = 0; c < 8; c++) {
        stsregs();
        __syncthreads();
        if (c < 7) loadregs((c + 1) * 32);

#pragma unroll
        for (int ks = 0; ks < 2; ks++) {
            uint32_t ahi[2][4], alo[2][4];
#pragma unroll
            for (int mt = 0; mt < 2; mt++) {
                uint32_t ad = sb + SM_AHI +
                    (uint32_t)((a_m + mt * 16) * (A_STRIDE * 2) +
                               (ks * 16 + a_koff) * 2);
                ldsm_x4(ahi[mt][0], ahi[mt][1], ahi[mt][2], ahi[mt][3], ad);
                ldsm_x4(alo[mt][0], alo[mt][1], alo[mt][2], alo[mt][3],
                        ad + (SM_ALO - SM_AHI));
            }
            uint32_t bhi[4][2], blo[4][2];
#pragma unroll
            for (int p = 0; p < 2; p++) {
                uint32_t bd = sb + SM_BHI +
                    (uint32_t)((b_n + p * 16) * (A_STRIDE * 2) +
                               (ks * 16 + b_koff) * 2);
                ldsm_x4(bhi[2 * p][0], bhi[2 * p][1],
                        bhi[2 * p + 1][0], bhi[2 * p + 1][1], bd);
                ldsm_x4(blo[2 * p][0], blo[2 * p][1],
                        blo[2 * p + 1][0], blo[2 * p + 1][1],
                        bd + (SM_BLO - SM_BHI));
            }
#pragma unroll
            for (int mt = 0; mt < 2; mt++)
#pragma unroll
                for (int nt = 0; nt < 4; nt++) {
                    float* d = acc[mt][nt];
                    mma_bf16(d[0], d[1], d[2], d[3],
                             ahi[mt][0], ahi[mt][1], ahi[mt][2], ahi[mt][3],
                             bhi[nt][0], bhi[nt][1]);
                    mma_bf16(d[0], d[1], d[2], d[3],
                             ahi[mt][0], ahi[mt][1], ahi[mt][2], ahi[mt][3],
                             blo[nt][0], blo[nt][1]);
                    mma_bf16(d[0], d[1], d[2], d[3],
                             alo[mt][0], alo[mt][1], alo[mt][2], alo[mt][3],
                             bhi[nt][0], bhi[nt][1]);
                }
        }
        __syncthreads();
    }

    const int lq = lane & 3;
    const int lr = lane >> 2;
#pragma unroll
    for (int mt = 0; mt < 2; mt++) {
        int m0 = rbase + warp_m * 32 + mt * 16 + lr;
#pragma unroll
        for (int nt = 0; nt < 4; nt++) {
            int cc = warp_n * 32 + nt * 8 + lq * 2;
            float2 bb = *(const float2*)(bias + cc);
            if (m0 < RE) {
                float2 o;
                o.x = fmaxf(acc[mt][nt][0] + bb.x, 0.f);
                o.y = fmaxf(acc[mt][nt][1] + bb.y, 0.f);
                *(float2*)(C + (size_t)m0 * 128 + cc) = o;
            }
            if (m0 + 8 < RE) {
                float2 o;
                o.x = fmaxf(acc[mt][nt][2] + bb.x, 0.f);
                o.y = fmaxf(acc[mt][nt][3] + bb.y, 0.f);
                *(float2*)(C + (size_t)(m0 + 8) * 128 + cc) = o;
            }
        }
    }
}

// ---------------- generalized N-tiled mma.sync bf16x3 GEMM ------------------
// C[r][cbase+cc] = act(A[R x K] @ Bsplit[cbase..] + bias[cbase..])
// cbase = blockIdx.y * (WN*32).  act = relu iff RELU.
// MMODE 0: A row = X0 + r*ld0
// MMODE 1: A[k] = relu(X0[r*ld0+k] + X1[(b*NN+j)*ld1+k])
// MMODE 2: A = X0[r*ld0](64) ++ X1[r*ld1](32)
template<int K, int WM, int WN, int MMODE, bool RELU>
__global__ __launch_bounds__(WM * WN * 32)
void mma_gemm(const float* __restrict__ X0, int ld0,
              const float* __restrict__ X1, int ld1,
              const unsigned short* __restrict__ Bhi,
              const unsigned short* __restrict__ Blo,
              const float* __restrict__ bias,
              float* __restrict__ C, int ldC, int R)
{
    constexpr int MT  = WM * 32;
    constexpr int NB  = WN * 32;
    constexpr int NTH = WM * WN * 32;
    __shared__ __align__(16) unsigned short sAhi[MT * A_STRIDE];
    __shared__ __align__(16) unsigned short sAlo[MT * A_STRIDE];
    __shared__ __align__(16) unsigned short sBhi[NB * A_STRIDE];
    __shared__ __align__(16) unsigned short sBlo[NB * A_STRIDE];

    const int tid  = threadIdx.x;
    const int wid  = tid >> 5;
    const int lane = tid & 31;
    const int warp_m = wid % WM;
    const int warp_n = wid / WM;
    const int rbase = blockIdx.x * MT;
    const int cbase = blockIdx.y * NB;

    float acc[2][4][4];
#pragma unroll
    for (int mt = 0; mt < 2; mt++)
#pragma unroll
        for (int nt = 0; nt < 4; nt++)
#pragma unroll
            for (int q = 0; q < 4; q++) acc[mt][nt][q] = 0.f;

    const int a_m    = warp_m * 32 + (lane & 7) + ((lane >> 3) & 1) * 8;
    const int a_koff = (lane >> 4) * 8;
    const int b_n    = warp_n * 32 + (lane & 7) + (lane >> 4) * 8;
    const int b_koff = ((lane >> 3) & 1) * 8;

    const uint32_t sb_ahi = smem_u32(sAhi);
    const uint32_t sb_alo = smem_u32(sAlo);
    const uint32_t sb_bhi = smem_u32(sBhi);
    const uint32_t sb_blo = smem_u32(sBlo);

#pragma unroll 1
    for (int c = 0; c < K / 32; c++) {
        const int k0 = c * 32;
        // ---- A loader ----
        for (int idx = tid; idx < MT * 4; idx += NTH) {
            const int row = idx >> 2;
            const int lk  = (idx & 3) * 8;
            const int r   = rbase + row;
            const int kb  = k0 + lk;
            float vals[8];
            if (r < R) {
                if (MMODE == 0) {
                    float4 v0 = *(const float4*)(X0 + (size_t)r * ld0 + kb);
                    float4 v1 = *(const float4*)(X0 + (size_t)r * ld0 + kb + 4);
                    vals[0] = v0.x; vals[1] = v0.y; vals[2] = v0.z; vals[3] = v0.w;
                    vals[4] = v1.x; vals[5] = v1.y; vals[6] = v1.z; vals[7] = v1.w;
                } else if (MMODE == 1) {
                    int b = (r >= NEg) ? 1 : 0;
                    int e = r - b * NEg;
                    int2 ij = g_eij[e];
                    const float* pa = X0 + (size_t)r * ld0 + kb;
                    const float* pb = X1 + ((size_t)(b * NN + ij.y)) * ld1 + kb;
                    float4 s0 = relu4(add4(*(const float4*)pa,
                                           *(const float4*)pb));
                    float4 s1 = relu4(add4(*(const float4*)(pa + 4),
                                           *(const float4*)(pb + 4)));
                    vals[0] = s0.x; vals[1] = s0.y; vals[2] = s0.z; vals[3] = s0.w;
                    vals[4] = s1.x; vals[5] = s1.y; vals[6] = s1.z; vals[7] = s1.w;
                } else { // MMODE 2: X0(64) ++ X1(32)
                    const float* s = (kb < 64) ? (X0 + (size_t)r * ld0 + kb)
                                               : (X1 + (size_t)r * ld1 + kb - 64);
                    float4 v0 = *(const float4*)s;
                    float4 v1 = *(const float4*)(s + 4);
                    vals[0] = v0.x; vals[1] = v0.y; vals[2] = v0.z; vals[3] = v0.w;
                    vals[4] = v1.x; vals[5] = v1.y; vals[6] = v1.z; vals[7] = v1.w;
                }
            } else {
#pragma unroll
                for (int q = 0; q < 8; q++) vals[q] = 0.f;
            }
            uint32_t hp[4], lp[4];
            split_pack8(vals, hp, lp);
            uint32_t off = (uint32_t)(row * A_STRIDE + lk) * 2;
            *(uint4*)((char*)sAhi + off) = make_uint4(hp[0], hp[1], hp[2], hp[3]);
            *(uint4*)((char*)sAlo + off) = make_uint4(lp[0], lp[1], lp[2], lp[3]);
        }
        // ---- B loader ----
        for (int idx = tid; idx < NB * 4; idx += NTH) {
            const int n  = idx >> 2;
            const int lk = (idx & 3) * 8;
            uint4 hv = *(const uint4*)(Bhi + (size_t)(cbase + n) * K + k0 + lk);
            uint4 lv = *(const uint4*)(Blo + (size_t)(cbase + n) * K + k0 + lk);
            uint32_t off = (uint32_t)(n * A_STRIDE + lk) * 2;
            *(uint4*)((char*)sBhi + off) = hv;
            *(uint4*)((char*)sBlo + off) = lv;
        }
        __syncthreads();

#pragma unroll
        for (int ks = 0; ks < 2; ks++) {
            uint32_t ahi[2][4], alo[2][4];
#pragma unroll
            for (int mt = 0; mt < 2; mt++) {
                uint32_t ad = sb_ahi +
                    (uint32_t)((a_m + mt * 16) * (A_STRIDE * 2) +
                               (ks * 16 + a_koff) * 2);
                ldsm_x4(ahi[mt][0], ahi[mt][1], ahi[mt][2], ahi[mt][3], ad);
                ldsm_x4(alo[mt][0], alo[mt][1], alo[mt][2], alo[mt][3],
                        ad + (sb_alo - sb_ahi));
            }
            uint32_t bhi[4][2], blo[4][2];
#pragma unroll
            for (int p = 0; p < 2; p++) {
                uint32_t bd = sb_bhi +
                    (uint32_t)((b_n + p * 16) * (A_STRIDE * 2) +
                               (ks * 16 + b_koff) * 2);
                ldsm_x4(bhi[2 * p][0], bhi[2 * p][1],
                        bhi[2 * p + 1][0], bhi[2 * p + 1][1], bd);
                ldsm_x4(blo[2 * p][0], blo[2 * p][1],
                        blo[2 * p + 1][0], blo[2 * p + 1][1],
                        bd + (sb_blo - sb_bhi));
            }
#pragma unroll
            for (int mt = 0; mt < 2; mt++)
#pragma unroll
                for (int nt = 0; nt < 4; nt++) {
                    float* d = acc[mt][nt];
                    mma_bf16(d[0], d[1], d[2], d[3],
                             ahi[mt][0], ahi[mt][1], ahi[mt][2], ahi[mt][3],
                             bhi[nt][0], bhi[nt][1]);
                    mma_bf16(d[0], d[1], d[2], d[3],
                             ahi[mt][0], ahi[mt][1], ahi[mt][2], ahi[mt][3],
                             blo[nt][0], blo[nt][1]);
                    mma_bf16(d[0], d[1], d[2], d[3],
                             alo[mt][0], alo[mt][1], alo[mt][2], alo[mt][3],
                             bhi[nt][0], bhi[nt][1]);
                }
        }
        __syncthreads();
    }

    // ---- epilogue ----
    const int lq = lane & 3;
    const int lr = lane >> 2;
#pragma unroll
    for (int mt = 0; mt < 2; mt++) {
        int m0 = rbase + warp_m * 32 + mt * 16 + lr;
#pragma unroll
        for (int nt = 0; nt < 4; nt++) {
            int cc = cbase + warp_n * 32 + nt * 8 + lq * 2;
            float2 bb = *(const float2*)(bias + cc);
            auto act = [](float v) { return RELU ? fmaxf(v, 0.f) : v; };
            if (m0 < R) {
                float2 o;
                o.x = act(acc[mt][nt][0] + bb.x);
                o.y = act(acc[mt][nt][1] + bb.y);
                *(float2*)(C + (size_t)m0 * ldC + cc) = o;
            }
            if (m0 + 8 < R) {
                float2 o;
                o.x = act(acc[mt][nt][2] + bb.x);
                o.y = act(acc[mt][nt][3] + bb.y);
                *(float2*)(C + (size_t)(m0 + 8) * ldC + cc) = o;
            }
        }
    }
}

// ---------------- FFMA2 GEMM (node-side small work) --------------------------
// MODE 0: A plain [R x K];  MODE 3: A = X0[r](128) ++ X1[r](64)  (K=192)
template<int K, int NOUT, int MODE, bool RELU>
__global__ __launch_bounds__(256, 2)
void gemm_bias_relu(const float* __restrict__ A,
                    const float* __restrict__ W, int ldW,
                    const float* __restrict__ bias,
                    float* __restrict__ C, int R,
                    const float* __restrict__ X0,
                    const float* __restrict__ X1)
{
    __shared__ __align__(16) float As[2][32][128];
    __shared__ __align__(16) float Bs[2][32][64];

    const int tid   = threadIdx.x;
    const int tx    = tid & 15;
    const int ty    = tid >> 4;
    const int rbase = blockIdx.y * 128;
    const int cbase = blockIdx.x * 64;

    const int lm = tid >> 1;
    const int lk = (tid & 1) * 16;
    const int r  = rbase + lm;
    const bool rv = (r < R);

    const float* p0 = nullptr;
    const float* p1 = nullptr;
    if (rv) {
        if (MODE == 0) {
            p0 = A + (size_t)r * K;
        } else { // MODE 3
            p0 = X0 + (size_t)r * 128;
            p1 = X1 + (size_t)r * 64;
        }
    }

    const int bk = tid >> 4;
    const int bn = (tid & 15) * 4;
    const bool cv = (cbase + bn < NOUT);

    unsigned long long acc[4][4];
#pragma unroll
    for (int p = 0; p < 4; p++)
#pragma unroll
        for (int v = 0; v < 4; v++) acc[p][v] = 0ull;

    float4 apf[4];
    float4 bpf[2];

    auto loadA = [&](int k0) {
        const int kb = k0 + lk;
#pragma unroll
        for (int u = 0; u < 4; u++) apf[u] = make_float4(0.f, 0.f, 0.f, 0.f);
        if (!rv) return;
        if (MODE == 0) {
#pragma unroll
            for (int u = 0; u < 4; u++) apf[u] = *(const float4*)(p0 + kb + 4 * u);
        } else {
            const float* s = (kb < 128) ? (p0 + kb) : (p1 + kb - 128);
#pragma unroll
            for (int u = 0; u < 4; u++) apf[u] = *(const float4*)(s + 4 * u);
        }
    };
    auto loadB = [&](int k0) {
        bpf[0] = make_float4(0.f, 0.f, 0.f, 0.f);
        bpf[1] = make_float4(0.f, 0.f, 0.f, 0.f);
        if (cv) {
            bpf[0] = *(const float4*)(W + (size_t)(k0 + bk) * ldW + (cbase + bn));
            bpf[1] = *(const float4*)(W + (size_t)(k0 + bk + 16) * ldW + (cbase + bn));
        }
    };
    auto stsA = [&](int buf) {
#pragma unroll
        for (int u = 0; u < 4; u++) {
            As[buf][lk + 4 * u + 0][lm] = apf[u].x;
            As[buf][lk + 4 * u + 1][lm] = apf[u].y;
            As[buf][lk + 4 * u + 2][lm] = apf[u].z;
            As[buf][lk + 4 * u + 3][lm] = apf[u].w;
        }
    };
    auto stsB = [&](int buf) {
        *(float4*)&Bs[buf][bk][bn]      = bpf[0];
        *(float4*)&Bs[buf][bk + 16][bn] = bpf[1];
    };

    constexpr int NC = K / 32;
    loadA(0); loadB(0);
    stsA(0);  stsB(0);
    __syncthreads();

#pragma unroll
    for (int c = 0; c < NC; c++) {
        const int cur = c & 1;
        if (c + 1 < NC) { loadA((c + 1) * 32); loadB((c + 1) * 32); }

#pragma unroll
        for (int kk = 0; kk < 32; kk++) {
            float4 b4 = *(const float4*)&Bs[cur][kk][tx * 4];
            unsigned long long bx = bcast2(b4.x);
            unsigned long long by = bcast2(b4.y);
            unsigned long long bz = bcast2(b4.z);
            unsigned long long bw = bcast2(b4.w);
            ulonglong2 a01 = *(const ulonglong2*)&As[cur][kk][ty * 8];
            ulonglong2 a23 = *(const ulonglong2*)&As[cur][kk][ty * 8 + 4];
            ffma2(acc[0][0], a01.x, bx); ffma2(acc[0][1], a01.x, by);
            ffma2(acc[0][2], a01.x, bz); ffma2(acc[0][3], a01.x, bw);
            ffma2(acc[1][0], a01.y, bx); ffma2(acc[1][1], a01.y, by);
            ffma2(acc[1][2], a01.y, bz); ffma2(acc[1][3], a01.y, bw);
            ffma2(acc[2][0], a23.x, bx); ffma2(acc[2][1], a23.x, by);
            ffma2(acc[2][2], a23.x, bz); ffma2(acc[2][3], a23.x, bw);
            ffma2(acc[3][0], a23.y, bx); ffma2(acc[3][1], a23.y, by);
            ffma2(acc[3][2], a23.y, bz); ffma2(acc[3][3], a23.y, bw);
        }

        if (c + 1 < NC) { stsA(1 - cur); stsB(1 - cur); }
        __syncthreads();
    }

    const int c = cbase + tx * 4;
    if (c < NOUT) {
        float4 bb = make_float4(0.f, 0.f, 0.f, 0.f);
        if (bias) bb = *(const float4*)(bias + c);
        auto act = [](float v) { return RELU ? fmaxf(v, 0.f) : v; };
#pragma unroll
        for (int p = 0; p < 4; p++) {
            float2 q0 = unpack2(acc[p][0]);
            float2 q1 = unpack2(acc[p][1]);
            float2 q2 = unpack2(acc[p][2]);
            float2 q3 = unpack2(acc[p][3]);
            int r0 = rbase + ty * 8 + 2 * p;
            if (r0 < R) {
                float4 o;
                o.x = act(q0.x + bb.x);
                o.y = act(q1.x + bb.y);
                o.z = act(q2.x + bb.z);
                o.w = act(q3.x + bb.w);
                *(float4*)(C + (size_t)r0 * NOUT + c) = o;
            }
            if (r0 + 1 < R) {
                float4 o;
                o.x = act(q0.y + bb.x);
                o.y = act(q1.y + bb.y);
                o.z = act(q2.y + bb.z);
                o.w = act(q3.y + bb.w);
                *(float4*)(C + (size_t)(r0 + 1) * NOUT + c) = o;
            }
        }
    }
}

// ---------------- node aggregation: mean of hn over incoming edges ----------
__global__ void pn_agg_kernel() {
    const int w    = threadIdx.x >> 5;
    const int lane = threadIdx.x & 31;
    const int i    = blockIdx.x * 4 + w;
    const int b    = blockIdx.y;
    const int t    = min(i, 32);
    const int k0   = group_start(i);
    float4 s = make_float4(0.f, 0.f, 0.f, 0.f);
    const float* src = g_hn + ((size_t)(b * NEg + k0)) * 128 + lane * 4;
    for (int l = 0; l < t; l++) {
        float4 v = *(const float4*)src;
        s = add4(s, v);
        src += 128;
    }
    const float nrm = 1.f / (float)max(t, 1);
    s.x *= nrm; s.y *= nrm; s.z *= nrm; s.w *= nrm;
    *(float4*)(g_pn + ((size_t)(b * NN + i)) * 128 + lane * 4) = s;
}

// ---------------- edge aggregation: exclusive in-group prefix mean ----------
__global__ void pe_agg_kernel() {
    const int w    = threadIdx.x >> 5;
    const int lane = threadIdx.x & 31;
    const int i    = blockIdx.x * 4 + w;
    const int b    = blockIdx.y;
    if (i == 0) return;
    const int t  = min(i, 32);
    const int k0 = group_start(i);
    float2 run = make_float2(0.f, 0.f);
    size_t base = ((size_t)(b * NEg + k0)) * 64 + lane * 2;
    for (int l = 0; l < t; l++) {
        float nrm = (l > 0) ? (1.f / (float)l) : 1.f;
        *(float2*)(g_pe + base) = make_float2(run.x * nrm, run.y * nrm);
        float2 h = *(const float2*)(g_he + base);
        run.x += h.x; run.y += h.y;
        base += 64;
    }
}

// ---------------- launch -----------------------------------------------------
extern "C" void kernel_launch(void* const* d_in, const int* in_sizes, int n_in,
                              void* d_out, int out_size) {
    const float* nodes = (const float*)d_in[0];
    const float* edges = (const float*)d_in[1];
    const float* Wan1  = (const float*)d_in[2];
    const float* ban1  = (const float*)d_in[3];
    const float* Wan2  = (const float*)d_in[4];
    const float* ban2  = (const float*)d_in[5];
    const float* Wln1  = (const float*)d_in[6];
    const float* bln1  = (const float*)d_in[7];
    const float* Wln2  = (const float*)d_in[8];
    const float* bln2  = (const float*)d_in[9];
    const float* Wae1  = (const float*)d_in[10];
    const float* bae1  = (const float*)d_in[11];
    const float* Wae2  = (const float*)d_in[12];
    const float* bae2  = (const float*)d_in[13];
    const float* Wle1  = (const float*)d_in[14];
    const float* ble1  = (const float*)d_in[15];
    const float* Wle2  = (const float*)d_in[16];
    const float* ble2  = (const float*)d_in[17];

    float* out_nodes = (float*)d_out;                         // [2,1024,64]
    float* out_edges = (float*)d_out + (size_t)BBc * NN * 64; // [2,NE,32]

    float *UVP, *E, *hn, *pn, *h3n, *he, *pe, *h3e, *WUVP, *bE;
    unsigned short *BheH, *BheL, *B3eH, *B3eL, *BoeH, *BoeL, *BeH, *BeL;
    cudaGetSymbolAddress((void**)&UVP, g_UVP);
    cudaGetSymbolAddress((void**)&E,   g_E);
    cudaGetSymbolAddress((void**)&hn,  g_hn);
    cudaGetSymbolAddress((void**)&pn,  g_pn);
    cudaGetSymbolAddress((void**)&h3n, g_h3n);
    cudaGetSymbolAddress((void**)&he,  g_he);
    cudaGetSymbolAddress((void**)&pe,  g_pe);
    cudaGetSymbolAddress((void**)&h3e, g_h3e);
    cudaGetSymbolAddress((void**)&WUVP, g_WUVP);
    cudaGetSymbolAddress((void**)&bE,  g_bE);
    cudaGetSymbolAddress((void**)&BheH, g_BheH);
    cudaGetSymbolAddress((void**)&BheL, g_BheL);
    cudaGetSymbolAddress((void**)&B3eH, g_B3eH);
    cudaGetSymbolAddress((void**)&B3eL, g_B3eL);
    cudaGetSymbolAddress((void**)&BoeH, g_BoeH);
    cudaGetSymbolAddress((void**)&BoeL, g_BoeL);
    cudaGetSymbolAddress((void**)&BeH, g_BeH);
    cudaGetSymbolAddress((void**)&BeL, g_BeL);

    const int gbE = (RE + 127) / 128;    // 504 row tiles of 128 edge rows
    const int gbN = (RN + 127) / 128;    // 16 row tiles for node rows

    build_eij_kernel<<<(NEg + 255) / 256, 256>>>();
    split_all_kernel<<<(SEG7 + 255) / 256, 256>>>(Wan1, Wan2, Wae1, Wae2,
                                                  Wle1, Wle2, ban1, bae1);

    // per-node precompute: UVP = nodes @ [Wan1[0:64] | Wan1[96:160] | Wae1[0:64]]
    gemm_bias_relu<64, 640, 0, false><<<dim3(10, gbN), 256>>>(
        nodes, WUVP, 640, nullptr, UVP, RN, nullptr, nullptr);

    // per-edge first-layer parts (E1|E2) on tensor cores, raw (bias folded)
    mma_gemm<32, 4, 4, 0, false><<<dim3(gbE, 3), 512>>>(
        edges, 32, nullptr, 0, BeH, BeL, bE, E, 384, RE);

    // node branch: L2 tensor (bf16x3), agg, L3, L4
    hn_mma_kernel<<<gbE, 512>>>(E, UVP, ban2, hn);
    pn_agg_kernel<<<dim3(NN / 4, BBc), 128>>>();
    gemm_bias_relu<192, 192, 3, true><<<dim3(3, gbN), 256>>>(
        nullptr, Wln1, 192, bln1, h3n, RN, pn, nodes);
    gemm_bias_relu<192, 64, 0, true><<<dim3(1, gbN), 256>>>(
        h3n, Wln2, 64, bln2, out_nodes, RN, nullptr, nullptr);

    // edge branch: all tensor (bf16x3)
    mma_gemm<128, 4, 2, 1, true><<<dim3(gbE, 1), 256>>>(
        E + 256, 384, UVP + 512, 640, BheH, BheL, bae2, he, 64, RE);
    pe_agg_kernel<<<dim3(NN / 4, BBc), 128>>>();
    mma_gemm<96, 4, 3, 2, true><<<dim3(gbE, 1), 384>>>(
        pe, 64, edges, 32, B3eH, B3eL, ble1, h3e, 96, RE);
    mma_gemm<96, 8, 1, 0, true><<<dim3((RE + 255) / 256, 1), 256>>>(
        h3e, 96, nullptr, 0, BoeH, BoeL, ble2, out_edges, 32, RE);
}

// round 9
// speedup vs baseline: 4.0257x; 1.0512x over previous
#include <cuda_runtime.h>
#include <cuda_bf16.h>
#include <math.h>
#include <stdint.h>

// Problem constants (match the reference's _build_indices(N=1024, M=32))
#define NN   1024
#define MMW  32
#define NEg  32240          // total edges
#define BBc  2
#define RE   (BBc*NEg)      // 64480 edge rows
#define RN   (BBc*NN)       // 2048 node rows

// ---------------- scratch (static device globals; no runtime allocs) -------
__device__ int2  g_eij[NEg];              // (i=target, j=source) per edge
__device__ float g_UVP[(size_t)RN*640];   // [U(256) | V(256) | P(128)] per node row
__device__ float g_E  [(size_t)RE*384];   // [E1(256) | E2(128)] per edge row (raw)
__device__ float g_hn [(size_t)RE*128];
__device__ float g_pn [(size_t)RN*128];
__device__ float g_h3n[(size_t)RN*192];
__device__ float g_he [(size_t)RE*64];
__device__ float g_pe [(size_t)RE*64];
__device__ float g_h3e[(size_t)RE*96];
// combined fp32 weight for UVP precompute: [64][640]
__device__ float g_WUVP[64*640];
// bf16 hi/lo splits of weights, stored as B[n][k] (transposed)
__device__ unsigned short g_Bhi  [128*256];   // Wan2
__device__ unsigned short g_Blo  [128*256];
__device__ unsigned short g_BheH [64*128];    // Wae2
__device__ unsigned short g_BheL [64*128];
__device__ unsigned short g_B3eH [96*96];     // Wle1
__device__ unsigned short g_B3eL [96*96];
__device__ unsigned short g_BoeH [32*96];     // Wle2
__device__ unsigned short g_BoeL [32*96];
__device__ unsigned short g_BeH  [384*32];    // [Wan1[64:96] | Wae1[64:96]]
__device__ unsigned short g_BeL  [384*32];
__device__ float g_bE[384];                   // [ban1 | bae1]

// ---------------- f32x2 packed-FMA helpers ----------------------------------
__device__ __forceinline__ void ffma2(unsigned long long& d,
                                      unsigned long long a,
                                      unsigned long long b) {
    asm("fma.rn.f32x2 %0, %1, %2, %0;" : "+l"(d) : "l"(a), "l"(b));
}
__device__ __forceinline__ unsigned long long bcast2(float x) {
    unsigned long long r;
    asm("mov.b64 %0, {%1, %1};" : "=l"(r) : "f"(x));
    return r;
}
__device__ __forceinline__ float2 unpack2(unsigned long long v) {
    float2 f;
    asm("mov.b64 {%0, %1}, %2;" : "=f"(f.x), "=f"(f.y) : "l"(v));
    return f;
}

// ---------------- mma.sync helpers ------------------------------------------
__device__ __forceinline__ uint32_t smem_u32(const void* p) {
    uint32_t a;
    asm("{ .reg .u64 t; cvta.to.shared.u64 t, %1; cvt.u32.u64 %0, t; }"
        : "=r"(a) : "l"(p));
    return a;
}
__device__ __forceinline__ void ldsm_x4(uint32_t& r0, uint32_t& r1,
                                        uint32_t& r2, uint32_t& r3,
                                        uint32_t addr) {
    asm volatile("ldmatrix.sync.aligned.m8n8.x4.shared.b16 {%0,%1,%2,%3}, [%4];"
                 : "=r"(r0), "=r"(r1), "=r"(r2), "=r"(r3) : "r"(addr));
}
__device__ __forceinline__ void mma_bf16(float& c0, float& c1, float& c2, float& c3,
                                         uint32_t a0, uint32_t a1, uint32_t a2, uint32_t a3,
                                         uint32_t b0, uint32_t b1) {
    asm volatile("mma.sync.aligned.m16n8k16.row.col.f32.bf16.bf16.f32 "
                 "{%0,%1,%2,%3}, {%4,%5,%6,%7}, {%8,%9}, {%0,%1,%2,%3};"
                 : "+f"(c0), "+f"(c1), "+f"(c2), "+f"(c3)
                 : "r"(a0), "r"(a1), "r"(a2), "r"(a3), "r"(b0), "r"(b1));
}

static __device__ __forceinline__ unsigned short bf16_bits(__nv_bfloat16 h) {
    return *reinterpret_cast<unsigned short*>(&h);
}
__device__ __forceinline__ void split_pack8(const float* vals,
                                            uint32_t* hp, uint32_t* lp) {
#pragma unroll
    for (int q = 0; q < 4; q++) {
        __nv_bfloat16 h0 = __float2bfloat16(vals[2 * q]);
        __nv_bfloat16 h1 = __float2bfloat16(vals[2 * q + 1]);
        float r0 = vals[2 * q]     - __bfloat162float(h0);
        float r1 = vals[2 * q + 1] - __bfloat162float(h1);
        __nv_bfloat16 l0 = __float2bfloat16(r0);
        __nv_bfloat16 l1 = __float2bfloat16(r1);
        hp[q] = (uint32_t)bf16_bits(h0) | ((uint32_t)bf16_bits(h1) << 16);
        lp[q] = (uint32_t)bf16_bits(l0) | ((uint32_t)bf16_bits(l1) << 16);
    }
}

__device__ __forceinline__ int group_start(int i) {
    return (i <= 32) ? (i * (i - 1) / 2) : (496 + (i - 32) * 32);
}

__device__ __forceinline__ float4 relu4(float4 v) {
    v.x = fmaxf(v.x, 0.f); v.y = fmaxf(v.y, 0.f);
    v.z = fmaxf(v.z, 0.f); v.w = fmaxf(v.w, 0.f);
    return v;
}
__device__ __forceinline__ float4 add4(float4 a, float4 b) {
    return make_float4(a.x + b.x, a.y + b.y, a.z + b.z, a.w + b.w);
}

// ---------------- all prep in one launch (weights + edge indices) -----------
__device__ __forceinline__ void split_store(float w, unsigned short* hi,
                                            unsigned short* lo, size_t o) {
    __nv_bfloat16 h = __float2bfloat16(w);
    float rem = w - __bfloat162float(h);
    hi[o] = bf16_bits(h);
    lo[o] = bf16_bits(__float2bfloat16(rem));
}
#define SEG0 32768                 // Wan2 -> g_Bhi/Blo
#define SEG1 (SEG0 + 8192)         // Wae2
#define SEG2 (SEG1 + 9216)         // Wle1
#define SEG3 (SEG2 + 3072)         // Wle2
#define SEG4 (SEG3 + 8192)         // Wan1[64:96] -> g_Be[0:256]
#define SEG5 (SEG4 + 4096)         // Wae1[64:96] -> g_Be[256:384]
#define SEG6 (SEG5 + 40960)        // g_WUVP
#define SEG7 (SEG6 + 384)          // g_bE
#define SEG8 (SEG7 + NEg)          // eij build
__global__ void prep_kernel(const float* __restrict__ Wan1,
                            const float* __restrict__ Wan2,
                            const float* __restrict__ Wae1,
                            const float* __restrict__ Wae2,
                            const float* __restrict__ Wle1,
                            const float* __restrict__ Wle2,
                            const float* __restrict__ ban1,
                            const float* __restrict__ bae1) {
    int idx = blockIdx.x * blockDim.x + threadIdx.x;
    if (idx < SEG0) {                          // Wan2 [256][128]
        int k = idx >> 7, n = idx & 127;
        split_store(Wan2[idx], g_Bhi, g_Blo, (size_t)n * 256 + k);
    } else if (idx < SEG1) {                   // Wae2 [128][64]
        int t = idx - SEG0;
        int k = t >> 6, n = t & 63;
        split_store(Wae2[t], g_BheH, g_BheL, (size_t)n * 128 + k);
    } else if (idx < SEG2) {                   // Wle1 [96][96]
        int t = idx - SEG1;
        int k = t / 96, n = t % 96;
        split_store(Wle1[t], g_B3eH, g_B3eL, (size_t)n * 96 + k);
    } else if (idx < SEG3) {                   // Wle2 [96][32]
        int t = idx - SEG2;
        int k = t >> 5, n = t & 31;
        split_store(Wle2[t], g_BoeH, g_BoeL, (size_t)n * 96 + k);
    } else if (idx < SEG4) {                   // Wan1 rows 64..95 -> g_Be n<256
        int t = idx - SEG3;
        int k = t >> 8, n = t & 255;
        split_store(Wan1[(size_t)(64 + k) * 256 + n], g_BeH, g_BeL,
                    (size_t)n * 32 + k);
    } else if (idx < SEG5) {                   // Wae1 rows 64..95 -> g_Be n 256..383
        int t = idx - SEG4;
        int k = t >> 7, n = t & 127;
        split_store(Wae1[(size_t)(64 + k) * 128 + n], g_BeH, g_BeL,
                    (size_t)(256 + n) * 32 + k);
    } else if (idx < SEG6) {                   // g_WUVP [64][640]
        int t = idx - SEG5;
        int k = t / 640, n = t % 640;
        float w;
        if (n < 256)      w = Wan1[(size_t)k * 256 + n];
        else if (n < 512) w = Wan1[(size_t)(96 + k) * 256 + (n - 256)];
        else              w = Wae1[(size_t)k * 128 + (n - 512)];
        g_WUVP[t] = w;
    } else if (idx < SEG7) {                   // g_bE
        int n = idx - SEG6;
        g_bE[n] = (n < 256) ? ban1[n] : bae1[n - 256];
    } else if (idx < SEG8) {                   // edge (i,j) build
        int e = idx - SEG7;
        int i, j;
        if (e < 496) {
            i = (int)((1.0f + sqrtf(8.0f * (float)e + 1.0f)) * 0.5f);
            while (i * (i - 1) / 2 > e) i--;
            while ((i + 1) * i / 2 <= e) i++;
            j = e - i * (i - 1) / 2;
        } else {
            int q = (e - 496) >> 5;
            i = 32 + q;
            j = (i - 32) + ((e - 496) & 31);
        }
        g_eij[e] = make_int2(i, j);
    }
}

#define A_STRIDE 40          // bf16 elems per row (80 B)

// ---------------- E kernel: E[r][0:384] = edges[r] @ [W|W] + [b|b] ----------
// A (128 rows x 32 k) resident in smem, A frags hoisted to regs; internal
// loop over 6 N-tiles of 64 with double-buffered B. grid 504, block 256.
__global__ __launch_bounds__(256, 2)
void e_mma_kernel(const float* __restrict__ edges, float* __restrict__ C)
{
    __shared__ __align__(16) unsigned short sAhi[128 * A_STRIDE];
    __shared__ __align__(16) unsigned short sAlo[128 * A_STRIDE];
    __shared__ __align__(16) unsigned short sBhi[2][64 * A_STRIDE];
    __shared__ __align__(16) unsigned short sBlo[2][64 * A_STRIDE];

    const int tid  = threadIdx.x;
    const int wid  = tid >> 5;
    const int lane = tid & 31;
    const int warp_m = wid & 3;          // 4 row groups
    const int warp_n = wid >> 2;         // 2 col groups of 32
    const int rbase  = blockIdx.x * 128;

    // ---- A load + split (2 segments per thread) ----
#pragma unroll
    for (int s = 0; s < 2; s++) {
        int idx = tid + s * 256;
        int row = idx >> 2;
        int lk  = (idx & 3) * 8;
        int r   = rbase + row;
        float vals[8];
        if (r < RE) {
            float4 v0 = *(const float4*)(edges + (size_t)r * 32 + lk);
            float4 v1 = *(const float4*)(edges + (size_t)r * 32 + lk + 4);
            vals[0] = v0.x; vals[1] = v0.y; vals[2] = v0.z; vals[3] = v0.w;
            vals[4] = v1.x; vals[5] = v1.y; vals[6] = v1.z; vals[7] = v1.w;
        } else {
#pragma unroll
            for (int q = 0; q < 8; q++) vals[q] = 0.f;
        }
        uint32_t hp[4], lp[4];
        split_pack8(vals, hp, lp);
        uint32_t off = (uint32_t)(row * A_STRIDE + lk) * 2;
        *(uint4*)((char*)sAhi + off) = make_uint4(hp[0], hp[1], hp[2], hp[3]);
        *(uint4*)((char*)sAlo + off) = make_uint4(lp[0], lp[1], lp[2], lp[3]);
    }

    // ---- B tile 0 load ----
    const int bnl = tid >> 2;            // 0..63 (local B row = output col)
    const int bkk = (tid & 3) * 8;
    uint4 bsh, bsl;
    auto ldgB = [&](int nt) {
        int n = nt * 64 + bnl;
        bsh = *(const uint4*)(g_BeH + (size_t)n * 32 + bkk);
        bsl = *(const uint4*)(g_BeL + (size_t)n * 32 + bkk);
    };
    auto stsB = [&](int buf) {
        uint32_t off = (uint32_t)(bnl * A_STRIDE + bkk) * 2;
        *(uint4*)((char*)sBhi[buf] + off) = bsh;
        *(uint4*)((char*)sBlo[buf] + off) = bsl;
    };
    ldgB(0);
    stsB(0);
    __syncthreads();

    // ---- hoisted A fragments ----
    const uint32_t sb_ahi = smem_u32(sAhi);
    const uint32_t sb_alo = smem_u32(sAlo);
    const int a_m    = warp_m * 32 + (lane & 7) + ((lane >> 3) & 1) * 8;
    const int a_koff = (lane >> 4) * 8;
    uint32_t ahi[2][2][4], alo[2][2][4];   // [ks][mt][4]
#pragma unroll
    for (int ks = 0; ks < 2; ks++)
#pragma unroll
        for (int mt = 0; mt < 2; mt++) {
            uint32_t ad = sb_ahi +
                (uint32_t)((a_m + mt * 16) * (A_STRIDE * 2) +
                           (ks * 16 + a_koff) * 2);
            ldsm_x4(ahi[ks][mt][0], ahi[ks][mt][1], ahi[ks][mt][2], ahi[ks][mt][3], ad);
            ldsm_x4(alo[ks][mt][0], alo[ks][mt][1], alo[ks][mt][2], alo[ks][mt][3],
                    ad + (sb_alo - sb_ahi));
        }

    const int b_n    = warp_n * 32 + (lane & 7) + (lane >> 4) * 8;
    const int b_koff = ((lane >> 3) & 1) * 8;
    const int lq = lane & 3;
    const int lr = lane >> 2;

#pragma unroll 1
    for (int nt = 0; nt < 6; nt++) {
        const int cur = nt & 1;
        if (nt < 5) ldgB(nt + 1);

        const uint32_t sb_bhi = smem_u32(sBhi[cur]);
        const uint32_t sb_blo = smem_u32(sBlo[cur]);
        uint32_t bhi[2][4][2], blo[2][4][2];   // [ks][n8][2]
#pragma unroll
        for (int ks = 0; ks < 2; ks++)
#pragma unroll
            for (int p = 0; p < 2; p++) {
                uint32_t bd = sb_bhi +
                    (uint32_t)((b_n + p * 16) * (A_STRIDE * 2) +
                               (ks * 16 + b_koff) * 2);
                ldsm_x4(bhi[ks][2 * p][0], bhi[ks][2 * p][1],
                        bhi[ks][2 * p + 1][0], bhi[ks][2 * p + 1][1], bd);
                ldsm_x4(blo[ks][2 * p][0], blo[ks][2 * p][1],
                        blo[ks][2 * p + 1][0], blo[ks][2 * p + 1][1],
                        bd + (sb_blo - sb_bhi));
            }

        float acc[2][4][4];
#pragma unroll
        for (int mt = 0; mt < 2; mt++)
#pragma unroll
            for (int n8 = 0; n8 < 4; n8++)
#pragma unroll
                for (int q = 0; q < 4; q++) acc[mt][n8][q] = 0.f;

#pragma unroll
        for (int ks = 0; ks < 2; ks++)
#pragma unroll
            for (int mt = 0; mt < 2; mt++)
#pragma unroll
                for (int n8 = 0; n8 < 4; n8++) {
                    float* d = acc[mt][n8];
                    mma_bf16(d[0], d[1], d[2], d[3],
                             ahi[ks][mt][0], ahi[ks][mt][1], ahi[ks][mt][2], ahi[ks][mt][3],
                             bhi[ks][n8][0], bhi[ks][n8][1]);
                    mma_bf16(d[0], d[1], d[2], d[3],
                             ahi[ks][mt][0], ahi[ks][mt][1], ahi[ks][mt][2], ahi[ks][mt][3],
                             blo[ks][n8][0], blo[ks][n8][1]);
                    mma_bf16(d[0], d[1], d[2], d[3],
                             alo[ks][mt][0], alo[ks][mt][1], alo[ks][mt][2], alo[ks][mt][3],
                             bhi[ks][n8][0], bhi[ks][n8][1]);
                }

        // epilogue (raw: bias only, no relu)
#pragma unroll
        for (int mt = 0; mt < 2; mt++) {
            int m0 = rbase + warp_m * 32 + mt * 16 + lr;
#pragma unroll
            for (int n8 = 0; n8 < 4; n8++) {
                int cc = nt * 64 + warp_n * 32 + n8 * 8 + lq * 2;
                float2 bb = *(const float2*)(g_bE + cc);
                if (m0 < RE) {
                    float2 o;
                    o.x = acc[mt][n8][0] + bb.x;
                    o.y = acc[mt][n8][1] + bb.y;
                    *(float2*)(C + (size_t)m0 * 384 + cc) = o;
                }
                if (m0 + 8 < RE) {
                    float2 o;
                    o.x = acc[mt][n8][2] + bb.x;
                    o.y = acc[mt][n8][3] + bb.y;
                    *(float2*)(C + (size_t)(m0 + 8) * 384 + cc) = o;
                }
            }
        }

        if (nt < 5) stsB(1 - cur);
        __syncthreads();
    }
}

// ---------------- mma.sync bf16x3 kernel: hn = relu((E1+U+V)@Wan2 + ban2) ---
#define SM_AHI 0
#define SM_ALO 10240
#define SM_BHI 20480
#define SM_BLO 30720

__global__ __launch_bounds__(512, 1)
void hn_mma_kernel(const float* __restrict__ E,
                   const float* __restrict__ UVP,
                   const float* __restrict__ bias,
                   float* __restrict__ C)
{
    __shared__ __align__(16) char smem[40960];
    const uint32_t sb = smem_u32(smem);

    const int tid   = threadIdx.x;
    const int wid   = tid >> 5;
    const int lane  = tid & 31;
    const int warp_m = wid & 3;
    const int warp_n = wid >> 2;
    const int rbase = blockIdx.x * 128;

    const int lrow = tid >> 2;
    const int lk   = (tid & 3) * 8;
    const int r    = rbase + lrow;
    const bool rv  = (r < RE);

    const float* pe1 = nullptr;
    const float* pu  = nullptr;
    const float* pv  = nullptr;
    if (rv) {
        int b = (r >= NEg) ? 1 : 0;
        int e = r - b * NEg;
        int2 ij = g_eij[e];
        pe1 = E + (size_t)r * 384;
        pu  = UVP + ((size_t)(b * NN + ij.y)) * 640;
        pv  = UVP + ((size_t)(b * NN + ij.x)) * 640 + 256;
    }

    float  a_st[8];
    uint4  b_st_hi, b_st_lo;

    auto loadregs = [&](int k0) {
        if (rv) {
            float4 e0 = *(const float4*)(pe1 + k0 + lk);
            float4 e1 = *(const float4*)(pe1 + k0 + lk + 4);
            float4 u0 = *(const float4*)(pu + k0 + lk);
            float4 u1 = *(const float4*)(pu + k0 + lk + 4);
            float4 v0 = *(const float4*)(pv + k0 + lk);
            float4 v1 = *(const float4*)(pv + k0 + lk + 4);
            float4 s0 = relu4(add4(add4(e0, u0), v0));
            float4 s1 = relu4(add4(add4(e1, u1), v1));
            a_st[0] = s0.x; a_st[1] = s0.y; a_st[2] = s0.z; a_st[3] = s0.w;
            a_st[4] = s1.x; a_st[5] = s1.y; a_st[6] = s1.z; a_st[7] = s1.w;
        } else {
#pragma unroll
            for (int q = 0; q < 8; q++) a_st[q] = 0.f;
        }
        b_st_hi = *(const uint4*)(g_Bhi + (size_t)lrow * 256 + k0 + lk);
        b_st_lo = *(const uint4*)(g_Blo + (size_t)lrow * 256 + k0 + lk);
    };
    auto stsregs = [&]() {
        uint32_t hp[4], lp[4];
        split_pack8(a_st, hp, lp);
        uint32_t off = (uint32_t)(lrow * (A_STRIDE * 2) + lk * 2);
        *(uint4*)(smem + SM_AHI + off) = make_uint4(hp[0], hp[1], hp[2], hp[3]);
        *(uint4*)(smem + SM_ALO + off) = make_uint4(lp[0], lp[1], lp[2], lp[3]);
        *(uint4*)(smem + SM_BHI + off) = b_st_hi;
        *(uint4*)(smem + SM_BLO + off) = b_st_lo;
    };

    float acc[2][4][4];
#pragma unroll
    for (int mt = 0; mt < 2; mt++)
#pragma unroll
        for (int nt = 0; nt < 4; nt++)
#pragma unroll
            for (int q = 0; q < 4; q++) acc[mt][nt][q] = 0.f;

    const int a_m   = warp_m * 32 + (lane & 7) + ((lane >> 3) & 1) * 8;
    const int a_koff = (lane >> 4) * 8;
    const int b_n   = warp_n * 32 + (lane & 7) + (lane >> 4) * 8;
    const int b_koff = ((lane >> 3) & 1) * 8;

    loadregs(0);
#pragma unroll 1
    for (int c = 0; c < 8; c++) {
        stsregs();
        __syncthreads();
        if (c < 7) loadregs((c + 1) * 32);

#pragma unroll
        for (int ks = 0; ks < 2; ks++) {
            uint32_t ahi[2][4], alo[2][4];
#pragma unroll
            for (int mt = 0; mt < 2; mt++) {
                uint32_t ad = sb + SM_AHI +
                    (uint32_t)((a_m + mt * 16) * (A_STRIDE * 2) +
                               (ks * 16 + a_koff) * 2);
                ldsm_x4(ahi[mt][0], ahi[mt][1], ahi[mt][2], ahi[mt][3], ad);
                ldsm_x4(alo[mt][0], alo[mt][1], alo[mt][2], alo[mt][3],
                        ad + (SM_ALO - SM_AHI));
            }
            uint32_t bhi[4][2], blo[4][2];
#pragma unroll
            for (int p = 0; p < 2; p++) {
                uint32_t bd = sb + SM_BHI +
                    (uint32_t)((b_n + p * 16) * (A_STRIDE * 2) +
                               (ks * 16 + b_koff) * 2);
                ldsm_x4(bhi[2 * p][0], bhi[2 * p][1],
                        bhi[2 * p + 1][0], bhi[2 * p + 1][1], bd);
                ldsm_x4(blo[2 * p][0], blo[2 * p][1],
                        blo[2 * p + 1][0], blo[2 * p + 1][1],
                        bd + (SM_BLO - SM_BHI));
            }
#pragma unroll
            for (int mt = 0; mt < 2; mt++)
#pragma unroll
                for (int nt = 0; nt < 4; nt++) {
                    float* d = acc[mt][nt];
                    mma_bf16(d[0], d[1], d[2], d[3],
                             ahi[mt][0], ahi[mt][1], ahi[mt][2], ahi[mt][3],
                             bhi[nt][0], bhi[nt][1]);
                    mma_bf16(d[0], d[1], d[2], d[3],
                             ahi[mt][0], ahi[mt][1], ahi[mt][2], ahi[mt][3],
                             blo[nt][0], blo[nt][1]);
                    mma_bf16(d[0], d[1], d[2], d[3],
                             alo[mt][0], alo[mt][1], alo[mt][2], alo[mt][3],
                             bhi[nt][0], bhi[nt][1]);
                }
        }
        __syncthreads();
    }

    const int lq = lane & 3;
    const int lr = lane >> 2;
#pragma unroll
    for (int mt = 0; mt < 2; mt++) {
        int m0 = rbase + warp_m * 32 + mt * 16 + lr;
#pragma unroll
        for (int nt = 0; nt < 4; nt++) {
            int cc = warp_n * 32 + nt * 8 + lq * 2;
            float2 bb = *(const float2*)(bias + cc);
            if (m0 < RE) {
                float2 o;
                o.x = fmaxf(acc[mt][nt][0] + bb.x, 0.f);
                o.y = fmaxf(acc[mt][nt][1] + bb.y, 0.f);
                *(float2*)(C + (size_t)m0 * 128 + cc) = o;
            }
            if (m0 + 8 < RE) {
                float2 o;
                o.x = fmaxf(acc[mt][nt][2] + bb.x, 0.f);
                o.y = fmaxf(acc[mt][nt][3] + bb.y, 0.f);
                *(float2*)(C + (size_t)(m0 + 8) * 128 + cc) = o;
            }
        }
    }
}

// ---------------- generalized N-tiled mma.sync bf16x3 GEMM ------------------
// MMODE 0: A row = X0 + r*ld0
// MMODE 1: A[k] = relu(X0[r*ld0+k] + X1[(b*NN+j)*ld1+k])
// MMODE 2: A = X0[r*ld0](64) ++ X1[r*ld1](32)
template<int K, int WM, int WN, int MMODE, bool RELU>
__global__ __launch_bounds__(WM * WN * 32)
void mma_gemm(const float* __restrict__ X0, int ld0,
              const float* __restrict__ X1, int ld1,
              const unsigned short* __restrict__ Bhi,
              const unsigned short* __restrict__ Blo,
              const float* __restrict__ bias,
              float* __restrict__ C, int ldC, int R)
{
    constexpr int MT  = WM * 32;
    constexpr int NB  = WN * 32;
    constexpr int NTH = WM * WN * 32;
    __shared__ __align__(16) unsigned short sAhi[MT * A_STRIDE];
    __shared__ __align__(16) unsigned short sAlo[MT * A_STRIDE];
    __shared__ __align__(16) unsigned short sBhi[NB * A_STRIDE];
    __shared__ __align__(16) unsigned short sBlo[NB * A_STRIDE];

    const int tid  = threadIdx.x;
    const int wid  = tid >> 5;
    const int lane = tid & 31;
    const int warp_m = wid % WM;
    const int warp_n = wid / WM;
    const int rbase = blockIdx.x * MT;
    const int cbase = blockIdx.y * NB;

    float acc[2][4][4];
#pragma unroll
    for (int mt = 0; mt < 2; mt++)
#pragma unroll
        for (int nt = 0; nt < 4; nt++)
#pragma unroll
            for (int q = 0; q < 4; q++) acc[mt][nt][q] = 0.f;

    const int a_m    = warp_m * 32 + (lane & 7) + ((lane >> 3) & 1) * 8;
    const int a_koff = (lane >> 4) * 8;
    const int b_n    = warp_n * 32 + (lane & 7) + (lane >> 4) * 8;
    const int b_koff = ((lane >> 3) & 1) * 8;

    const uint32_t sb_ahi = smem_u32(sAhi);
    const uint32_t sb_alo = smem_u32(sAlo);
    const uint32_t sb_bhi = smem_u32(sBhi);
    const uint32_t sb_blo = smem_u32(sBlo);

#pragma unroll 1
    for (int c = 0; c < K / 32; c++) {
        const int k0 = c * 32;
        // ---- A loader ----
        for (int idx = tid; idx < MT * 4; idx += NTH) {
            const int row = idx >> 2;
            const int lk  = (idx & 3) * 8;
            const int r   = rbase + row;
            const int kb  = k0 + lk;
            float vals[8];
            if (r < R) {
                if (MMODE == 0) {
                    float4 v0 = *(const float4*)(X0 + (size_t)r * ld0 + kb);
                    float4 v1 = *(const float4*)(X0 + (size_t)r * ld0 + kb + 4);
                    vals[0] = v0.x; vals[1] = v0.y; vals[2] = v0.z; vals[3] = v0.w;
                    vals[4] = v1.x; vals[5] = v1.y; vals[6] = v1.z; vals[7] = v1.w;
                } else if (MMODE == 1) {
                    int b = (r >= NEg) ? 1 : 0;
                    int e = r - b * NEg;
                    int2 ij = g_eij[e];
                    const float* pa = X0 + (size_t)r * ld0 + kb;
                    const float* pb = X1 + ((size_t)(b * NN + ij.y)) * ld1 + kb;
                    float4 s0 = relu4(add4(*(const float4*)pa,
                                           *(const float4*)pb));
                    float4 s1 = relu4(add4(*(const float4*)(pa + 4),
                                           *(const float4*)(pb + 4)));
                    vals[0] = s0.x; vals[1] = s0.y; vals[2] = s0.z; vals[3] = s0.w;
                    vals[4] = s1.x; vals[5] = s1.y; vals[6] = s1.z; vals[7] = s1.w;
                } else { // MMODE 2: X0(64) ++ X1(32)
                    const float* s = (kb < 64) ? (X0 + (size_t)r * ld0 + kb)
                                               : (X1 + (size_t)r * ld1 + kb - 64);
                    float4 v0 = *(const float4*)s;
                    float4 v1 = *(const float4*)(s + 4);
                    vals[0] = v0.x; vals[1] = v0.y; vals[2] = v0.z; vals[3] = v0.w;
                    vals[4] = v1.x; vals[5] = v1.y; vals[6] = v1.z; vals[7] = v1.w;
                }
            } else {
#pragma unroll
                for (int q = 0; q < 8; q++) vals[q] = 0.f;
            }
            uint32_t hp[4], lp[4];
            split_pack8(vals, hp, lp);
            uint32_t off = (uint32_t)(row * A_STRIDE + lk) * 2;
            *(uint4*)((char*)sAhi + off) = make_uint4(hp[0], hp[1], hp[2], hp[3]);
            *(uint4*)((char*)sAlo + off) = make_uint4(lp[0], lp[1], lp[2], lp[3]);
        }
        // ---- B loader ----
        for (int idx = tid; idx < NB * 4; idx += NTH) {
            const int n  = idx >> 2;
            const int lk = (idx & 3) * 8;
            uint4 hv = *(const uint4*)(Bhi + (size_t)(cbase + n) * K + k0 + lk);
            uint4 lv = *(const uint4*)(Blo + (size_t)(cbase + n) * K + k0 + lk);
            uint32_t off = (uint32_t)(n * A_STRIDE + lk) * 2;
            *(uint4*)((char*)sBhi + off) = hv;
            *(uint4*)((char*)sBlo + off) = lv;
        }
        __syncthreads();

#pragma unroll
        for (int ks = 0; ks < 2; ks++) {
            uint32_t ahi[2][4], alo[2][4];
#pragma unroll
            for (int mt = 0; mt < 2; mt++) {
                uint32_t ad = sb_ahi +
                    (uint32_t)((a_m + mt * 16) * (A_STRIDE * 2) +
                               (ks * 16 + a_koff) * 2);
                ldsm_x4(ahi[mt][0], ahi[mt][1], ahi[mt][2], ahi[mt][3], ad);
                ldsm_x4(alo[mt][0], alo[mt][1], alo[mt][2], alo[mt][3],
                        ad + (sb_alo - sb_ahi));
            }
            uint32_t bhi[4][2], blo[4][2];
#pragma unroll
            for (int p = 0; p < 2; p++) {
                uint32_t bd = sb_bhi +
                    (uint32_t)((b_n + p * 16) * (A_STRIDE * 2) +
                               (ks * 16 + b_koff) * 2);
                ldsm_x4(bhi[2 * p][0], bhi[2 * p][1],
                        bhi[2 * p + 1][0], bhi[2 * p + 1][1], bd);
                ldsm_x4(blo[2 * p][0], blo[2 * p][1],
                        blo[2 * p + 1][0], blo[2 * p + 1][1],
                        bd + (sb_blo - sb_bhi));
            }
#pragma unroll
            for (int mt = 0; mt < 2; mt++)
#pragma unroll
                for (int nt = 0; nt < 4; nt++) {
                    float* d = acc[mt][nt];
                    mma_bf16(d[0], d[1], d[2], d[3],
                             ahi[mt][0], ahi[mt][1], ahi[mt][2], ahi[mt][3],
                             bhi[nt][0], bhi[nt][1]);
                    mma_bf16(d[0], d[1], d[2], d[3],
                             ahi[mt][0], ahi[mt][1], ahi[mt][2], ahi[mt][3],
                             blo[nt][0], blo[nt][1]);
                    mma_bf16(d[0], d[1], d[2], d[3],
                             alo[mt][0], alo[mt][1], alo[mt][2], alo[mt][3],
                             bhi[nt][0], bhi[nt][1]);
                }
        }
        __syncthreads();
    }

    // ---- epilogue ----
    const int lq = lane & 3;
    const int lr = lane >> 2;
#pragma unroll
    for (int mt = 0; mt < 2; mt++) {
        int m0 = rbase + warp_m * 32 + mt * 16 + lr;
#pragma unroll
        for (int nt = 0; nt < 4; nt++) {
            int cc = cbase + warp_n * 32 + nt * 8 + lq * 2;
            float2 bb = *(const float2*)(bias + cc);
            auto act = [](float v) { return RELU ? fmaxf(v, 0.f) : v; };
            if (m0 < R) {
                float2 o;
                o.x = act(acc[mt][nt][0] + bb.x);
                o.y = act(acc[mt][nt][1] + bb.y);
                *(float2*)(C + (size_t)m0 * ldC + cc) = o;
            }
            if (m0 + 8 < R) {
                float2 o;
                o.x = act(acc[mt][nt][2] + bb.x);
                o.y = act(acc[mt][nt][3] + bb.y);
                *(float2*)(C + (size_t)(m0 + 8) * ldC + cc) = o;
            }
        }
    }
}

// ---------------- FFMA2 GEMM (node-side small work) --------------------------
// MODE 0: A plain [R x K];  MODE 3: A = X0[r](128) ++ X1[r](64)  (K=192)
template<int K, int NOUT, int MODE, bool RELU>
__global__ __launch_bounds__(256, 2)
void gemm_bias_relu(const float* __restrict__ A,
                    const float* __restrict__ W, int ldW,
                    const float* __restrict__ bias,
                    float* __restrict__ C, int R,
                    const float* __restrict__ X0,
                    const float* __restrict__ X1)
{
    __shared__ __align__(16) float As[2][32][128];
    __shared__ __align__(16) float Bs[2][32][64];

    const int tid   = threadIdx.x;
    const int tx    = tid & 15;
    const int ty    = tid >> 4;
    const int rbase = blockIdx.y * 128;
    const int cbase = blockIdx.x * 64;

    const int lm = tid >> 1;
    const int lk = (tid & 1) * 16;
    const int r  = rbase + lm;
    const bool rv = (r < R);

    const float* p0 = nullptr;
    const float* p1 = nullptr;
    if (rv) {
        if (MODE == 0) {
            p0 = A + (size_t)r * K;
        } else { // MODE 3
            p0 = X0 + (size_t)r * 128;
            p1 = X1 + (size_t)r * 64;
        }
    }

    const int bk = tid >> 4;
    const int bn = (tid & 15) * 4;
    const bool cv = (cbase + bn < NOUT);

    unsigned long long acc[4][4];
#pragma unroll
    for (int p = 0; p < 4; p++)
#pragma unroll
        for (int v = 0; v < 4; v++) acc[p][v] = 0ull;

    float4 apf[4];
    float4 bpf[2];

    auto loadA = [&](int k0) {
        const int kb = k0 + lk;
#pragma unroll
        for (int u = 0; u < 4; u++) apf[u] = make_float4(0.f, 0.f, 0.f, 0.f);
        if (!rv) return;
        if (MODE == 0) {
#pragma unroll
            for (int u = 0; u < 4; u++) apf[u] = *(const float4*)(p0 + kb + 4 * u);
        } else {
            const float* s = (kb < 128) ? (p0 + kb) : (p1 + kb - 128);
#pragma unroll
            for (int u = 0; u < 4; u++) apf[u] = *(const float4*)(s + 4 * u);
        }
    };
    auto loadB = [&](int k0) {
        bpf[0] = make_float4(0.f, 0.f, 0.f, 0.f);
        bpf[1] = make_float4(0.f, 0.f, 0.f, 0.f);
        if (cv) {
            bpf[0] = *(const float4*)(W + (size_t)(k0 + bk) * ldW + (cbase + bn));
            bpf[1] = *(const float4*)(W + (size_t)(k0 + bk + 16) * ldW + (cbase + bn));
        }
    };
    auto stsA = [&](int buf) {
#pragma unroll
        for (int u = 0; u < 4; u++) {
            As[buf][lk + 4 * u + 0][lm] = apf[u].x;
            As[buf][lk + 4 * u + 1][lm] = apf[u].y;
            As[buf][lk + 4 * u + 2][lm] = apf[u].z;
            As[buf][lk + 4 * u + 3][lm] = apf[u].w;
        }
    };
    auto stsB = [&](int buf) {
        *(float4*)&Bs[buf][bk][bn]      = bpf[0];
        *(float4*)&Bs[buf][bk + 16][bn] = bpf[1];
    };

    constexpr int NC = K / 32;
    loadA(0); loadB(0);
    stsA(0);  stsB(0);
    __syncthreads();

#pragma unroll
    for (int c = 0; c < NC; c++) {
        const int cur = c & 1;
        if (c + 1 < NC) { loadA((c + 1) * 32); loadB((c + 1) * 32); }

#pragma unroll
        for (int kk = 0; kk < 32; kk++) {
            float4 b4 = *(const float4*)&Bs[cur][kk][tx * 4];
            unsigned long long bx = bcast2(b4.x);
            unsigned long long by = bcast2(b4.y);
            unsigned long long bz = bcast2(b4.z);
            unsigned long long bw = bcast2(b4.w);
            ulonglong2 a01 = *(const ulonglong2*)&As[cur][kk][ty * 8];
            ulonglong2 a23 = *(const ulonglong2*)&As[cur][kk][ty * 8 + 4];
            ffma2(acc[0][0], a01.x, bx); ffma2(acc[0][1], a01.x, by);
            ffma2(acc[0][2], a01.x, bz); ffma2(acc[0][3], a01.x, bw);
            ffma2(acc[1][0], a01.y, bx); ffma2(acc[1][1], a01.y, by);
            ffma2(acc[1][2], a01.y, bz); ffma2(acc[1][3], a01.y, bw);
            ffma2(acc[2][0], a23.x, bx); ffma2(acc[2][1], a23.x, by);
            ffma2(acc[2][2], a23.x, bz); ffma2(acc[2][3], a23.x, bw);
            ffma2(acc[3][0], a23.y, bx); ffma2(acc[3][1], a23.y, by);
            ffma2(acc[3][2], a23.y, bz); ffma2(acc[3][3], a23.y, bw);
        }

        if (c + 1 < NC) { stsA(1 - cur); stsB(1 - cur); }
        __syncthreads();
    }

    const int c = cbase + tx * 4;
    if (c < NOUT) {
        float4 bb = make_float4(0.f, 0.f, 0.f, 0.f);
        if (bias) bb = *(const float4*)(bias + c);
        auto act = [](float v) { return RELU ? fmaxf(v, 0.f) : v; };
#pragma unroll
        for (int p = 0; p < 4; p++) {
            float2 q0 = unpack2(acc[p][0]);
            float2 q1 = unpack2(acc[p][1]);
            float2 q2 = unpack2(acc[p][2]);
            float2 q3 = unpack2(acc[p][3]);
            int r0 = rbase + ty * 8 + 2 * p;
            if (r0 < R) {
                float4 o;
                o.x = act(q0.x + bb.x);
                o.y = act(q1.x + bb.y);
                o.z = act(q2.x + bb.z);
                o.w = act(q3.x + bb.w);
                *(float4*)(C + (size_t)r0 * NOUT + c) = o;
            }
            if (r0 + 1 < R) {
                float4 o;
                o.x = act(q0.y + bb.x);
                o.y = act(q1.y + bb.y);
                o.z = act(q2.y + bb.z);
                o.w = act(q3.y + bb.w);
                *(float4*)(C + (size_t)(r0 + 1) * NOUT + c) = o;
            }
        }
    }
}

// ---------------- merged aggregation (pn + pe in one launch) ----------------
// grid (NN/4, BBc, 2), block 128. z=0: node mean; z=1: edge prefix mean.
__global__ void agg_kernel() {
    const int w    = threadIdx.x >> 5;
    const int lane = threadIdx.x & 31;
    const int i    = blockIdx.x * 4 + w;
    const int b    = blockIdx.y;
    if (blockIdx.z == 0) {
        const int t  = min(i, 32);
        const int k0 = group_start(i);
        float4 s = make_float4(0.f, 0.f, 0.f, 0.f);
        const float* src = g_hn + ((size_t)(b * NEg + k0)) * 128 + lane * 4;
        for (int l = 0; l < t; l++) {
            float4 v = *(const float4*)src;
            s = add4(s, v);
            src += 128;
        }
        const float nrm = 1.f / (float)max(t, 1);
        s.x *= nrm; s.y *= nrm; s.z *= nrm; s.w *= nrm;
        *(float4*)(g_pn + ((size_t)(b * NN + i)) * 128 + lane * 4) = s;
    } else {
        if (i == 0) return;
        const int t  = min(i, 32);
        const int k0 = group_start(i);
        float2 run = make_float2(0.f, 0.f);
        size_t base = ((size_t)(b * NEg + k0)) * 64 + lane * 2;
        for (int l = 0; l < t; l++) {
            float nrm = (l > 0) ? (1.f / (float)l) : 1.f;
            *(float2*)(g_pe + base) = make_float2(run.x * nrm, run.y * nrm);
            float2 h = *(const float2*)(g_he + base);
            run.x += h.x; run.y += h.y;
            base += 64;
        }
    }
}

// ---------------- launch -----------------------------------------------------
extern "C" void kernel_launch(void* const* d_in, const int* in_sizes, int n_in,
                              void* d_out, int out_size) {
    const float* nodes = (const float*)d_in[0];
    const float* edges = (const float*)d_in[1];
    const float* Wan1  = (const float*)d_in[2];
    const float* ban1  = (const float*)d_in[3];
    const float* Wan2  = (const float*)d_in[4];
    const float* ban2  = (const float*)d_in[5];
    const float* Wln1  = (const float*)d_in[6];
    const float* bln1  = (const float*)d_in[7];
    const float* Wln2  = (const float*)d_in[8];
    const float* bln2  = (const float*)d_in[9];
    const float* Wae1  = (const float*)d_in[10];
    const float* bae1  = (const float*)d_in[11];
    const float* Wae2  = (const float*)d_in[12];
    const float* bae2  = (const float*)d_in[13];
    const float* Wle1  = (const float*)d_in[14];
    const float* ble1  = (const float*)d_in[15];
    const float* Wle2  = (const float*)d_in[16];
    const float* ble2  = (const float*)d_in[17];

    float* out_nodes = (float*)d_out;                         // [2,1024,64]
    float* out_edges = (float*)d_out + (size_t)BBc * NN * 64; // [2,NE,32]

    float *UVP, *E, *hn, *pn, *h3n, *he, *pe, *h3e, *WUVP;
    unsigned short *BheH, *BheL, *B3eH, *B3eL, *BoeH, *BoeL;
    cudaGetSymbolAddress((void**)&UVP, g_UVP);
    cudaGetSymbolAddress((void**)&E,   g_E);
    cudaGetSymbolAddress((void**)&hn,  g_hn);
    cudaGetSymbolAddress((void**)&pn,  g_pn);
    cudaGetSymbolAddress((void**)&h3n, g_h3n);
    cudaGetSymbolAddress((void**)&he,  g_he);
    cudaGetSymbolAddress((void**)&pe,  g_pe);
    cudaGetSymbolAddress((void**)&h3e, g_h3e);
    cudaGetSymbolAddress((void**)&WUVP, g_WUVP);
    cudaGetSymbolAddress((void**)&BheH, g_BheH);
    cudaGetSymbolAddress((void**)&BheL, g_BheL);
    cudaGetSymbolAddress((void**)&B3eH, g_B3eH);
    cudaGetSymbolAddress((void**)&B3eL, g_B3eL);
    cudaGetSymbolAddress((void**)&BoeH, g_BoeH);
    cudaGetSymbolAddress((void**)&BoeL, g_BoeL);

    const int gbE = (RE + 127) / 128;    // 504 row tiles of 128 edge rows
    const int gbN = (RN + 127) / 128;    // 16 row tiles for node rows

    // all weight prep + edge index build in ONE launch
    prep_kernel<<<(SEG8 + 255) / 256, 256>>>(Wan1, Wan2, Wae1, Wae2,
                                             Wle1, Wle2, ban1, bae1);

    // per-node precompute: UVP = nodes @ [Wan1[0:64] | Wan1[96:160] | Wae1[0:64]]
    gemm_bias_relu<64, 640, 0, false><<<dim3(10, gbN), 256>>>(
        nodes, WUVP, 640, nullptr, UVP, RN, nullptr, nullptr);

    // per-edge first-layer parts (E1|E2), A-resident N-tile loop
    e_mma_kernel<<<gbE, 256>>>(edges, E);

    // big L2 GEMMs (both branches), then merged aggregation
    hn_mma_kernel<<<gbE, 512>>>(E, UVP, ban2, hn);
    mma_gemm<128, 4, 2, 1, true><<<dim3(gbE, 1), 256>>>(
        E + 256, 384, UVP + 512, 640, BheH, BheL, bae2, he, 64, RE);
    agg_kernel<<<dim3(NN / 4, BBc, 2), 128>>>();

    // node tail
    gemm_bias_relu<192, 192, 3, true><<<dim3(3, gbN), 256>>>(
        nullptr, Wln1, 192, bln1, h3n, RN, pn, nodes);
    gemm_bias_relu<192, 64, 0, true><<<dim3(1, gbN), 256>>>(
        h3n, Wln2, 64, bln2, out_nodes, RN, nullptr, nullptr);

    // edge tail
    mma_gemm<96, 4, 3, 2, true><<<dim3(gbE, 1), 384>>>(
        pe, 64, edges, 32, B3eH, B3eL, ble1, h3e, 96, RE);
    mma_gemm<96, 8, 1, 0, true><<<dim3((RE + 255) / 256, 1), 256>>>(
        h3e, 96, nullptr, 0, BoeH, BoeL, ble2, out_edges, 32, RE);
}

// round 14
// speedup vs baseline: 4.0559x; 1.0075x over previous
#include <cuda_runtime.h>
#include <cuda_bf16.h>
#include <math.h>
#include <stdint.h>

// Problem constants (match the reference's _build_indices(N=1024, M=32))
#define NN   1024
#define MMW  32
#define NEg  32240          // total edges
#define BBc  2
#define RE   (BBc*NEg)      // 64480 edge rows
#define RN   (BBc*NN)       // 2048 node rows

// ---------------- scratch (static device globals; no runtime allocs) -------
__device__ int2  g_eij[NEg];              // (i=target, j=source) per edge
__device__ float g_UVP[(size_t)RN*640];   // [U(256) | V(256) | P(128)] per node row
__device__ float g_E  [(size_t)RE*384];   // [E1(256) | E2(128)] per edge row (raw)
__device__ float g_hn [(size_t)RE*128];
__device__ float g_pn [(size_t)RN*128];
__device__ float g_h3n[(size_t)RN*192];
__device__ float g_he [(size_t)RE*64];
__device__ float g_pe [(size_t)RE*64];
__device__ float g_h3e[(size_t)RE*96];
// combined fp32 weight for UVP precompute: [64][640]
__device__ float g_WUVP[64*640];
// bf16 hi/lo splits of weights, stored as B[n][k] (transposed)
__device__ unsigned short g_Bhi  [128*256];   // Wan2
__device__ unsigned short g_Blo  [128*256];
__device__ unsigned short g_BheH [64*128];    // Wae2
__device__ unsigned short g_BheL [64*128];
__device__ unsigned short g_B3eH [96*96];     // Wle1
__device__ unsigned short g_B3eL [96*96];
__device__ unsigned short g_BoeH [32*96];     // Wle2
__device__ unsigned short g_BoeL [32*96];
__device__ unsigned short g_BeH  [384*32];    // [Wan1[64:96] | Wae1[64:96]]
__device__ unsigned short g_BeL  [384*32];
__device__ float g_bE[384];                   // [ban1 | bae1]

// ---------------- f32x2 packed-FMA helpers ----------------------------------
__device__ __forceinline__ void ffma2(unsigned long long& d,
                                      unsigned long long a,
                                      unsigned long long b) {
    asm("fma.rn.f32x2 %0, %1, %2, %0;" : "+l"(d) : "l"(a), "l"(b));
}
__device__ __forceinline__ unsigned long long bcast2(float x) {
    unsigned long long r;
    asm("mov.b64 %0, {%1, %1};" : "=l"(r) : "f"(x));
    return r;
}
__device__ __forceinline__ float2 unpack2(unsigned long long v) {
    float2 f;
    asm("mov.b64 {%0, %1}, %2;" : "=f"(f.x), "=f"(f.y) : "l"(v));
    return f;
}

// ---------------- mma.sync helpers ------------------------------------------
__device__ __forceinline__ uint32_t smem_u32(const void* p) {
    uint32_t a;
    asm("{ .reg .u64 t; cvta.to.shared.u64 t, %1; cvt.u32.u64 %0, t; }"
        : "=r"(a) : "l"(p));
    return a;
}
__device__ __forceinline__ void ldsm_x4(uint32_t& r0, uint32_t& r1,
                                        uint32_t& r2, uint32_t& r3,
                                        uint32_t addr) {
    asm volatile("ldmatrix.sync.aligned.m8n8.x4.shared.b16 {%0,%1,%2,%3}, [%4];"
                 : "=r"(r0), "=r"(r1), "=r"(r2), "=r"(r3) : "r"(addr));
}
__device__ __forceinline__ void mma_bf16(float& c0, float& c1, float& c2, float& c3,
                                         uint32_t a0, uint32_t a1, uint32_t a2, uint32_t a3,
                                         uint32_t b0, uint32_t b1) {
    asm volatile("mma.sync.aligned.m16n8k16.row.col.f32.bf16.bf16.f32 "
                 "{%0,%1,%2,%3}, {%4,%5,%6,%7}, {%8,%9}, {%0,%1,%2,%3};"
                 : "+f"(c0), "+f"(c1), "+f"(c2), "+f"(c3)
                 : "r"(a0), "r"(a1), "r"(a2), "r"(a3), "r"(b0), "r"(b1));
}

static __device__ __forceinline__ unsigned short bf16_bits(__nv_bfloat16 h) {
    return *reinterpret_cast<unsigned short*>(&h);
}
__device__ __forceinline__ void split_pack8(const float* vals,
                                            uint32_t* hp, uint32_t* lp) {
#pragma unroll
    for (int q = 0; q < 4; q++) {
        __nv_bfloat16 h0 = __float2bfloat16(vals[2 * q]);
        __nv_bfloat16 h1 = __float2bfloat16(vals[2 * q + 1]);
        float r0 = vals[2 * q]     - __bfloat162float(h0);
        float r1 = vals[2 * q + 1] - __bfloat162float(h1);
        __nv_bfloat16 l0 = __float2bfloat16(r0);
        __nv_bfloat16 l1 = __float2bfloat16(r1);
        hp[q] = (uint32_t)bf16_bits(h0) | ((uint32_t)bf16_bits(h1) << 16);
        lp[q] = (uint32_t)bf16_bits(l0) | ((uint32_t)bf16_bits(l1) << 16);
    }
}

__device__ __forceinline__ int group_start(int i) {
    return (i <= 32) ? (i * (i - 1) / 2) : (496 + (i - 32) * 32);
}

__device__ __forceinline__ float4 relu4(float4 v) {
    v.x = fmaxf(v.x, 0.f); v.y = fmaxf(v.y, 0.f);
    v.z = fmaxf(v.z, 0.f); v.w = fmaxf(v.w, 0.f);
    return v;
}
__device__ __forceinline__ float4 add4(float4 a, float4 b) {
    return make_float4(a.x + b.x, a.y + b.y, a.z + b.z, a.w + b.w);
}

// ---------------- all prep in one launch (weights + edge indices) -----------
__device__ __forceinline__ void split_store(float w, unsigned short* hi,
                                            unsigned short* lo, size_t o) {
    __nv_bfloat16 h = __float2bfloat16(w);
    float rem = w - __bfloat162float(h);
    hi[o] = bf16_bits(h);
    lo[o] = bf16_bits(__float2bfloat16(rem));
}
#define SEG0 32768                 // Wan2 -> g_Bhi/Blo
#define SEG1 (SEG0 + 8192)         // Wae2
#define SEG2 (SEG1 + 9216)         // Wle1
#define SEG3 (SEG2 + 3072)         // Wle2
#define SEG4 (SEG3 + 8192)         // Wan1[64:96] -> g_Be[0:256]
#define SEG5 (SEG4 + 4096)         // Wae1[64:96] -> g_Be[256:384]
#define SEG6 (SEG5 + 40960)        // g_WUVP
#define SEG7 (SEG6 + 384)          // g_bE
#define SEG8 (SEG7 + NEg)          // eij build
__global__ void prep_kernel(const float* __restrict__ Wan1,
                            const float* __restrict__ Wan2,
                            const float* __restrict__ Wae1,
                            const float* __restrict__ Wae2,
                            const float* __restrict__ Wle1,
                            const float* __restrict__ Wle2,
                            const float* __restrict__ ban1,
                            const float* __restrict__ bae1) {
    int idx = blockIdx.x * blockDim.x + threadIdx.x;
    if (idx < SEG0) {                          // Wan2 [256][128]
        int k = idx >> 7, n = idx & 127;
        split_store(Wan2[idx], g_Bhi, g_Blo, (size_t)n * 256 + k);
    } else if (idx < SEG1) {                   // Wae2 [128][64]
        int t = idx - SEG0;
        int k = t >> 6, n = t & 63;
        split_store(Wae2[t], g_BheH, g_BheL, (size_t)n * 128 + k);
    } else if (idx < SEG2) {                   // Wle1 [96][96]
        int t = idx - SEG1;
        int k = t / 96, n = t % 96;
        split_store(Wle1[t], g_B3eH, g_B3eL, (size_t)n * 96 + k);
    } else if (idx < SEG3) {                   // Wle2 [96][32]
        int t = idx - SEG2;
        int k = t >> 5, n = t & 31;
        split_store(Wle2[t], g_BoeH, g_BoeL, (size_t)n * 96 + k);
    } else if (idx < SEG4) {                   // Wan1 rows 64..95 -> g_Be n<256
        int t = idx - SEG3;
        int k = t >> 8, n = t & 255;
        split_store(Wan1[(size_t)(64 + k) * 256 + n], g_BeH, g_BeL,
                    (size_t)n * 32 + k);
    } else if (idx < SEG5) {                   // Wae1 rows 64..95 -> g_Be n 256..383
        int t = idx - SEG4;
        int k = t >> 7, n = t & 127;
        split_store(Wae1[(size_t)(64 + k) * 128 + n], g_BeH, g_BeL,
                    (size_t)(256 + n) * 32 + k);
    } else if (idx < SEG6) {                   // g_WUVP [64][640]
        int t = idx - SEG5;
        int k = t / 640, n = t % 640;
        float w;
        if (n < 256)      w = Wan1[(size_t)k * 256 + n];
        else if (n < 512) w = Wan1[(size_t)(96 + k) * 256 + (n - 256)];
        else              w = Wae1[(size_t)k * 128 + (n - 512)];
        g_WUVP[t] = w;
    } else if (idx < SEG7) {                   // g_bE
        int n = idx - SEG6;
        g_bE[n] = (n < 256) ? ban1[n] : bae1[n - 256];
    } else if (idx < SEG8) {                   // edge (i,j) build
        int e = idx - SEG7;
        int i, j;
        if (e < 496) {
            i = (int)((1.0f + sqrtf(8.0f * (float)e + 1.0f)) * 0.5f);
            while (i * (i - 1) / 2 > e) i--;
            while ((i + 1) * i / 2 <= e) i++;
            j = e - i * (i - 1) / 2;
        } else {
            int q = (e - 496) >> 5;
            i = 32 + q;
            j = (i - 32) + ((e - 496) & 31);
        }
        g_eij[e] = make_int2(i, j);
    }
}

#define A_STRIDE 40          // bf16 elems per row (80 B)

// ---------------- E kernel: E[r][0:384] = edges[r] @ [W|W] + [b|b] ----------
__global__ __launch_bounds__(256, 2)
void e_mma_kernel(const float* __restrict__ edges, float* __restrict__ C)
{
    __shared__ __align__(16) unsigned short sAhi[128 * A_STRIDE];
    __shared__ __align__(16) unsigned short sAlo[128 * A_STRIDE];
    __shared__ __align__(16) unsigned short sBhi[2][64 * A_STRIDE];
    __shared__ __align__(16) unsigned short sBlo[2][64 * A_STRIDE];

    const int tid  = threadIdx.x;
    const int wid  = tid >> 5;
    const int lane = tid & 31;
    const int warp_m = wid & 3;          // 4 row groups
    const int warp_n = wid >> 2;         // 2 col groups of 32
    const int rbase  = blockIdx.x * 128;

    // ---- A load + split (2 segments per thread) ----
#pragma unroll
    for (int s = 0; s < 2; s++) {
        int idx = tid + s * 256;
        int row = idx >> 2;
        int lk  = (idx & 3) * 8;
        int r   = rbase + row;
        float vals[8];
        if (r < RE) {
            float4 v0 = *(const float4*)(edges + (size_t)r * 32 + lk);
            float4 v1 = *(const float4*)(edges + (size_t)r * 32 + lk + 4);
            vals[0] = v0.x; vals[1] = v0.y; vals[2] = v0.z; vals[3] = v0.w;
            vals[4] = v1.x; vals[5] = v1.y; vals[6] = v1.z; vals[7] = v1.w;
        } else {
#pragma unroll
            for (int q = 0; q < 8; q++) vals[q] = 0.f;
        }
        uint32_t hp[4], lp[4];
        split_pack8(vals, hp, lp);
        uint32_t off = (uint32_t)(row * A_STRIDE + lk) * 2;
        *(uint4*)((char*)sAhi + off) = make_uint4(hp[0], hp[1], hp[2], hp[3]);
        *(uint4*)((char*)sAlo + off) = make_uint4(lp[0], lp[1], lp[2], lp[3]);
    }

    // ---- B tile 0 load ----
    const int bnl = tid >> 2;            // 0..63
    const int bkk = (tid & 3) * 8;
    uint4 bsh, bsl;
    auto ldgB = [&](int nt) {
        int n = nt * 64 + bnl;
        bsh = *(const uint4*)(g_BeH + (size_t)n * 32 + bkk);
        bsl = *(const uint4*)(g_BeL + (size_t)n * 32 + bkk);
    };
    auto stsB = [&](int buf) {
        uint32_t off = (uint32_t)(bnl * A_STRIDE + bkk) * 2;
        *(uint4*)((char*)sBhi[buf] + off) = bsh;
        *(uint4*)((char*)sBlo[buf] + off) = bsl;
    };
    ldgB(0);
    stsB(0);
    __syncthreads();

    // ---- hoisted A fragments ----
    const uint32_t sb_ahi = smem_u32(sAhi);
    const uint32_t sb_alo = smem_u32(sAlo);
    const int a_m    = warp_m * 32 + (lane & 7) + ((lane >> 3) & 1) * 8;
    const int a_koff = (lane >> 4) * 8;
    uint32_t ahi[2][2][4], alo[2][2][4];
#pragma unroll
    for (int ks = 0; ks < 2; ks++)
#pragma unroll
        for (int mt = 0; mt < 2; mt++) {
            uint32_t ad = sb_ahi +
                (uint32_t)((a_m + mt * 16) * (A_STRIDE * 2) +
                           (ks * 16 + a_koff) * 2);
            ldsm_x4(ahi[ks][mt][0], ahi[ks][mt][1], ahi[ks][mt][2], ahi[ks][mt][3], ad);
            ldsm_x4(alo[ks][mt][0], alo[ks][mt][1], alo[ks][mt][2], alo[ks][mt][3],
                    ad + (sb_alo - sb_ahi));
        }

    const int b_n    = warp_n * 32 + (lane & 7) + (lane >> 4) * 8;
    const int b_koff = ((lane >> 3) & 1) * 8;
    const int lq = lane & 3;
    const int lr = lane >> 2;

#pragma unroll 1
    for (int nt = 0; nt < 6; nt++) {
        const int cur = nt & 1;
        if (nt < 5) ldgB(nt + 1);

        const uint32_t sb_bhi = smem_u32(sBhi[cur]);
        const uint32_t sb_blo = smem_u32(sBlo[cur]);
        uint32_t bhi[2][4][2], blo[2][4][2];
#pragma unroll
        for (int ks = 0; ks < 2; ks++)
#pragma unroll
            for (int p = 0; p < 2; p++) {
                uint32_t bd = sb_bhi +
                    (uint32_t)((b_n + p * 16) * (A_STRIDE * 2) +
                               (ks * 16 + b_koff) * 2);
                ldsm_x4(bhi[ks][2 * p][0], bhi[ks][2 * p][1],
                        bhi[ks][2 * p + 1][0], bhi[ks][2 * p + 1][1], bd);
                ldsm_x4(blo[ks][2 * p][0], blo[ks][2 * p][1],
                        blo[ks][2 * p + 1][0], blo[ks][2 * p + 1][1],
                        bd + (sb_blo - sb_bhi));
            }

        float acc[2][4][4];
#pragma unroll
        for (int mt = 0; mt < 2; mt++)
#pragma unroll
            for (int n8 = 0; n8 < 4; n8++)
#pragma unroll
                for (int q = 0; q < 4; q++) acc[mt][n8][q] = 0.f;

#pragma unroll
        for (int ks = 0; ks < 2; ks++)
#pragma unroll
            for (int mt = 0; mt < 2; mt++)
#pragma unroll
                for (int n8 = 0; n8 < 4; n8++) {
                    float* d = acc[mt][n8];
                    mma_bf16(d[0], d[1], d[2], d[3],
                             ahi[ks][mt][0], ahi[ks][mt][1], ahi[ks][mt][2], ahi[ks][mt][3],
                             bhi[ks][n8][0], bhi[ks][n8][1]);
                    mma_bf16(d[0], d[1], d[2], d[3],
                             ahi[ks][mt][0], ahi[ks][mt][1], ahi[ks][mt][2], ahi[ks][mt][3],
                             blo[ks][n8][0], blo[ks][n8][1]);
                    mma_bf16(d[0], d[1], d[2], d[3],
                             alo[ks][mt][0], alo[ks][mt][1], alo[ks][mt][2], alo[ks][mt][3],
                             bhi[ks][n8][0], bhi[ks][n8][1]);
                }

#pragma unroll
        for (int mt = 0; mt < 2; mt++) {
            int m0 = rbase + warp_m * 32 + mt * 16 + lr;
#pragma unroll
            for (int n8 = 0; n8 < 4; n8++) {
                int cc = nt * 64 + warp_n * 32 + n8 * 8 + lq * 2;
                float2 bb = *(const float2*)(g_bE + cc);
                if (m0 < RE) {
                    float2 o;
                    o.x = acc[mt][n8][0] + bb.x;
                    o.y = acc[mt][n8][1] + bb.y;
                    *(float2*)(C + (size_t)m0 * 384 + cc) = o;
                }
                if (m0 + 8 < RE) {
                    float2 o;
                    o.x = acc[mt][n8][2] + bb.x;
                    o.y = acc[mt][n8][3] + bb.y;
                    *(float2*)(C + (size_t)(m0 + 8) * 384 + cc) = o;
                }
            }
        }

        if (nt < 5) stsB(1 - cur);
        __syncthreads();
    }
}

// ---------------- generalized N-tiled mma.sync bf16x3 GEMM ------------------
// MMODE 0: A row = X0 + r*ld0
// MMODE 1: A[k] = relu(X0[r*ld0+k] + X1[(b*NN+j)*ld1+k])
// MMODE 2: A = X0[r*ld0](64) ++ X1[r*ld1](32)
// MMODE 3: A[k] = relu(X0[r*ld0+k] + X1[(b*NN+j)*ld1+k] + X1[(b*NN+i)*ld1+256+k])
template<int K, int WM, int WN, int MMODE, bool RELU>
__global__ __launch_bounds__(WM * WN * 32)
void mma_gemm(const float* __restrict__ X0, int ld0,
              const float* __restrict__ X1, int ld1,
              const unsigned short* __restrict__ Bhi,
              const unsigned short* __restrict__ Blo,
              const float* __restrict__ bias,
              float* __restrict__ C, int ldC, int R)
{
    constexpr int MT  = WM * 32;
    constexpr int NB  = WN * 32;
    constexpr int NTH = WM * WN * 32;
    __shared__ __align__(16) unsigned short sAhi[MT * A_STRIDE];
    __shared__ __align__(16) unsigned short sAlo[MT * A_STRIDE];
    __shared__ __align__(16) unsigned short sBhi[NB * A_STRIDE];
    __shared__ __align__(16) unsigned short sBlo[NB * A_STRIDE];

    const int tid  = threadIdx.x;
    const int wid  = tid >> 5;
    const int lane = tid & 31;
    const int warp_m = wid % WM;
    const int warp_n = wid / WM;
    const int rbase = blockIdx.x * MT;
    const int cbase = blockIdx.y * NB;

    float acc[2][4][4];
#pragma unroll
    for (int mt = 0; mt < 2; mt++)
#pragma unroll
        for (int nt = 0; nt < 4; nt++)
#pragma unroll
            for (int q = 0; q < 4; q++) acc[mt][nt][q] = 0.f;

    const int a_m    = warp_m * 32 + (lane & 7) + ((lane >> 3) & 1) * 8;
    const int a_koff = (lane >> 4) * 8;
    const int b_n    = warp_n * 32 + (lane & 7) + (lane >> 4) * 8;
    const int b_koff = ((lane >> 3) & 1) * 8;

    const uint32_t sb_ahi = smem_u32(sAhi);
    const uint32_t sb_alo = smem_u32(sAlo);
    const uint32_t sb_bhi = smem_u32(sBhi);
    const uint32_t sb_blo = smem_u32(sBlo);

#pragma unroll 1
    for (int c = 0; c < K / 32; c++) {
        const int k0 = c * 32;
        // ---- A loader ----
        for (int idx = tid; idx < MT * 4; idx += NTH) {
            const int row = idx >> 2;
            const int lk  = (idx & 3) * 8;
            const int r   = rbase + row;
            const int kb  = k0 + lk;
            float vals[8];
            if (r < R) {
                if (MMODE == 0) {
                    float4 v0 = *(const float4*)(X0 + (size_t)r * ld0 + kb);
                    float4 v1 = *(const float4*)(X0 + (size_t)r * ld0 + kb + 4);
                    vals[0] = v0.x; vals[1] = v0.y; vals[2] = v0.z; vals[3] = v0.w;
                    vals[4] = v1.x; vals[5] = v1.y; vals[6] = v1.z; vals[7] = v1.w;
                } else if (MMODE == 1) {
                    int b = (r >= NEg) ? 1 : 0;
                    int e = r - b * NEg;
                    int2 ij = g_eij[e];
                    const float* pa = X0 + (size_t)r * ld0 + kb;
                    const float* pb = X1 + ((size_t)(b * NN + ij.y)) * ld1 + kb;
                    float4 s0 = relu4(add4(*(const float4*)pa,
                                           *(const float4*)pb));
                    float4 s1 = relu4(add4(*(const float4*)(pa + 4),
                                           *(const float4*)(pb + 4)));
                    vals[0] = s0.x; vals[1] = s0.y; vals[2] = s0.z; vals[3] = s0.w;
                    vals[4] = s1.x; vals[5] = s1.y; vals[6] = s1.z; vals[7] = s1.w;
                } else if (MMODE == 2) { // X0(64) ++ X1(32)
                    const float* s = (kb < 64) ? (X0 + (size_t)r * ld0 + kb)
                                               : (X1 + (size_t)r * ld1 + kb - 64);
                    float4 v0 = *(const float4*)s;
                    float4 v1 = *(const float4*)(s + 4);
                    vals[0] = v0.x; vals[1] = v0.y; vals[2] = v0.z; vals[3] = v0.w;
                    vals[4] = v1.x; vals[5] = v1.y; vals[6] = v1.z; vals[7] = v1.w;
                } else { // MMODE 3: relu(E1 + U[j] + V[i])
                    int b = (r >= NEg) ? 1 : 0;
                    int e = r - b * NEg;
                    int2 ij = g_eij[e];
                    const float* pa = X0 + (size_t)r * ld0 + kb;
                    const float* pu = X1 + ((size_t)(b * NN + ij.y)) * ld1 + kb;
                    const float* pv = X1 + ((size_t)(b * NN + ij.x)) * ld1 + 256 + kb;
                    float4 s0 = relu4(add4(add4(*(const float4*)pa,
                                                *(const float4*)pu),
                                           *(const float4*)pv));
                    float4 s1 = relu4(add4(add4(*(const float4*)(pa + 4),
                                                *(const float4*)(pu + 4)),
                                           *(const float4*)(pv + 4)));
                    vals[0] = s0.x; vals[1] = s0.y; vals[2] = s0.z; vals[3] = s0.w;
                    vals[4] = s1.x; vals[5] = s1.y; vals[6] = s1.z; vals[7] = s1.w;
                }
            } else {
#pragma unroll
                for (int q = 0; q < 8; q++) vals[q] = 0.f;
            }
            uint32_t hp[4], lp[4];
            split_pack8(vals, hp, lp);
            uint32_t off = (uint32_t)(row * A_STRIDE + lk) * 2;
            *(uint4*)((char*)sAhi + off) = make_uint4(hp[0], hp[1], hp[2], hp[3]);
            *(uint4*)((char*)sAlo + off) = make_uint4(lp[0], lp[1], lp[2], lp[3]);
        }
        // ---- B loader ----
        for (int idx = tid; idx < NB * 4; idx += NTH) {
            const int n  = idx >> 2;
            const int lk = (idx & 3) * 8;
            uint4 hv = *(const uint4*)(Bhi + (size_t)(cbase + n) * K + k0 + lk);
            uint4 lv = *(const uint4*)(Blo + (size_t)(cbase + n) * K + k0 + lk);
            uint32_t off = (uint32_t)(n * A_STRIDE + lk) * 2;
            *(uint4*)((char*)sBhi + off) = hv;
            *(uint4*)((char*)sBlo + off) = lv;
        }
        __syncthreads();

#pragma unroll
        for (int ks = 0; ks < 2; ks++) {
            uint32_t ahi[2][4], alo[2][4];
#pragma unroll
            for (int mt = 0; mt < 2; mt++) {
                uint32_t ad = sb_ahi +
                    (uint32_t)((a_m + mt * 16) * (A_STRIDE * 2) +
                               (ks * 16 + a_koff) * 2);
                ldsm_x4(ahi[mt][0], ahi[mt][1], ahi[mt][2], ahi[mt][3], ad);
                ldsm_x4(alo[mt][0], alo[mt][1], alo[mt][2], alo[mt][3],
                        ad + (sb_alo - sb_ahi));
            }
            uint32_t bhi[4][2], blo[4][2];
#pragma unroll
            for (int p = 0; p < 2; p++) {
                uint32_t bd = sb_bhi +
                    (uint32_t)((b_n + p * 16) * (A_STRIDE * 2) +
                               (ks * 16 + b_koff) * 2);
                ldsm_x4(bhi[2 * p][0], bhi[2 * p][1],
                        bhi[2 * p + 1][0], bhi[2 * p + 1][1], bd);
                ldsm_x4(blo[2 * p][0], blo[2 * p][1],
                        blo[2 * p + 1][0], blo[2 * p + 1][1],
                        bd + (sb_blo - sb_bhi));
            }
#pragma unroll
            for (int mt = 0; mt < 2; mt++)
#pragma unroll
                for (int nt = 0; nt < 4; nt++) {
                    float* d = acc[mt][nt];
                    mma_bf16(d[0], d[1], d[2], d[3],
                             ahi[mt][0], ahi[mt][1], ahi[mt][2], ahi[mt][3],
                             bhi[nt][0], bhi[nt][1]);
                    mma_bf16(d[0], d[1], d[2], d[3],
                             ahi[mt][0], ahi[mt][1], ahi[mt][2], ahi[mt][3],
                             blo[nt][0], blo[nt][1]);
                    mma_bf16(d[0], d[1], d[2], d[3],
                             alo[mt][0], alo[mt][1], alo[mt][2], alo[mt][3],
                             bhi[nt][0], bhi[nt][1]);
                }
        }
        __syncthreads();
    }

    // ---- epilogue ----
    const int lq = lane & 3;
    const int lr = lane >> 2;
#pragma unroll
    for (int mt = 0; mt < 2; mt++) {
        int m0 = rbase + warp_m * 32 + mt * 16 + lr;
#pragma unroll
        for (int nt = 0; nt < 4; nt++) {
            int cc = cbase + warp_n * 32 + nt * 8 + lq * 2;
            float2 bb = *(const float2*)(bias + cc);
            auto act = [](float v) { return RELU ? fmaxf(v, 0.f) : v; };
            if (m0 < R) {
                float2 o;
                o.x = act(acc[mt][nt][0] + bb.x);
                o.y = act(acc[mt][nt][1] + bb.y);
                *(float2*)(C + (size_t)m0 * ldC + cc) = o;
            }
            if (m0 + 8 < R) {
                float2 o;
                o.x = act(acc[mt][nt][2] + bb.x);
                o.y = act(acc[mt][nt][3] + bb.y);
                *(float2*)(C + (size_t)(m0 + 8) * ldC + cc) = o;
            }
        }
    }
}

// ---------------- FFMA2 GEMM (node-side small work) --------------------------
// MODE 0: A plain [R x K];  MODE 3: A = X0[r](128) ++ X1[r](64)  (K=192)
template<int K, int NOUT, int MODE, bool RELU>
__global__ __launch_bounds__(256, 2)
void gemm_bias_relu(const float* __restrict__ A,
                    const float* __restrict__ W, int ldW,
                    const float* __restrict__ bias,
                    float* __restrict__ C, int R,
                    const float* __restrict__ X0,
                    const float* __restrict__ X1)
{
    __shared__ __align__(16) float As[2][32][128];
    __shared__ __align__(16) float Bs[2][32][64];

    const int tid   = threadIdx.x;
    const int tx    = tid & 15;
    const int ty    = tid >> 4;
    const int rbase = blockIdx.y * 128;
    const int cbase = blockIdx.x * 64;

    const int lm = tid >> 1;
    const int lk = (tid & 1) * 16;
    const int r  = rbase + lm;
    const bool rv = (r < R);

    const float* p0 = nullptr;
    const float* p1 = nullptr;
    if (rv) {
        if (MODE == 0) {
            p0 = A + (size_t)r * K;
        } else { // MODE 3
            p0 = X0 + (size_t)r * 128;
            p1 = X1 + (size_t)r * 64;
        }
    }

    const int bk = tid >> 4;
    const int bn = (tid & 15) * 4;
    const bool cv = (cbase + bn < NOUT);

    unsigned long long acc[4][4];
#pragma unroll
    for (int p = 0; p < 4; p++)
#pragma unroll
        for (int v = 0; v < 4; v++) acc[p][v] = 0ull;

    float4 apf[4];
    float4 bpf[2];

    auto loadA = [&](int k0) {
        const int kb = k0 + lk;
#pragma unroll
        for (int u = 0; u < 4; u++) apf[u] = make_float4(0.f, 0.f, 0.f, 0.f);
        if (!rv) return;
        if (MODE == 0) {
#pragma unroll
            for (int u = 0; u < 4; u++) apf[u] = *(const float4*)(p0 + kb + 4 * u);
        } else {
            const float* s = (kb < 128) ? (p0 + kb) : (p1 + kb - 128);
#pragma unroll
            for (int u = 0; u < 4; u++) apf[u] = *(const float4*)(s + 4 * u);
        }
    };
    auto loadB = [&](int k0) {
        bpf[0] = make_float4(0.f, 0.f, 0.f, 0.f);
        bpf[1] = make_float4(0.f, 0.f, 0.f, 0.f);
        if (cv) {
            bpf[0] = *(const float4*)(W + (size_t)(k0 + bk) * ldW + (cbase + bn));
            bpf[1] = *(const float4*)(W + (size_t)(k0 + bk + 16) * ldW + (cbase + bn));
        }
    };
    auto stsA = [&](int buf) {
#pragma unroll
        for (int u = 0; u < 4; u++) {
            As[buf][lk + 4 * u + 0][lm] = apf[u].x;
            As[buf][lk + 4 * u + 1][lm] = apf[u].y;
            As[buf][lk + 4 * u + 2][lm] = apf[u].z;
            As[buf][lk + 4 * u + 3][lm] = apf[u].w;
        }
    };
    auto stsB = [&](int buf) {
        *(float4*)&Bs[buf][bk][bn]      = bpf[0];
        *(float4*)&Bs[buf][bk + 16][bn] = bpf[1];
    };

    constexpr int NC = K / 32;
    loadA(0); loadB(0);
    stsA(0);  stsB(0);
    __syncthreads();

#pragma unroll
    for (int c = 0; c < NC; c++) {
        const int cur = c & 1;
        if (c + 1 < NC) { loadA((c + 1) * 32); loadB((c + 1) * 32); }

#pragma unroll
        for (int kk = 0; kk < 32; kk++) {
            float4 b4 = *(const float4*)&Bs[cur][kk][tx * 4];
            unsigned long long bx = bcast2(b4.x);
            unsigned long long by = bcast2(b4.y);
            unsigned long long bz = bcast2(b4.z);
            unsigned long long bw = bcast2(b4.w);
            ulonglong2 a01 = *(const ulonglong2*)&As[cur][kk][ty * 8];
            ulonglong2 a23 = *(const ulonglong2*)&As[cur][kk][ty * 8 + 4];
            ffma2(acc[0][0], a01.x, bx); ffma2(acc[0][1], a01.x, by);
            ffma2(acc[0][2], a01.x, bz); ffma2(acc[0][3], a01.x, bw);
            ffma2(acc[1][0], a01.y, bx); ffma2(acc[1][1], a01.y, by);
            ffma2(acc[1][2], a01.y, bz); ffma2(acc[1][3], a01.y, bw);
            ffma2(acc[2][0], a23.x, bx); ffma2(acc[2][1], a23.x, by);
            ffma2(acc[2][2], a23.x, bz); ffma2(acc[2][3], a23.x, bw);
            ffma2(acc[3][0], a23.y, bx); ffma2(acc[3][1], a23.y, by);
            ffma2(acc[3][2], a23.y, bz); ffma2(acc[3][3], a23.y, bw);
        }

        if (c + 1 < NC) { stsA(1 - cur); stsB(1 - cur); }
        __syncthreads();
    }

    const int c = cbase + tx * 4;
    if (c < NOUT) {
        float4 bb = make_float4(0.f, 0.f, 0.f, 0.f);
        if (bias) bb = *(const float4*)(bias + c);
        auto act = [](float v) { return RELU ? fmaxf(v, 0.f) : v; };
#pragma unroll
        for (int p = 0; p < 4; p++) {
            float2 q0 = unpack2(acc[p][0]);
            float2 q1 = unpack2(acc[p][1]);
            float2 q2 = unpack2(acc[p][2]);
            float2 q3 = unpack2(acc[p][3]);
            int r0 = rbase + ty * 8 + 2 * p;
            if (r0 < R) {
                float4 o;
                o.x = act(q0.x + bb.x);
                o.y = act(q1.x + bb.y);
                o.z = act(q2.x + bb.z);
                o.w = act(q3.x + bb.w);
                *(float4*)(C + (size_t)r0 * NOUT + c) = o;
            }
            if (r0 + 1 < R) {
                float4 o;
                o.x = act(q0.y + bb.x);
                o.y = act(q1.y + bb.y);
                o.z = act(q2.y + bb.z);
                o.w = act(q3.y + bb.w);
                *(float4*)(C + (size_t)(r0 + 1) * NOUT + c) = o;
            }
        }
    }
}

// ---------------- merged aggregation (pn + pe in one launch) ----------------
__global__ void agg_kernel() {
    const int w    = threadIdx.x >> 5;
    const int lane = threadIdx.x & 31;
    const int i    = blockIdx.x * 4 + w;
    const int b    = blockIdx.y;
    if (blockIdx.z == 0) {
        const int t  = min(i, 32);
        const int k0 = group_start(i);
        float4 s = make_float4(0.f, 0.f, 0.f, 0.f);
        const float* src = g_hn + ((size_t)(b * NEg + k0)) * 128 + lane * 4;
        for (int l = 0; l < t; l++) {
            float4 v = *(const float4*)src;
            s = add4(s, v);
            src += 128;
        }
        const float nrm = 1.f / (float)max(t, 1);
        s.x *= nrm; s.y *= nrm; s.z *= nrm; s.w *= nrm;
        *(float4*)(g_pn + ((size_t)(b * NN + i)) * 128 + lane * 4) = s;
    } else {
        if (i == 0) return;
        const int t  = min(i, 32);
        const int k0 = group_start(i);
        float2 run = make_float2(0.f, 0.f);
        size_t base = ((size_t)(b * NEg + k0)) * 64 + lane * 2;
        for (int l = 0; l < t; l++) {
            float nrm = (l > 0) ? (1.f / (float)l) : 1.f;
            *(float2*)(g_pe + base) = make_float2(run.x * nrm, run.y * nrm);
            float2 h = *(const float2*)(g_he + base);
            run.x += h.x; run.y += h.y;
            base += 64;
        }
    }
}

// ---------------- launch -----------------------------------------------------
extern "C" void kernel_launch(void* const* d_in, const int* in_sizes, int n_in,
                              void* d_out, int out_size) {
    const float* nodes = (const float*)d_in[0];
    const float* edges = (const float*)d_in[1];
    const float* Wan1  = (const float*)d_in[2];
    const float* ban1  = (const float*)d_in[3];
    const float* Wan2  = (const float*)d_in[4];
    const float* ban2  = (const float*)d_in[5];
    const float* Wln1  = (const float*)d_in[6];
    const float* bln1  = (const float*)d_in[7];
    const float* Wln2  = (const float*)d_in[8];
    const float* bln2  = (const float*)d_in[9];
    const float* Wae1  = (const float*)d_in[10];
    const float* bae1  = (const float*)d_in[11];
    const float* Wae2  = (const float*)d_in[12];
    const float* bae2  = (const float*)d_in[13];
    const float* Wle1  = (const float*)d_in[14];
    const float* ble1  = (const float*)d_in[15];
    const float* Wle2  = (const float*)d_in[16];
    const float* ble2  = (const float*)d_in[17];

    float* out_nodes = (float*)d_out;                         // [2,1024,64]
    float* out_edges = (float*)d_out + (size_t)BBc * NN * 64; // [2,NE,32]

    float *UVP, *E, *hn, *pn, *h3n, *he, *pe, *h3e, *WUVP;
    unsigned short *Bhi, *Blo, *BheH, *BheL, *B3eH, *B3eL, *BoeH, *BoeL;
    cudaGetSymbolAddress((void**)&UVP, g_UVP);
    cudaGetSymbolAddress((void**)&E,   g_E);
    cudaGetSymbolAddress((void**)&hn,  g_hn);
    cudaGetSymbolAddress((void**)&pn,  g_pn);
    cudaGetSymbolAddress((void**)&h3n, g_h3n);
    cudaGetSymbolAddress((void**)&he,  g_he);
    cudaGetSymbolAddress((void**)&pe,  g_pe);
    cudaGetSymbolAddress((void**)&h3e, g_h3e);
    cudaGetSymbolAddress((void**)&WUVP, g_WUVP);
    cudaGetSymbolAddress((void**)&Bhi, g_Bhi);
    cudaGetSymbolAddress((void**)&Blo, g_Blo);
    cudaGetSymbolAddress((void**)&BheH, g_BheH);
    cudaGetSymbolAddress((void**)&BheL, g_BheL);
    cudaGetSymbolAddress((void**)&B3eH, g_B3eH);
    cudaGetSymbolAddress((void**)&B3eL, g_B3eL);
    cudaGetSymbolAddress((void**)&BoeH, g_BoeH);
    cudaGetSymbolAddress((void**)&BoeL, g_BoeL);

    const int gbE  = (RE + 127) / 128;   // 504 tiles of 128 edge rows
    const int gbE2 = (RE + 63) / 64;     // 1008 tiles of 64 edge rows
    const int gbN  = (RN + 127) / 128;   // 16 row tiles for node rows

    // all weight prep + edge index build in ONE launch
    prep_kernel<<<(SEG8 + 255) / 256, 256>>>(Wan1, Wan2, Wae1, Wae2,
                                             Wle1, Wle2, ban1, bae1);

    // per-node precompute: UVP = nodes @ [Wan1[0:64] | Wan1[96:160] | Wae1[0:64]]
    gemm_bias_relu<64, 640, 0, false><<<dim3(10, gbN), 256>>>(
        nodes, WUVP, 640, nullptr, UVP, RN, nullptr, nullptr);

    // per-edge first-layer parts (E1|E2), A-resident N-tile loop
    e_mma_kernel<<<gbE, 256>>>(edges, E);

    // big L2 GEMMs: hn now MT=64, full N=128 (2+ blocks/SM)
    mma_gemm<256, 2, 4, 3, true><<<dim3(gbE2, 1), 256>>>(
        E, 384, UVP, 640, Bhi, Blo, ban2, hn, 128, RE);
    mma_gemm<128, 4, 2, 1, true><<<dim3(gbE, 1), 256>>>(
        E + 256, 384, UVP + 512, 640, BheH, BheL, bae2, he, 64, RE);
    agg_kernel<<<dim3(NN / 4, BBc, 2), 128>>>();

    // node tail
    gemm_bias_relu<192, 192, 3, true><<<dim3(3, gbN), 256>>>(
        nullptr, Wln1, 192, bln1, h3n, RN, pn, nodes);
    gemm_bias_relu<192, 64, 0, true><<<dim3(1, gbN), 256>>>(
        h3n, Wln2, 64, bln2, out_nodes, RN, nullptr, nullptr);

    // edge tail
    mma_gemm<96, 4, 3, 2, true><<<dim3(gbE, 1), 384>>>(
        pe, 64, edges, 32, B3eH, B3eL, ble1, h3e, 96, RE);
    mma_gemm<96, 8, 1, 0, true><<<dim3((RE + 255) / 256, 1), 256>>>(
        h3e, 96, nullptr, 0, BoeH, BoeL, ble2, out_edges, 32, RE);
}

// round 15
// speedup vs baseline: 4.3388x; 1.0698x over previous
#include <cuda_runtime.h>
#include <cuda_bf16.h>
#include <math.h>
#include <stdint.h>

// Problem constants (match the reference's _build_indices(N=1024, M=32))
#define NN   1024
#define MMW  32
#define NEg  32240          // total edges
#define BBc  2
#define RE   (BBc*NEg)      // 64480 edge rows
#define RN   (BBc*NN)       // 2048 node rows

// ---------------- scratch (static device globals; no runtime allocs) -------
__device__ int2  g_eij[NEg];              // (i=target, j=source) per edge
__device__ float g_UVP[(size_t)RN*640];   // [U(256) | V(256) | P(128)] per node row
__device__ float g_E  [(size_t)RE*384];   // [E1(256) | E2(128)] per edge row (raw)
__device__ float g_hn [(size_t)RE*128];
__device__ float g_pn [(size_t)RN*128];
__device__ float g_h3n[(size_t)RN*192];
__device__ float g_he [(size_t)RE*64];
__device__ float g_pe [(size_t)RE*64];
__device__ float g_h3e[(size_t)RE*96];
// combined fp32 weight for UVP precompute: [64][640]
__device__ float g_WUVP[64*640];
// bf16 hi/lo splits of weights, stored as B[n][k] (transposed)
__device__ unsigned short g_Bhi  [128*256];   // Wan2
__device__ unsigned short g_Blo  [128*256];
__device__ unsigned short g_BheH [64*128];    // Wae2
__device__ unsigned short g_BheL [64*128];
__device__ unsigned short g_B3eH [96*96];     // Wle1
__device__ unsigned short g_B3eL [96*96];
__device__ unsigned short g_BoeH [32*96];     // Wle2
__device__ unsigned short g_BoeL [32*96];
__device__ unsigned short g_BeH  [384*32];    // [Wan1[64:96] | Wae1[64:96]]
__device__ unsigned short g_BeL  [384*32];
__device__ float g_bE[384];                   // [ban1 | bae1]

// ---------------- f32x2 packed-FMA helpers ----------------------------------
__device__ __forceinline__ void ffma2(unsigned long long& d,
                                      unsigned long long a,
                                      unsigned long long b) {
    asm("fma.rn.f32x2 %0, %1, %2, %0;" : "+l"(d) : "l"(a), "l"(b));
}
__device__ __forceinline__ unsigned long long bcast2(float x) {
    unsigned long long r;
    asm("mov.b64 %0, {%1, %1};" : "=l"(r) : "f"(x));
    return r;
}
__device__ __forceinline__ float2 unpack2(unsigned long long v) {
    float2 f;
    asm("mov.b64 {%0, %1}, %2;" : "=f"(f.x), "=f"(f.y) : "l"(v));
    return f;
}

// ---------------- mma.sync helpers ------------------------------------------
__device__ __forceinline__ uint32_t smem_u32(const void* p) {
    uint32_t a;
    asm("{ .reg .u64 t; cvta.to.shared.u64 t, %1; cvt.u32.u64 %0, t; }"
        : "=r"(a) : "l"(p));
    return a;
}
__device__ __forceinline__ void ldsm_x4(uint32_t& r0, uint32_t& r1,
                                        uint32_t& r2, uint32_t& r3,
                                        uint32_t addr) {
    asm volatile("ldmatrix.sync.aligned.m8n8.x4.shared.b16 {%0,%1,%2,%3}, [%4];"
                 : "=r"(r0), "=r"(r1), "=r"(r2), "=r"(r3) : "r"(addr));
}
__device__ __forceinline__ void mma_bf16(float& c0, float& c1, float& c2, float& c3,
                                         uint32_t a0, uint32_t a1, uint32_t a2, uint32_t a3,
                                         uint32_t b0, uint32_t b1) {
    asm volatile("mma.sync.aligned.m16n8k16.row.col.f32.bf16.bf16.f32 "
                 "{%0,%1,%2,%3}, {%4,%5,%6,%7}, {%8,%9}, {%0,%1,%2,%3};"
                 : "+f"(c0), "+f"(c1), "+f"(c2), "+f"(c3)
                 : "r"(a0), "r"(a1), "r"(a2), "r"(a3), "r"(b0), "r"(b1));
}

static __device__ __forceinline__ unsigned short bf16_bits(__nv_bfloat16 h) {
    return *reinterpret_cast<unsigned short*>(&h);
}
__device__ __forceinline__ void split_pack8(const float* vals,
                                            uint32_t* hp, uint32_t* lp) {
#pragma unroll
    for (int q = 0; q < 4; q++) {
        __nv_bfloat16 h0 = __float2bfloat16(vals[2 * q]);
        __nv_bfloat16 h1 = __float2bfloat16(vals[2 * q + 1]);
        float r0 = vals[2 * q]     - __bfloat162float(h0);
        float r1 = vals[2 * q + 1] - __bfloat162float(h1);
        __nv_bfloat16 l0 = __float2bfloat16(r0);
        __nv_bfloat16 l1 = __float2bfloat16(r1);
        hp[q] = (uint32_t)bf16_bits(h0) | ((uint32_t)bf16_bits(h1) << 16);
        lp[q] = (uint32_t)bf16_bits(l0) | ((uint32_t)bf16_bits(l1) << 16);
    }
}

__device__ __forceinline__ int group_start(int i) {
    return (i <= 32) ? (i * (i - 1) / 2) : (496 + (i - 32) * 32);
}

__device__ __forceinline__ float4 relu4(float4 v) {
    v.x = fmaxf(v.x, 0.f); v.y = fmaxf(v.y, 0.f);
    v.z = fmaxf(v.z, 0.f); v.w = fmaxf(v.w, 0.f);
    return v;
}
__device__ __forceinline__ float4 add4(float4 a, float4 b) {
    return make_float4(a.x + b.x, a.y + b.y, a.z + b.z, a.w + b.w);
}

// ---------------- all prep in one launch (weights + edge indices) -----------
__device__ __forceinline__ void split_store(float w, unsigned short* hi,
                                            unsigned short* lo, size_t o) {
    __nv_bfloat16 h = __float2bfloat16(w);
    float rem = w - __bfloat162float(h);
    hi[o] = bf16_bits(h);
    lo[o] = bf16_bits(__float2bfloat16(rem));
}
#define SEG0 32768                 // Wan2 -> g_Bhi/Blo
#define SEG1 (SEG0 + 8192)         // Wae2
#define SEG2 (SEG1 + 9216)         // Wle1
#define SEG3 (SEG2 + 3072)         // Wle2
#define SEG4 (SEG3 + 8192)         // Wan1[64:96] -> g_Be[0:256]
#define SEG5 (SEG4 + 4096)         // Wae1[64:96] -> g_Be[256:384]
#define SEG6 (SEG5 + 40960)        // g_WUVP
#define SEG7 (SEG6 + 384)          // g_bE
#define SEG8 (SEG7 + NEg)          // eij build
__global__ void prep_kernel(const float* __restrict__ Wan1,
                            const float* __restrict__ Wan2,
                            const float* __restrict__ Wae1,
                            const float* __restrict__ Wae2,
                            const float* __restrict__ Wle1,
                            const float* __restrict__ Wle2,
                            const float* __restrict__ ban1,
                            const float* __restrict__ bae1) {
    int idx = blockIdx.x * blockDim.x + threadIdx.x;
    if (idx < SEG0) {                          // Wan2 [256][128]
        int k = idx >> 7, n = idx & 127;
        split_store(Wan2[idx], g_Bhi, g_Blo, (size_t)n * 256 + k);
    } else if (idx < SEG1) {                   // Wae2 [128][64]
        int t = idx - SEG0;
        int k = t >> 6, n = t & 63;
        split_store(Wae2[t], g_BheH, g_BheL, (size_t)n * 128 + k);
    } else if (idx < SEG2) {                   // Wle1 [96][96]
        int t = idx - SEG1;
        int k = t / 96, n = t % 96;
        split_store(Wle1[t], g_B3eH, g_B3eL, (size_t)n * 96 + k);
    } else if (idx < SEG3) {                   // Wle2 [96][32]
        int t = idx - SEG2;
        int k = t >> 5, n = t & 31;
        split_store(Wle2[t], g_BoeH, g_BoeL, (size_t)n * 96 + k);
    } else if (idx < SEG4) {                   // Wan1 rows 64..95 -> g_Be n<256
        int t = idx - SEG3;
        int k = t >> 8, n = t & 255;
        split_store(Wan1[(size_t)(64 + k) * 256 + n], g_BeH, g_BeL,
                    (size_t)n * 32 + k);
    } else if (idx < SEG5) {                   // Wae1 rows 64..95 -> g_Be n 256..383
        int t = idx - SEG4;
        int k = t >> 7, n = t & 127;
        split_store(Wae1[(size_t)(64 + k) * 128 + n], g_BeH, g_BeL,
                    (size_t)(256 + n) * 32 + k);
    } else if (idx < SEG6) {                   // g_WUVP [64][640]
        int t = idx - SEG5;
        int k = t / 640, n = t % 640;
        float w;
        if (n < 256)      w = Wan1[(size_t)k * 256 + n];
        else if (n < 512) w = Wan1[(size_t)(96 + k) * 256 + (n - 256)];
        else              w = Wae1[(size_t)k * 128 + (n - 512)];
        g_WUVP[t] = w;
    } else if (idx < SEG7) {                   // g_bE
        int n = idx - SEG6;
        g_bE[n] = (n < 256) ? ban1[n] : bae1[n - 256];
    } else if (idx < SEG8) {                   // edge (i,j) build
        int e = idx - SEG7;
        int i, j;
        if (e < 496) {
            i = (int)((1.0f + sqrtf(8.0f * (float)e + 1.0f)) * 0.5f);
            while (i * (i - 1) / 2 > e) i--;
            while ((i + 1) * i / 2 <= e) i++;
            j = e - i * (i - 1) / 2;
        } else {
            int q = (e - 496) >> 5;
            i = 32 + q;
            j = (i - 32) + ((e - 496) & 31);
        }
        g_eij[e] = make_int2(i, j);
    }
}

#define A_STRIDE 40          // bf16 elems per row (80 B)

// ---------------- E kernel: E[r][0:384] = edges[r] @ [W|W] + [b|b] ----------
__global__ __launch_bounds__(256, 2)
void e_mma_kernel(const float* __restrict__ edges, float* __restrict__ C)
{
    __shared__ __align__(16) unsigned short sAhi[128 * A_STRIDE];
    __shared__ __align__(16) unsigned short sAlo[128 * A_STRIDE];
    __shared__ __align__(16) unsigned short sBhi[2][64 * A_STRIDE];
    __shared__ __align__(16) unsigned short sBlo[2][64 * A_STRIDE];

    const int tid  = threadIdx.x;
    const int wid  = tid >> 5;
    const int lane = tid & 31;
    const int warp_m = wid & 3;          // 4 row groups
    const int warp_n = wid >> 2;         // 2 col groups of 32
    const int rbase  = blockIdx.x * 128;

    // ---- A load + split (2 segments per thread) ----
#pragma unroll
    for (int s = 0; s < 2; s++) {
        int idx = tid + s * 256;
        int row = idx >> 2;
        int lk  = (idx & 3) * 8;
        int r   = rbase + row;
        float vals[8];
        if (r < RE) {
            float4 v0 = *(const float4*)(edges + (size_t)r * 32 + lk);
            float4 v1 = *(const float4*)(edges + (size_t)r * 32 + lk + 4);
            vals[0] = v0.x; vals[1] = v0.y; vals[2] = v0.z; vals[3] = v0.w;
            vals[4] = v1.x; vals[5] = v1.y; vals[6] = v1.z; vals[7] = v1.w;
        } else {
#pragma unroll
            for (int q = 0; q < 8; q++) vals[q] = 0.f;
        }
        uint32_t hp[4], lp[4];
        split_pack8(vals, hp, lp);
        uint32_t off = (uint32_t)(row * A_STRIDE + lk) * 2;
        *(uint4*)((char*)sAhi + off) = make_uint4(hp[0], hp[1], hp[2], hp[3]);
        *(uint4*)((char*)sAlo + off) = make_uint4(lp[0], lp[1], lp[2], lp[3]);
    }

    // ---- B tile 0 load ----
    const int bnl = tid >> 2;            // 0..63
    const int bkk = (tid & 3) * 8;
    uint4 bsh, bsl;
    auto ldgB = [&](int nt) {
        int n = nt * 64 + bnl;
        bsh = *(const uint4*)(g_BeH + (size_t)n * 32 + bkk);
        bsl = *(const uint4*)(g_BeL + (size_t)n * 32 + bkk);
    };
    auto stsB = [&](int buf) {
        uint32_t off = (uint32_t)(bnl * A_STRIDE + bkk) * 2;
        *(uint4*)((char*)sBhi[buf] + off) = bsh;
        *(uint4*)((char*)sBlo[buf] + off) = bsl;
    };
    ldgB(0);
    stsB(0);
    __syncthreads();

    // ---- hoisted A fragments ----
    const uint32_t sb_ahi = smem_u32(sAhi);
    const uint32_t sb_alo = smem_u32(sAlo);
    const int a_m    = warp_m * 32 + (lane & 7) + ((lane >> 3) & 1) * 8;
    const int a_koff = (lane >> 4) * 8;
    uint32_t ahi[2][2][4], alo[2][2][4];
#pragma unroll
    for (int ks = 0; ks < 2; ks++)
#pragma unroll
        for (int mt = 0; mt < 2; mt++) {
            uint32_t ad = sb_ahi +
                (uint32_t)((a_m + mt * 16) * (A_STRIDE * 2) +
                           (ks * 16 + a_koff) * 2);
            ldsm_x4(ahi[ks][mt][0], ahi[ks][mt][1], ahi[ks][mt][2], ahi[ks][mt][3], ad);
            ldsm_x4(alo[ks][mt][0], alo[ks][mt][1], alo[ks][mt][2], alo[ks][mt][3],
                    ad + (sb_alo - sb_ahi));
        }

    const int b_n    = warp_n * 32 + (lane & 7) + (lane >> 4) * 8;
    const int b_koff = ((lane >> 3) & 1) * 8;
    const int lq = lane & 3;
    const int lr = lane >> 2;

#pragma unroll 1
    for (int nt = 0; nt < 6; nt++) {
        const int cur = nt & 1;
        if (nt < 5) ldgB(nt + 1);

        const uint32_t sb_bhi = smem_u32(sBhi[cur]);
        const uint32_t sb_blo = smem_u32(sBlo[cur]);
        uint32_t bhi[2][4][2], blo[2][4][2];
#pragma unroll
        for (int ks = 0; ks < 2; ks++)
#pragma unroll
            for (int p = 0; p < 2; p++) {
                uint32_t bd = sb_bhi +
                    (uint32_t)((b_n + p * 16) * (A_STRIDE * 2) +
                               (ks * 16 + b_koff) * 2);
                ldsm_x4(bhi[ks][2 * p][0], bhi[ks][2 * p][1],
                        bhi[ks][2 * p + 1][0], bhi[ks][2 * p + 1][1], bd);
                ldsm_x4(blo[ks][2 * p][0], blo[ks][2 * p][1],
                        blo[ks][2 * p + 1][0], blo[ks][2 * p + 1][1],
                        bd + (sb_blo - sb_bhi));
            }

        float acc[2][4][4];
#pragma unroll
        for (int mt = 0; mt < 2; mt++)
#pragma unroll
            for (int n8 = 0; n8 < 4; n8++)
#pragma unroll
                for (int q = 0; q < 4; q++) acc[mt][n8][q] = 0.f;

#pragma unroll
        for (int ks = 0; ks < 2; ks++)
#pragma unroll
            for (int mt = 0; mt < 2; mt++)
#pragma unroll
                for (int n8 = 0; n8 < 4; n8++) {
                    float* d = acc[mt][n8];
                    mma_bf16(d[0], d[1], d[2], d[3],
                             ahi[ks][mt][0], ahi[ks][mt][1], ahi[ks][mt][2], ahi[ks][mt][3],
                             bhi[ks][n8][0], bhi[ks][n8][1]);
                    mma_bf16(d[0], d[1], d[2], d[3],
                             ahi[ks][mt][0], ahi[ks][mt][1], ahi[ks][mt][2], ahi[ks][mt][3],
                             blo[ks][n8][0], blo[ks][n8][1]);
                    mma_bf16(d[0], d[1], d[2], d[3],
                             alo[ks][mt][0], alo[ks][mt][1], alo[ks][mt][2], alo[ks][mt][3],
                             bhi[ks][n8][0], bhi[ks][n8][1]);
                }

#pragma unroll
        for (int mt = 0; mt < 2; mt++) {
            int m0 = rbase + warp_m * 32 + mt * 16 + lr;
#pragma unroll
            for (int n8 = 0; n8 < 4; n8++) {
                int cc = nt * 64 + warp_n * 32 + n8 * 8 + lq * 2;
                float2 bb = *(const float2*)(g_bE + cc);
                if (m0 < RE) {
                    float2 o;
                    o.x = acc[mt][n8][0] + bb.x;
                    o.y = acc[mt][n8][1] + bb.y;
                    *(float2*)(C + (size_t)m0 * 384 + cc) = o;
                }
                if (m0 + 8 < RE) {
                    float2 o;
                    o.x = acc[mt][n8][2] + bb.x;
                    o.y = acc[mt][n8][3] + bb.y;
                    *(float2*)(C + (size_t)(m0 + 8) * 384 + cc) = o;
                }
            }
        }

        if (nt < 5) stsB(1 - cur);
        __syncthreads();
    }
}

// ---------------- pipelined N-tiled mma.sync bf16x3 GEMM --------------------
// Register-staged prefetch: chunk c+1's LDGs issue during chunk c's mma phase,
// STS after the read-fence sync. Single smem buffer (stays under 48KB static).
// MMODE 0: A row = X0 + r*ld0
// MMODE 1: A[k] = relu(X0[r*ld0+k] + X1[(b*NN+j)*ld1+k])
// MMODE 2: A = X0[r*ld0](64) ++ X1[r*ld1](32)
// MMODE 3: A[k] = relu(X0[r*ld0+k] + X1[(b*NN+j)*ld1+k] + X1[(b*NN+i)*ld1+256+k])
template<int K, int WM, int WN, int MMODE, bool RELU>
__global__ __launch_bounds__(WM * WN * 32)
void mma_gemm(const float* __restrict__ X0, int ld0,
              const float* __restrict__ X1, int ld1,
              const unsigned short* __restrict__ Bhi,
              const unsigned short* __restrict__ Blo,
              const float* __restrict__ bias,
              float* __restrict__ C, int ldC, int R)
{
    constexpr int MT  = WM * 32;
    constexpr int NB  = WN * 32;
    constexpr int NTH = WM * WN * 32;
    constexpr int AIT = (MT * 4 + NTH - 1) / NTH;   // A-loader iterations
    constexpr int BIT = (NB * 4 + NTH - 1) / NTH;   // B-loader iterations
    __shared__ __align__(16) unsigned short sAhi[MT * A_STRIDE];
    __shared__ __align__(16) unsigned short sAlo[MT * A_STRIDE];
    __shared__ __align__(16) unsigned short sBhi[NB * A_STRIDE];
    __shared__ __align__(16) unsigned short sBlo[NB * A_STRIDE];

    const int tid  = threadIdx.x;
    const int wid  = tid >> 5;
    const int lane = tid & 31;
    const int warp_m = wid % WM;
    const int warp_n = wid / WM;
    const int rbase = blockIdx.x * MT;
    const int cbase = blockIdx.y * NB;

    float acc[2][4][4];
#pragma unroll
    for (int mt = 0; mt < 2; mt++)
#pragma unroll
        for (int nt = 0; nt < 4; nt++)
#pragma unroll
            for (int q = 0; q < 4; q++) acc[mt][nt][q] = 0.f;

    const int a_m    = warp_m * 32 + (lane & 7) + ((lane >> 3) & 1) * 8;
    const int a_koff = (lane >> 4) * 8;
    const int b_n    = warp_n * 32 + (lane & 7) + (lane >> 4) * 8;
    const int b_koff = ((lane >> 3) & 1) * 8;

    const uint32_t sb_ahi = smem_u32(sAhi);
    const uint32_t sb_alo = smem_u32(sAlo);
    const uint32_t sb_bhi = smem_u32(sBhi);
    const uint32_t sb_blo = smem_u32(sBlo);

    // -------- register staging for the prefetch pipeline --------
    float a_st[AIT][8];
    uint4 b_sth[BIT], b_stl[BIT];

    auto loadA = [&](int chunk) {
        const int k0 = chunk * 32;
#pragma unroll
        for (int it = 0; it < AIT; it++) {
            const int idx = tid + it * NTH;
            if (idx >= MT * 4) break;
            const int row = idx >> 2;
            const int lk  = (idx & 3) * 8;
            const int r   = rbase + row;
            const int kb  = k0 + lk;
            float* vals = a_st[it];
            if (r < R) {
                if (MMODE == 0) {
                    float4 v0 = *(const float4*)(X0 + (size_t)r * ld0 + kb);
                    float4 v1 = *(const float4*)(X0 + (size_t)r * ld0 + kb + 4);
                    vals[0] = v0.x; vals[1] = v0.y; vals[2] = v0.z; vals[3] = v0.w;
                    vals[4] = v1.x; vals[5] = v1.y; vals[6] = v1.z; vals[7] = v1.w;
                } else if (MMODE == 1) {
                    int b = (r >= NEg) ? 1 : 0;
                    int e = r - b * NEg;
                    int2 ij = g_eij[e];
                    const float* pa = X0 + (size_t)r * ld0 + kb;
                    const float* pb = X1 + ((size_t)(b * NN + ij.y)) * ld1 + kb;
                    float4 s0 = relu4(add4(*(const float4*)pa,
                                           *(const float4*)pb));
                    float4 s1 = relu4(add4(*(const float4*)(pa + 4),
                                           *(const float4*)(pb + 4)));
                    vals[0] = s0.x; vals[1] = s0.y; vals[2] = s0.z; vals[3] = s0.w;
                    vals[4] = s1.x; vals[5] = s1.y; vals[6] = s1.z; vals[7] = s1.w;
                } else if (MMODE == 2) { // X0(64) ++ X1(32)
                    const float* s = (kb < 64) ? (X0 + (size_t)r * ld0 + kb)
                                               : (X1 + (size_t)r * ld1 + kb - 64);
                    float4 v0 = *(const float4*)s;
                    float4 v1 = *(const float4*)(s + 4);
                    vals[0] = v0.x; vals[1] = v0.y; vals[2] = v0.z; vals[3] = v0.w;
                    vals[4] = v1.x; vals[5] = v1.y; vals[6] = v1.z; vals[7] = v1.w;
                } else { // MMODE 3: relu(E1 + U[j] + V[i])
                    int b = (r >= NEg) ? 1 : 0;
                    int e = r - b * NEg;
                    int2 ij = g_eij[e];
                    const float* pa = X0 + (size_t)r * ld0 + kb;
                    const float* pu = X1 + ((size_t)(b * NN + ij.y)) * ld1 + kb;
                    const float* pv = X1 + ((size_t)(b * NN + ij.x)) * ld1 + 256 + kb;
                    float4 s0 = relu4(add4(add4(*(const float4*)pa,
                                                *(const float4*)pu),
                                           *(const float4*)pv));
                    float4 s1 = relu4(add4(add4(*(const float4*)(pa + 4),
                                                *(const float4*)(pu + 4)),
                                           *(const float4*)(pv + 4)));
                    vals[0] = s0.x; vals[1] = s0.y; vals[2] = s0.z; vals[3] = s0.w;
                    vals[4] = s1.x; vals[5] = s1.y; vals[6] = s1.z; vals[7] = s1.w;
                }
            } else {
#pragma unroll
                for (int q = 0; q < 8; q++) vals[q] = 0.f;
            }
        }
    };
    auto loadB = [&](int chunk) {
        const int k0 = chunk * 32;
#pragma unroll
        for (int it = 0; it < BIT; it++) {
            const int idx = tid + it * NTH;
            if (idx >= NB * 4) break;
            const int n  = idx >> 2;
            const int lk = (idx & 3) * 8;
            b_sth[it] = *(const uint4*)(Bhi + (size_t)(cbase + n) * K + k0 + lk);
            b_stl[it] = *(const uint4*)(Blo + (size_t)(cbase + n) * K + k0 + lk);
        }
    };
    auto stsA = [&]() {
#pragma unroll
        for (int it = 0; it < AIT; it++) {
            const int idx = tid + it * NTH;
            if (idx >= MT * 4) break;
            const int row = idx >> 2;
            const int lk  = (idx & 3) * 8;
            uint32_t hp[4], lp[4];
            split_pack8(a_st[it], hp, lp);
            uint32_t off = (uint32_t)(row * A_STRIDE + lk) * 2;
            *(uint4*)((char*)sAhi + off) = make_uint4(hp[0], hp[1], hp[2], hp[3]);
            *(uint4*)((char*)sAlo + off) = make_uint4(lp[0], lp[1], lp[2], lp[3]);
        }
    };
    auto stsB = [&]() {
#pragma unroll
        for (int it = 0; it < BIT; it++) {
            const int idx = tid + it * NTH;
            if (idx >= NB * 4) break;
            const int n  = idx >> 2;
            const int lk = (idx & 3) * 8;
            uint32_t off = (uint32_t)(n * A_STRIDE + lk) * 2;
            *(uint4*)((char*)sBhi + off) = b_sth[it];
            *(uint4*)((char*)sBlo + off) = b_stl[it];
        }
    };

    constexpr int NC = K / 32;
    loadA(0); loadB(0);
    stsA();   stsB();
    __syncthreads();

#pragma unroll 1
    for (int c = 0; c < NC; c++) {
        // prefetch next chunk's LDGs (hidden under the mma phase below)
        if (c + 1 < NC) { loadA(c + 1); loadB(c + 1); }

#pragma unroll
        for (int ks = 0; ks < 2; ks++) {
            uint32_t ahi[2][4], alo[2][4];
#pragma unroll
            for (int mt = 0; mt < 2; mt++) {
                uint32_t ad = sb_ahi +
                    (uint32_t)((a_m + mt * 16) * (A_STRIDE * 2) +
                               (ks * 16 + a_koff) * 2);
                ldsm_x4(ahi[mt][0], ahi[mt][1], ahi[mt][2], ahi[mt][3], ad);
                ldsm_x4(alo[mt][0], alo[mt][1], alo[mt][2], alo[mt][3],
                        ad + (sb_alo - sb_ahi));
            }
            uint32_t bhi[4][2], blo[4][2];
#pragma unroll
            for (int p = 0; p < 2; p++) {
                uint32_t bd = sb_bhi +
                    (uint32_t)((b_n + p * 16) * (A_STRIDE * 2) +
                               (ks * 16 + b_koff) * 2);
                ldsm_x4(bhi[2 * p][0], bhi[2 * p][1],
                        bhi[2 * p + 1][0], bhi[2 * p + 1][1], bd);
                ldsm_x4(blo[2 * p][0], blo[2 * p][1],
                        blo[2 * p + 1][0], blo[2 * p + 1][1],
                        bd + (sb_blo - sb_bhi));
            }
#pragma unroll
            for (int mt = 0; mt < 2; mt++)
#pragma unroll
                for (int nt = 0; nt < 4; nt++) {
                    float* d = acc[mt][nt];
                    mma_bf16(d[0], d[1], d[2], d[3],
                             ahi[mt][0], ahi[mt][1], ahi[mt][2], ahi[mt][3],
                             bhi[nt][0], bhi[nt][1]);
                    mma_bf16(d[0], d[1], d[2], d[3],
                             ahi[mt][0], ahi[mt][1], ahi[mt][2], ahi[mt][3],
                             blo[nt][0], blo[nt][1]);
                    mma_bf16(d[0], d[1], d[2], d[3],
                             alo[mt][0], alo[mt][1], alo[mt][2], alo[mt][3],
                             bhi[nt][0], bhi[nt][1]);
                }
        }
        __syncthreads();                     // all smem reads of chunk c done
        if (c + 1 < NC) {
            stsA(); stsB();                  // write chunk c+1
            __syncthreads();                 // visible before next ldsm
        }
    }

    // ---- epilogue ----
    const int lq = lane & 3;
    const int lr = lane >> 2;
#pragma unroll
    for (int mt = 0; mt < 2; mt++) {
        int m0 = rbase + warp_m * 32 + mt * 16 + lr;
#pragma unroll
        for (int nt = 0; nt < 4; nt++) {
            int cc = cbase + warp_n * 32 + nt * 8 + lq * 2;
            float2 bb = *(const float2*)(bias + cc);
            auto act = [](float v) { return RELU ? fmaxf(v, 0.f) : v; };
            if (m0 < R) {
                float2 o;
                o.x = act(acc[mt][nt][0] + bb.x);
                o.y = act(acc[mt][nt][1] + bb.y);
                *(float2*)(C + (size_t)m0 * ldC + cc) = o;
            }
            if (m0 + 8 < R) {
                float2 o;
                o.x = act(acc[mt][nt][2] + bb.x);
                o.y = act(acc[mt][nt][3] + bb.y);
                *(float2*)(C + (size_t)(m0 + 8) * ldC + cc) = o;
            }
        }
    }
}

// ---------------- FFMA2 GEMM (node-side small work) --------------------------
// MODE 0: A plain [R x K];  MODE 3: A = X0[r](128) ++ X1[r](64)  (K=192)
template<int K, int NOUT, int MODE, bool RELU>
__global__ __launch_bounds__(256, 2)
void gemm_bias_relu(const float* __restrict__ A,
                    const float* __restrict__ W, int ldW,
                    const float* __restrict__ bias,
                    float* __restrict__ C, int R,
                    const float* __restrict__ X0,
                    const float* __restrict__ X1)
{
    __shared__ __align__(16) float As[2][32][128];
    __shared__ __align__(16) float Bs[2][32][64];

    const int tid   = threadIdx.x;
    const int tx    = tid & 15;
    const int ty    = tid >> 4;
    const int rbase = blockIdx.y * 128;
    const int cbase = blockIdx.x * 64;

    const int lm = tid >> 1;
    const int lk = (tid & 1) * 16;
    const int r  = rbase + lm;
    const bool rv = (r < R);

    const float* p0 = nullptr;
    const float* p1 = nullptr;
    if (rv) {
        if (MODE == 0) {
            p0 = A + (size_t)r * K;
        } else { // MODE 3
            p0 = X0 + (size_t)r * 128;
            p1 = X1 + (size_t)r * 64;
        }
    }

    const int bk = tid >> 4;
    const int bn = (tid & 15) * 4;
    const bool cv = (cbase + bn < NOUT);

    unsigned long long acc[4][4];
#pragma unroll
    for (int p = 0; p < 4; p++)
#pragma unroll
        for (int v = 0; v < 4; v++) acc[p][v] = 0ull;

    float4 apf[4];
    float4 bpf[2];

    auto loadA = [&](int k0) {
        const int kb = k0 + lk;
#pragma unroll
        for (int u = 0; u < 4; u++) apf[u] = make_float4(0.f, 0.f, 0.f, 0.f);
        if (!rv) return;
        if (MODE == 0) {
#pragma unroll
            for (int u = 0; u < 4; u++) apf[u] = *(const float4*)(p0 + kb + 4 * u);
        } else {
            const float* s = (kb < 128) ? (p0 + kb) : (p1 + kb - 128);
#pragma unroll
            for (int u = 0; u < 4; u++) apf[u] = *(const float4*)(s + 4 * u);
        }
    };
    auto loadB = [&](int k0) {
        bpf[0] = make_float4(0.f, 0.f, 0.f, 0.f);
        bpf[1] = make_float4(0.f, 0.f, 0.f, 0.f);
        if (cv) {
            bpf[0] = *(const float4*)(W + (size_t)(k0 + bk) * ldW + (cbase + bn));
            bpf[1] = *(const float4*)(W + (size_t)(k0 + bk + 16) * ldW + (cbase + bn));
        }
    };
    auto stsA = [&](int buf) {
#pragma unroll
        for (int u = 0; u < 4; u++) {
            As[buf][lk + 4 * u + 0][lm] = apf[u].x;
            As[buf][lk + 4 * u + 1][lm] = apf[u].y;
            As[buf][lk + 4 * u + 2][lm] = apf[u].z;
            As[buf][lk + 4 * u + 3][lm] = apf[u].w;
        }
    };
    auto stsB = [&](int buf) {
        *(float4*)&Bs[buf][bk][bn]      = bpf[0];
        *(float4*)&Bs[buf][bk + 16][bn] = bpf[1];
    };

    constexpr int NC = K / 32;
    loadA(0); loadB(0);
    stsA(0);  stsB(0);
    __syncthreads();

#pragma unroll
    for (int c = 0; c < NC; c++) {
        const int cur = c & 1;
        if (c + 1 < NC) { loadA((c + 1) * 32); loadB((c + 1) * 32); }

#pragma unroll
        for (int kk = 0; kk < 32; kk++) {
            float4 b4 = *(const float4*)&Bs[cur][kk][tx * 4];
            unsigned long long bx = bcast2(b4.x);
            unsigned long long by = bcast2(b4.y);
            unsigned long long bz = bcast2(b4.z);
            unsigned long long bw = bcast2(b4.w);
            ulonglong2 a01 = *(const ulonglong2*)&As[cur][kk][ty * 8];
            ulonglong2 a23 = *(const ulonglong2*)&As[cur][kk][ty * 8 + 4];
            ffma2(acc[0][0], a01.x, bx); ffma2(acc[0][1], a01.x, by);
            ffma2(acc[0][2], a01.x, bz); ffma2(acc[0][3], a01.x, bw);
            ffma2(acc[1][0], a01.y, bx); ffma2(acc[1][1], a01.y, by);
            ffma2(acc[1][2], a01.y, bz); ffma2(acc[1][3], a01.y, bw);
            ffma2(acc[2][0], a23.x, bx); ffma2(acc[2][1], a23.x, by);
            ffma2(acc[2][2], a23.x, bz); ffma2(acc[2][3], a23.x, bw);
            ffma2(acc[3][0], a23.y, bx); ffma2(acc[3][1], a23.y, by);
            ffma2(acc[3][2], a23.y, bz); ffma2(acc[3][3], a23.y, bw);
        }

        if (c + 1 < NC) { stsA(1 - cur); stsB(1 - cur); }
        __syncthreads();
    }

    const int c = cbase + tx * 4;
    if (c < NOUT) {
        float4 bb = make_float4(0.f, 0.f, 0.f, 0.f);
        if (bias) bb = *(const float4*)(bias + c);
        auto act = [](float v) { return RELU ? fmaxf(v, 0.f) : v; };
#pragma unroll
        for (int p = 0; p < 4; p++) {
            float2 q0 = unpack2(acc[p][0]);
            float2 q1 = unpack2(acc[p][1]);
            float2 q2 = unpack2(acc[p][2]);
            float2 q3 = unpack2(acc[p][3]);
            int r0 = rbase + ty * 8 + 2 * p;
            if (r0 < R) {
                float4 o;
                o.x = act(q0.x + bb.x);
                o.y = act(q1.x + bb.y);
                o.z = act(q2.x + bb.z);
                o.w = act(q3.x + bb.w);
                *(float4*)(C + (size_t)r0 * NOUT + c) = o;
            }
            if (r0 + 1 < R) {
                float4 o;
                o.x = act(q0.y + bb.x);
                o.y = act(q1.y + bb.y);
                o.z = act(q2.y + bb.z);
                o.w = act(q3.y + bb.w);
                *(float4*)(C + (size_t)(r0 + 1) * NOUT + c) = o;
            }
        }
    }
}

// ---------------- merged aggregation (pn + pe in one launch) ----------------
__global__ void agg_kernel() {
    const int w    = threadIdx.x >> 5;
    const int lane = threadIdx.x & 31;
    const int i    = blockIdx.x * 4 + w;
    const int b    = blockIdx.y;
    if (blockIdx.z == 0) {
        const int t  = min(i, 32);
        const int k0 = group_start(i);
        float4 s = make_float4(0.f, 0.f, 0.f, 0.f);
        const float* src = g_hn + ((size_t)(b * NEg + k0)) * 128 + lane * 4;
        for (int l = 0; l < t; l++) {
            float4 v = *(const float4*)src;
            s = add4(s, v);
            src += 128;
        }
        const float nrm = 1.f / (float)max(t, 1);
        s.x *= nrm; s.y *= nrm; s.z *= nrm; s.w *= nrm;
        *(float4*)(g_pn + ((size_t)(b * NN + i)) * 128 + lane * 4) = s;
    } else {
        if (i == 0) return;
        const int t  = min(i, 32);
        const int k0 = group_start(i);
        float2 run = make_float2(0.f, 0.f);
        size_t base = ((size_t)(b * NEg + k0)) * 64 + lane * 2;
        for (int l = 0; l < t; l++) {
            float nrm = (l > 0) ? (1.f / (float)l) : 1.f;
            *(float2*)(g_pe + base) = make_float2(run.x * nrm, run.y * nrm);
            float2 h = *(const float2*)(g_he + base);
            run.x += h.x; run.y += h.y;
            base += 64;
        }
    }
}

// ---------------- launch -----------------------------------------------------
extern "C" void kernel_launch(void* const* d_in, const int* in_sizes, int n_in,
                              void* d_out, int out_size) {
    const float* nodes = (const float*)d_in[0];
    const float* edges = (const float*)d_in[1];
    const float* Wan1  = (const float*)d_in[2];
    const float* ban1  = (const float*)d_in[3];
    const float* Wan2  = (const float*)d_in[4];
    const float* ban2  = (const float*)d_in[5];
    const float* Wln1  = (const float*)d_in[6];
    const float* bln1  = (const float*)d_in[7];
    const float* Wln2  = (const float*)d_in[8];
    const float* bln2  = (const float*)d_in[9];
    const float* Wae1  = (const float*)d_in[10];
    const float* bae1  = (const float*)d_in[11];
    const float* Wae2  = (const float*)d_in[12];
    const float* bae2  = (const float*)d_in[13];
    const float* Wle1  = (const float*)d_in[14];
    const float* ble1  = (const float*)d_in[15];
    const float* Wle2  = (const float*)d_in[16];
    const float* ble2  = (const float*)d_in[17];

    float* out_nodes = (float*)d_out;                         // [2,1024,64]
    float* out_edges = (float*)d_out + (size_t)BBc * NN * 64; // [2,NE,32]

    float *UVP, *E, *hn, *pn, *h3n, *he, *pe, *h3e, *WUVP;
    unsigned short *Bhi, *Blo, *BheH, *BheL, *B3eH, *B3eL, *BoeH, *BoeL;
    cudaGetSymbolAddress((void**)&UVP, g_UVP);
    cudaGetSymbolAddress((void**)&E,   g_E);
    cudaGetSymbolAddress((void**)&hn,  g_hn);
    cudaGetSymbolAddress((void**)&pn,  g_pn);
    cudaGetSymbolAddress((void**)&h3n, g_h3n);
    cudaGetSymbolAddress((void**)&he,  g_he);
    cudaGetSymbolAddress((void**)&pe,  g_pe);
    cudaGetSymbolAddress((void**)&h3e, g_h3e);
    cudaGetSymbolAddress((void**)&WUVP, g_WUVP);
    cudaGetSymbolAddress((void**)&Bhi, g_Bhi);
    cudaGetSymbolAddress((void**)&Blo, g_Blo);
    cudaGetSymbolAddress((void**)&BheH, g_BheH);
    cudaGetSymbolAddress((void**)&BheL, g_BheL);
    cudaGetSymbolAddress((void**)&B3eH, g_B3eH);
    cudaGetSymbolAddress((void**)&B3eL, g_B3eL);
    cudaGetSymbolAddress((void**)&BoeH, g_BoeH);
    cudaGetSymbolAddress((void**)&BoeL, g_BoeL);

    const int gbE  = (RE + 127) / 128;   // 504 tiles of 128 edge rows
    const int gbE2 = (RE + 63) / 64;     // 1008 tiles of 64 edge rows
    const int gbN  = (RN + 127) / 128;   // 16 row tiles for node rows

    // all weight prep + edge index build in ONE launch
    prep_kernel<<<(SEG8 + 255) / 256, 256>>>(Wan1, Wan2, Wae1, Wae2,
                                             Wle1, Wle2, ban1, bae1);

    // per-node precompute: UVP = nodes @ [Wan1[0:64] | Wan1[96:160] | Wae1[0:64]]
    gemm_bias_relu<64, 640, 0, false><<<dim3(10, gbN), 256>>>(
        nodes, WUVP, 640, nullptr, UVP, RN, nullptr, nullptr);

    // per-edge first-layer parts (E1|E2), A-resident N-tile loop
    e_mma_kernel<<<gbE, 256>>>(edges, E);

    // big L2 GEMMs, all MT=64 pipelined tiles
    mma_gemm<256, 2, 4, 3, true><<<dim3(gbE2, 1), 256>>>(
        E, 384, UVP, 640, Bhi, Blo, ban2, hn, 128, RE);
    mma_gemm<128, 2, 2, 1, true><<<dim3(gbE2, 1), 128>>>(
        E + 256, 384, UVP + 512, 640, BheH, BheL, bae2, he, 64, RE);
    agg_kernel<<<dim3(NN / 4, BBc, 2), 128>>>();

    // node tail
    gemm_bias_relu<192, 192, 3, true><<<dim3(3, gbN), 256>>>(
        nullptr, Wln1, 192, bln1, h3n, RN, pn, nodes);
    gemm_bias_relu<192, 64, 0, true><<<dim3(1, gbN), 256>>>(
        h3n, Wln2, 64, bln2, out_nodes, RN, nullptr, nullptr);

    // edge tail
    mma_gemm<96, 2, 3, 2, true><<<dim3(gbE2, 1), 192>>>(
        pe, 64, edges, 32, B3eH, B3eL, ble1, h3e, 96, RE);
    mma_gemm<96, 4, 1, 0, true><<<dim3(gbE, 1), 128>>>(
        h3e, 96, nullptr, 0, BoeH, BoeL, ble2, out_edges, 32, RE);
}